// round 7
// baseline (speedup 1.0000x reference)
#include <cuda_runtime.h>
#include <cuda_bf16.h>
#include <cstdint>

#define Nn 16384
#define Dd 64
#define KK 17
#define Ee (Nn*16)
#define Ll 4

typedef unsigned long long ull;

// ---------------- scratch (static device allocations) ----------------
__device__ float g_h[Nn*Dd];
__device__ float g_hsq[Nn];                     // exact 0.5 * ||h_i||^2
__device__ int   g_idx[Nn*KK];
__device__ float g_y1[(size_t)Ee*Dd];
__device__ float g_y2[(size_t)Ee*Dd];
__device__ float g_agg[Nn*Dd];
__device__ float g_u1[Nn*Dd];
__device__ float g_u2[Nn*Dd];
__device__ float g_part[2048*128];
__device__ float g_scale[Dd];
__device__ float g_shift[Dd];
// pre-SW128-swizzled bf16 hi parts of h (row = node, 128 bytes/row)
__device__ unsigned g_hb_hi[Nn*32];

// ---------------- packed f32x2 helpers (for MLP GEMMs) ----------------
__device__ __forceinline__ ull ff2(ull a, ull b, ull c) {
    ull d;
    asm("fma.rn.f32x2 %0, %1, %2, %3;" : "=l"(d) : "l"(a), "l"(b), "l"(c));
    return d;
}
__device__ __forceinline__ ull dup2(float x) {
    ull d;
    unsigned u = __float_as_uint(x);
    asm("mov.b64 %0, {%1, %1};" : "=l"(d) : "r"(u));
    return d;
}
__device__ __forceinline__ float2 up2(ull v) {
    float2 r;
    asm("mov.b64 {%0, %1}, %2;" : "=f"(r.x), "=f"(r.y) : "l"(v));
    return r;
}

// ---------------- sm_80-era async-copy / ldmatrix / mma helpers --------
__device__ __forceinline__ uint32_t smem_u32(const void* p) {
    uint32_t a;
    asm("{ .reg .u64 t; cvta.to.shared.u64 t, %1; cvt.u32.u64 %0, t; }"
        : "=r"(a) : "l"(p));
    return a;
}
__device__ __forceinline__ void cp16(uint32_t d, const void* s) {
    asm volatile("cp.async.cg.shared.global [%0], [%1], 16;"
                 :: "r"(d), "l"(s) : "memory");
}
__device__ __forceinline__ void cp_commit() {
    asm volatile("cp.async.commit_group;" ::: "memory");
}
template<int N> __device__ __forceinline__ void cp_wait() {
    asm volatile("cp.async.wait_group %0;" :: "n"(N) : "memory");
}
__device__ __forceinline__ void ldsm4(uint32_t& r0, uint32_t& r1,
                                      uint32_t& r2, uint32_t& r3, uint32_t a) {
    asm volatile("ldmatrix.sync.aligned.m8n8.x4.shared.b16 {%0,%1,%2,%3}, [%4];"
                 : "=r"(r0), "=r"(r1), "=r"(r2), "=r"(r3) : "r"(a));
}
__device__ __forceinline__ void mma_bf16(float& c0, float& c1, float& c2, float& c3,
                                         uint32_t a0, uint32_t a1, uint32_t a2,
                                         uint32_t a3, uint32_t b0, uint32_t b1) {
    asm volatile(
        "mma.sync.aligned.m16n8k16.row.col.f32.bf16.bf16.f32 "
        "{%0,%1,%2,%3}, {%4,%5,%6,%7}, {%8,%9}, {%0,%1,%2,%3};"
        : "+f"(c0), "+f"(c1), "+f"(c2), "+f"(c3)
        : "r"(a0), "r"(a1), "r"(a2), "r"(a3), "r"(b0), "r"(b1));
}
__device__ __forceinline__ uint32_t sw128(uint32_t off) {
    return off ^ ((off >> 3) & 0x70u);
}

// ---------------- input projection ----------------
__global__ void k_lin_in(const float* __restrict__ pos,
                         const float* __restrict__ W,
                         const float* __restrict__ b) {
    __shared__ float sW[11*64];
    __shared__ float sp[11];
    const int i = blockIdx.x;
    const int f = threadIdx.x;
    for (int t = f; t < 11*64; t += 64) sW[t] = W[t];
    if (f < 11) sp[f] = pos[i*11 + f];
    __syncthreads();
    float acc = b[f];
    #pragma unroll
    for (int c = 0; c < 11; c++) acc = fmaf(sp[c], sW[c*64 + f], acc);
    g_h[i*64 + f] = acc;
}

// ---------------- bf16 hi + swizzled store + exact 0.5*sq --------------
__global__ void k_split() {
    const int node = blockIdx.x*8 + (threadIdx.x >> 5);
    const int lane = threadIdx.x & 31;
    float2 f = *(const float2*)(g_h + (size_t)node*64 + lane*2);

    __nv_bfloat16 h0 = __float2bfloat16(f.x);
    __nv_bfloat16 h1 = __float2bfloat16(f.y);

    unsigned off = (unsigned)node*128u + (unsigned)lane*4u;
    unsigned sw  = sw128(off);
    *(unsigned*)((char*)g_hb_hi + sw) =
        (unsigned)__bfloat16_as_ushort(h0) | ((unsigned)__bfloat16_as_ushort(h1) << 16);

    float s = f.x*f.x + f.y*f.y;            // exact fp32 norms
    #pragma unroll
    for (int o = 16; o > 0; o >>= 1) s += __shfl_down_sync(0xffffffffu, s, o);
    if (lane == 0) g_hsq[node] = 0.5f * s;
}

// ---------------- fused mma.sync d2 prefilter + exact rerank ------------
// smem layout (bytes from 1024-aligned base):
//  B bufs:  2 x 16384 = 32768        @ 0      (reused as fp32 A rows in rerank)
//  A:       16384                    @ 32768
//  hsq:     2 x 512                  @ 49152
//  lv:      128*33*4 = 16896         @ 50176  (top-32 lists, pad stride 33)
//  li:      128*33*4 = 16896         @ 67072
#define MC      32
#define MCP     33
#define OB_B    0u
#define OB_A    32768u
#define OB_HSQ  49152u
#define OB_LV   50176u
#define OB_LI   67072u
#define SMEM_D2 (83968u + 1024u)

__device__ __forceinline__ void ins32(float* lv, int* li, float v, int j) {
    int p = MC - 1;
    while (p > 0 && lv[p-1] > v) { lv[p] = lv[p-1]; li[p] = li[p-1]; p--; }
    lv[p] = v; li[p] = j;
}

__global__ __launch_bounds__(256) void k_d2topk() {
    extern __shared__ __align__(16) char smraw[];
    const uint32_t rawb = smem_u32(smraw);
    const uint32_t sb = (rawb + 1023u) & ~1023u;
    char* smc = smraw + (sb - rawb);

    const int tid  = threadIdx.x;
    const int w    = tid >> 5;
    const int lane = tid & 31;
    const int row0 = blockIdx.x * 128;

    float* lv = (float*)(smc + OB_LV);
    int*   li = (int*)  (smc + OB_LI);

    // ---- prologue: async copies (A, B0, B1) — hi parts only ----
    {
        const char* srchi = (const char*)g_hb_hi + (size_t)row0*128;
        for (int i = tid; i < 1024; i += 256)
            cp16(sb + OB_A + i*16, srchi + i*16);
        cp_commit();
        #pragma unroll
        for (int tt = 0; tt < 2; tt++) {
            const char* bhi = (const char*)g_hb_hi + (size_t)tt*16384;
            uint32_t dst = sb + OB_B + (uint32_t)tt*16384u;
            for (int i = tid; i < 1024; i += 256)
                cp16(dst + i*16, bhi + i*16);
            if (tid < 32) cp16(sb + OB_HSQ + (uint32_t)tt*512u + tid*16,
                               (const char*)g_hsq + (size_t)tt*512 + tid*16);
            cp_commit();
        }
    }
    if (tid < 128) {
        #pragma unroll
        for (int p = 0; p < MC; p++) {
            lv[tid*MCP + p] = 3.4e38f;
            li[tid*MCP + p] = 0x7FFFFFFF;
        }
    }
    cp_wait<1>();          // A + B0 resident
    __syncthreads();

    // ---- preload A fragments (hi only, fixed across all tiles) ----
    uint32_t af[4][4];
    {
        const int m  = lane >> 3;
        const int rr = (w << 4) + ((m & 1) << 3) + (lane & 7);
        const int kb0 = (m >> 1) << 4;
        #pragma unroll
        for (int ks = 0; ks < 4; ks++) {
            uint32_t loc = (uint32_t)rr*128u + (uint32_t)(ks*32 + kb0);
            ldsm4(af[ks][0], af[ks][1], af[ks][2], af[ks][3],
                  sb + OB_A + sw128(loc));
        }
    }

    const int q   = lane >> 2;            // row within m16 (and +8)
    const int s3  = lane & 3;             // column pair selector
    const int lr0 = (w << 4) + q;
    const int lr1 = lr0 + 8;
    float th0 = 3.4e38f, th1 = 3.4e38f;

    const int bm = lane >> 3;             // ldmatrix B address helper
    const int bn = lane & 7;

    for (int t = 0; t < 128; t++) {
        const uint32_t bbase = sb + OB_B + (uint32_t)(t & 1)*16384u;
        const char* hsqp = smc + OB_HSQ + (uint32_t)(t & 1)*512u;
        const int jb = t * 128;

        #pragma unroll 1
        for (int nb = 0; nb < 16; nb++) {
            // ---- B fragments: hi only, 4 k-steps via 2 ldmatrix.x4 ----
            uint32_t bh[8];
            {
                uint32_t loc = (uint32_t)((nb*8 + bn)*128 + bm*16);
                ldsm4(bh[0], bh[1], bh[2], bh[3], bbase + sw128(loc));
                ldsm4(bh[4], bh[5], bh[6], bh[7], bbase + sw128(loc + 64u));
            }
            // ---- hi*hi only: 2 independent chains of 2 MMAs ----
            float h0 = 0.f, h1 = 0.f, h2 = 0.f, h3 = 0.f;
            float g0 = 0.f, g1 = 0.f, g2 = 0.f, g3 = 0.f;
            mma_bf16(h0, h1, h2, h3, af[0][0], af[0][1], af[0][2], af[0][3],
                     bh[0], bh[1]);
            mma_bf16(g0, g1, g2, g3, af[1][0], af[1][1], af[1][2], af[1][3],
                     bh[2], bh[3]);
            mma_bf16(h0, h1, h2, h3, af[2][0], af[2][1], af[2][2], af[2][3],
                     bh[4], bh[5]);
            mma_bf16(g0, g1, g2, g3, af[3][0], af[3][1], af[3][2], af[3][3],
                     bh[6], bh[7]);
            float c0 = h0 + g0;
            float c1 = h1 + g1;
            float c2 = h2 + g2;
            float c3 = h3 + g3;

            // ---- approx key = 0.5*sq_c - dot_hi; threshold + rare insert --
            float2 hs = *(const float2*)(hsqp + (nb*8 + 2*s3)*4);
            float k0 = hs.x - c0;
            float k1 = hs.y - c1;
            float k2 = hs.x - c2;
            float k3 = hs.y - c3;
            bool p0 = k0 < th0, p1 = k1 < th0, p2 = k2 < th1, p3 = k3 < th1;
            unsigned any = __ballot_sync(0xffffffffu, p0 | p1 | p2 | p3);
            if (any) {
                const int colb = jb + nb*8 + 2*s3;
                #pragma unroll
                for (int s = 0; s < 4; s++) {
                    __syncwarp();
                    if (s3 == s && (p0 | p1 | p2 | p3)) {
                        float* L0 = lv + lr0*MCP; int* I0 = li + lr0*MCP;
                        float t0 = L0[MC-1];
                        if (k0 < t0) { ins32(L0, I0, k0, colb);   t0 = L0[MC-1]; }
                        if (k1 < t0) { ins32(L0, I0, k1, colb+1); }
                        float* L1 = lv + lr1*MCP; int* I1 = li + lr1*MCP;
                        float t1 = L1[MC-1];
                        if (k2 < t1) { ins32(L1, I1, k2, colb);   t1 = L1[MC-1]; }
                        if (k3 < t1) { ins32(L1, I1, k3, colb+1); }
                    }
                }
                __syncwarp();
                th0 = lv[lr0*MCP + MC-1];
                th1 = lv[lr1*MCP + MC-1];
            }
        }

        __syncthreads();     // all warps done with buf[t&1] + lists stable
        if (t + 2 < 128) {
            const int tt = t + 2;
            const char* bhi = (const char*)g_hb_hi + (size_t)tt*16384;
            uint32_t dst = sb + OB_B + (uint32_t)(t & 1)*16384u;
            for (int i = tid; i < 1024; i += 256)
                cp16(dst + i*16, bhi + i*16);
            if (tid < 32) cp16(sb + OB_HSQ + (uint32_t)(t & 1)*512u + tid*16,
                               (const char*)g_hsq + (size_t)tt*512 + tid*16);
            cp_commit();
            cp_wait<1>();    // tile t+1 resident
        } else {
            cp_wait<0>();
        }
        __syncthreads();
    }

    // ---- exact fp32 rerank of the 32 candidates per row ----
    __syncthreads();
    float* hrow = (float*)(smc + OB_B);     // reuse B buffers: 128 x 64 fp32
    {
        const float4* src = (const float4*)(g_h + (size_t)row0*64);
        float4* dst = (float4*)hrow;
        for (int i = tid; i < 2048; i += 256) dst[i] = src[i];
    }
    __syncthreads();

    for (int rr = 0; rr < 16; rr++) {
        const int row = (w << 4) + rr;
        const int cidx = li[row*MCP + lane];
        const float4* hj  = (const float4*)(g_h + (size_t)cidx*64);
        const float4* hi4 = (const float4*)(hrow + row*64);
        float s0 = 0.f, s1 = 0.f, s2 = 0.f, s3v = 0.f;
        #pragma unroll
        for (int kk = 0; kk < 16; kk++) {
            float4 a = hi4[kk];
            float4 b = hj[kk];
            s0 = fmaf(a.x, b.x, s0); s1 = fmaf(a.y, b.y, s1);
            s2 = fmaf(a.z, b.z, s2); s3v = fmaf(a.w, b.w, s3v);
        }
        float key = g_hsq[cidx] - ((s0 + s1) + (s2 + s3v));
        const int myi = cidx;
        #pragma unroll
        for (int r = 0; r < KK; r++) {
            float bv = key; int bi = myi;
            #pragma unroll
            for (int o = 16; o > 0; o >>= 1) {
                float ov = __shfl_xor_sync(0xffffffffu, bv, o);
                int   oi = __shfl_xor_sync(0xffffffffu, bi, o);
                if (ov < bv || (ov == bv && oi < bi)) { bv = ov; bi = oi; }
            }
            if (lane == 0) g_idx[(row0 + row)*KK + r] = bi;
            if (myi == bi) key = 3.4e38f;
        }
    }
}

// ------------- GEMM A: depth-128 (MODE 0: msg gather, MODE 1: upd concat)
template<int MODE>
__global__ __launch_bounds__(256) void k_gemm_a(const float* __restrict__ W,
                                                const float* __restrict__ bias) {
    __shared__ float As[64][128];
    __shared__ float Ws[64][64];
    const int tid = threadIdx.x;
    const int e0  = blockIdx.x * 128;
    const int r0  = (tid >> 4) * 8;
    const int f0  = (tid & 15) * 4;
    ull acc[4][4];
    #pragma unroll
    for (int rp = 0; rp < 4; rp++)
        #pragma unroll
        for (int c = 0; c < 4; c++) acc[rp][c] = 0ull;

    for (int p = 0; p < 2; p++) {
        for (int t = tid; t < 1024; t += 256) {
            int f4 = t & 15, kk = t >> 4;
            *(float4*)&Ws[kk][f4<<2] =
                *(const float4*)(W + (size_t)((p<<6)+kk)*64 + (f4<<2));
        }
        for (int t = tid; t < 2048; t += 256) {
            int e = t & 127, k4 = t >> 7;
            int eg = e0 + e;
            const float* src;
            if (MODE == 0) {
                int i = eg & (Nn-1);
                int node = (p == 0) ? g_idx[i*KK + 1 + (eg >> 14)] : g_idx[i*KK];
                src = g_h + (size_t)node*64;
            } else {
                src = (p == 0 ? g_h : g_agg) + (size_t)eg*64;
            }
            float4 v = *(const float4*)(src + (k4<<2));
            As[(k4<<2)+0][e] = v.x; As[(k4<<2)+1][e] = v.y;
            As[(k4<<2)+2][e] = v.z; As[(k4<<2)+3][e] = v.w;
        }
        __syncthreads();
        #pragma unroll 4
        for (int k = 0; k < 64; k++) {
            ulonglong2 a01 = *(const ulonglong2*)(&As[k][r0]);
            ulonglong2 a23 = *(const ulonglong2*)(&As[k][r0+4]);
            float4 b = *(const float4*)(&Ws[k][f0]);
            ull ar[4] = { a01.x, a01.y, a23.x, a23.y };
            ull bd[4] = { dup2(b.x), dup2(b.y), dup2(b.z), dup2(b.w) };
            #pragma unroll
            for (int rp = 0; rp < 4; rp++)
                #pragma unroll
                for (int c = 0; c < 4; c++)
                    acc[rp][c] = ff2(ar[rp], bd[c], acc[rp][c]);
        }
        __syncthreads();
    }

    float* out = (MODE == 0) ? g_y1 : g_u1;
    float4 bv = *(const float4*)(bias + f0);
    #pragma unroll
    for (int rp = 0; rp < 4; rp++) {
        float2 u0 = up2(acc[rp][0]), u1 = up2(acc[rp][1]);
        float2 u2 = up2(acc[rp][2]), u3 = up2(acc[rp][3]);
        int ea = e0 + r0 + 2*rp;
        *(float4*)(out + (size_t)ea*64 + f0) =
            make_float4(u0.x + bv.x, u1.x + bv.y, u2.x + bv.z, u3.x + bv.w);
        *(float4*)(out + (size_t)(ea+1)*64 + f0) =
            make_float4(u0.y + bv.x, u1.y + bv.y, u2.y + bv.z, u3.y + bv.w);
    }
}

// ------------- GEMM B: depth-64 with fused BN-affine + ReLU on input ----
template<int MODE>
__global__ __launch_bounds__(256) void k_gemm_b(const float* __restrict__ W,
                                                const float* __restrict__ bias) {
    __shared__ float As[64][128];
    __shared__ float Ws[64][64];
    const int tid = threadIdx.x;
    const int e0  = blockIdx.x * 128;
    const int r0  = (tid >> 4) * 8;
    const int f0  = (tid & 15) * 4;

    const float* in = (MODE == 0) ? g_y1 : g_u1;

    for (int t = tid; t < 1024; t += 256) {
        int f4 = t & 15, kk = t >> 4;
        *(float4*)&Ws[kk][f4<<2] = *(const float4*)(W + (size_t)kk*64 + (f4<<2));
    }
    for (int t = tid; t < 2048; t += 256) {
        int e = t & 127, k4 = t >> 7;
        int eg = e0 + e;
        float4 v  = *(const float4*)(in + (size_t)eg*64 + (k4<<2));
        float4 sc = *(const float4*)(g_scale + (k4<<2));
        float4 sh = *(const float4*)(g_shift + (k4<<2));
        As[(k4<<2)+0][e] = fmaxf(fmaf(v.x, sc.x, sh.x), 0.f);
        As[(k4<<2)+1][e] = fmaxf(fmaf(v.y, sc.y, sh.y), 0.f);
        As[(k4<<2)+2][e] = fmaxf(fmaf(v.z, sc.z, sh.z), 0.f);
        As[(k4<<2)+3][e] = fmaxf(fmaf(v.w, sc.w, sh.w), 0.f);
    }
    __syncthreads();

    ull acc[4][4];
    #pragma unroll
    for (int rp = 0; rp < 4; rp++)
        #pragma unroll
        for (int c = 0; c < 4; c++) acc[rp][c] = 0ull;

    #pragma unroll 4
    for (int k = 0; k < 64; k++) {
        ulonglong2 a01 = *(const ulonglong2*)(&As[k][r0]);
        ulonglong2 a23 = *(const ulonglong2*)(&As[k][r0+4]);
        float4 b = *(const float4*)(&Ws[k][f0]);
        ull ar[4] = { a01.x, a01.y, a23.x, a23.y };
        ull bd[4] = { dup2(b.x), dup2(b.y), dup2(b.z), dup2(b.w) };
        #pragma unroll
        for (int rp = 0; rp < 4; rp++)
            #pragma unroll
            for (int c = 0; c < 4; c++)
                acc[rp][c] = ff2(ar[rp], bd[c], acc[rp][c]);
    }

    float* out = (MODE == 0) ? g_y2 : g_u2;
    float4 bv = *(const float4*)(bias + f0);
    #pragma unroll
    for (int rp = 0; rp < 4; rp++) {
        float2 u0 = up2(acc[rp][0]), u1 = up2(acc[rp][1]);
        float2 u2 = up2(acc[rp][2]), u3 = up2(acc[rp][3]);
        int ea = e0 + r0 + 2*rp;
        *(float4*)(out + (size_t)ea*64 + f0) =
            make_float4(u0.x + bv.x, u1.x + bv.y, u2.x + bv.z, u3.x + bv.w);
        *(float4*)(out + (size_t)(ea+1)*64 + f0) =
            make_float4(u0.y + bv.x, u1.y + bv.y, u2.y + bv.z, u3.y + bv.w);
    }
}

// ---------------- batch statistics (deterministic two-pass) ------------
__device__ __forceinline__ const float* stat_src(int sel) {
    switch (sel) {
        case 0: return g_y1;
        case 1: return g_y2;
        case 2: return g_u1;
        case 3: return g_u2;
        default: return g_h;
    }
}

__global__ void k_stats(int sel, int M, int P) {
    const float* __restrict__ x = stat_src(sel);
    const int t = threadIdx.x;
    float s = 0.f, s2 = 0.f;
    const size_t total = (size_t)M * 64;
    for (size_t idx = (size_t)blockIdx.x*256 + t; idx < total; idx += (size_t)P*256) {
        float v = x[idx];
        s += v; s2 = fmaf(v, v, s2);
    }
    __shared__ float sh[256], sh2[256];
    sh[t] = s; sh2[t] = s2;
    __syncthreads();
    if (t < 64) {
        s  = sh[t]  + sh[t+64]  + sh[t+128]  + sh[t+192];
        s2 = sh2[t] + sh2[t+64] + sh2[t+128] + sh2[t+192];
        g_part[(size_t)blockIdx.x*128 + t]      = s;
        g_part[(size_t)blockIdx.x*128 + 64 + t] = s2;
    }
}

__global__ void k_stats_fin(int M, int P,
                            const float* __restrict__ g,
                            const float* __restrict__ be) {
    const int f = threadIdx.x;
    float s = 0.f, s2 = 0.f;
    for (int p = 0; p < P; p++) {
        s  += g_part[(size_t)p*128 + f];
        s2 += g_part[(size_t)p*128 + 64 + f];
    }
    const float inv  = 1.f / (float)M;
    const float mean = s * inv;
    const float var  = fmaf(-mean, mean, s2 * inv);
    const float sc   = g[f] * rsqrtf(var + 1e-5f);
    g_scale[f] = sc;
    g_shift[f] = fmaf(-mean, sc, be[f]);
}

// ---------------- zero, scatter, residual ----------------
__global__ void k_zero_agg() {
    int i = blockIdx.x*blockDim.x + threadIdx.x;
    g_agg[i] = 0.f;
}

__global__ void k_scatter() {
    const int gid = blockIdx.x*256 + threadIdx.x;
    const int q = gid & 15;
    const int e = gid >> 4;
    const int i = e & (Nn-1);
    const int to = g_idx[i*KK + 1 + (e >> 14)];
    const int f = q << 2;
    float4 v  = *(const float4*)(g_y2 + (size_t)e*64 + f);
    float4 sc = *(const float4*)(g_scale + f);
    float4 sh = *(const float4*)(g_shift + f);
    float* dst = g_agg + (size_t)to*64 + f;
    atomicAdd(dst+0, fmaxf(fmaf(v.x, sc.x, sh.x), 0.f));
    atomicAdd(dst+1, fmaxf(fmaf(v.y, sc.y, sh.y), 0.f));
    atomicAdd(dst+2, fmaxf(fmaf(v.z, sc.z, sh.z), 0.f));
    atomicAdd(dst+3, fmaxf(fmaf(v.w, sc.w, sh.w), 0.f));
}

__global__ void k_resid() {
    const int gid = blockIdx.x*blockDim.x + threadIdx.x;
    const int f = gid & 63;
    const float v = g_u2[gid];
    g_h[gid] += fmaxf(fmaf(v, g_scale[f], g_shift[f]), 0.f);
}

// ---------------- final pool + prediction ----------------
__global__ void k_fin(const float* __restrict__ pW,
                      const float* __restrict__ pb,
                      float* __restrict__ out, int P) {
    const int f = threadIdx.x;
    float s = 0.f;
    for (int p = 0; p < P; p++) s += g_part[(size_t)p*128 + f];
    float v = (s / (float)Nn) * pW[f];
    __shared__ float red[64];
    red[f] = v;
    __syncthreads();
    if (f < 32) {
        float x = red[f] + red[f+32];
        #pragma unroll
        for (int o = 16; o > 0; o >>= 1) x += __shfl_down_sync(0xffffffffu, x, o);
        if (f == 0) out[0] = x + pb[0];
    }
}

// ---------------- host driver ----------------
extern "C" void kernel_launch(void* const* d_in, const int* in_sizes, int n_in,
                              void* d_out, int out_size) {
    const float* pos    = (const float*)d_in[0];
    const float* linW   = (const float*)d_in[1];
    const float* linb   = (const float*)d_in[2];
    const float* predW  = (const float*)d_in[3];
    const float* predb  = (const float*)d_in[4];
    const float* msgW1  = (const float*)d_in[5];
    const float* msgb1  = (const float*)d_in[6];
    const float* msgg1  = (const float*)d_in[7];
    const float* msgbe1 = (const float*)d_in[8];
    const float* msgW2  = (const float*)d_in[9];
    const float* msgb2  = (const float*)d_in[10];
    const float* msgg2  = (const float*)d_in[11];
    const float* msgbe2 = (const float*)d_in[12];
    const float* updW1  = (const float*)d_in[13];
    const float* updb1  = (const float*)d_in[14];
    const float* updg1  = (const float*)d_in[15];
    const float* updbe1 = (const float*)d_in[16];
    const float* updW2  = (const float*)d_in[17];
    const float* updb2  = (const float*)d_in[18];
    const float* updg2  = (const float*)d_in[19];
    const float* updbe2 = (const float*)d_in[20];
    float* out = (float*)d_out;

    static int smem_set = 0;
    if (!smem_set) {
        cudaFuncSetAttribute(k_d2topk, cudaFuncAttributeMaxDynamicSharedMemorySize,
                             SMEM_D2);
        smem_set = 1;
    }

    k_lin_in<<<Nn, 64>>>(pos, linW, linb);

    for (int l = 0; l < Ll; l++) {
        // ---- KNN: bf16-hi prefilter + exact fp32 rerank ----
        k_split<<<Nn/8, 256>>>();
        k_d2topk<<<Nn/128, 256, SMEM_D2>>>();

        // ---- message MLP over E edges ----
        k_gemm_a<0><<<Ee/128, 256>>>(msgW1 + (size_t)l*128*64, msgb1 + l*64);
        k_stats<<<2048, 256>>>(0, Ee, 2048);
        k_stats_fin<<<1, 64>>>(Ee, 2048, msgg1 + l*64, msgbe1 + l*64);
        k_gemm_b<0><<<Ee/128, 256>>>(msgW2 + (size_t)l*64*64, msgb2 + l*64);
        k_stats<<<2048, 256>>>(1, Ee, 2048);
        k_stats_fin<<<1, 64>>>(Ee, 2048, msgg2 + l*64, msgbe2 + l*64);

        // ---- aggregate ----
        k_zero_agg<<<Nn*64/256, 256>>>();
        k_scatter<<<Ee*16/256, 256>>>();

        // ---- update MLP + residual ----
        k_gemm_a<1><<<Nn/128, 256>>>(updW1 + (size_t)l*128*64, updb1 + l*64);
        k_stats<<<64, 256>>>(2, Nn, 64);
        k_stats_fin<<<1, 64>>>(Nn, 64, updg1 + l*64, updbe1 + l*64);
        k_gemm_b<1><<<Nn/128, 256>>>(updW2 + (size_t)l*64*64, updb2 + l*64);
        k_stats<<<64, 256>>>(3, Nn, 64);
        k_stats_fin<<<1, 64>>>(Nn, 64, updg2 + l*64, updbe2 + l*64);
        k_resid<<<Nn*64/256, 256>>>();
    }

    k_stats<<<64, 256>>>(4, Nn, 64);
    k_fin<<<1, 64>>>(predW, predb, out, 64);
}

// round 8
// speedup vs baseline: 1.8831x; 1.8831x over previous
#include <cuda_runtime.h>
#include <cuda_bf16.h>
#include <cstdint>

#define Nn 16384
#define Dd 64
#define KK 17
#define Ee (Nn*16)
#define Ll 4

typedef unsigned long long ull;

// ---------------- scratch (static device allocations) ----------------
__device__ float g_h[Nn*Dd];
__device__ float g_hsq[Nn];                     // exact 0.5 * ||h_i||^2
__device__ int   g_idx[Nn*KK];
__device__ float g_y1[(size_t)Ee*Dd];
__device__ float g_y2[(size_t)Ee*Dd];
__device__ float g_agg[Nn*Dd];
__device__ float g_u1[Nn*Dd];
__device__ float g_u2[Nn*Dd];
__device__ float g_part[2048*128];
__device__ float g_scale[Dd];
__device__ float g_shift[Dd];
// pre-SW128-swizzled bf16 hi parts of h (row = node, 128 bytes/row)
__device__ unsigned g_hb_hi[Nn*32];

// ---------------- packed f32x2 helpers (for MLP GEMMs) ----------------
__device__ __forceinline__ ull ff2(ull a, ull b, ull c) {
    ull d;
    asm("fma.rn.f32x2 %0, %1, %2, %3;" : "=l"(d) : "l"(a), "l"(b), "l"(c));
    return d;
}
__device__ __forceinline__ ull dup2(float x) {
    ull d;
    unsigned u = __float_as_uint(x);
    asm("mov.b64 %0, {%1, %1};" : "=l"(d) : "r"(u));
    return d;
}
__device__ __forceinline__ float2 up2(ull v) {
    float2 r;
    asm("mov.b64 {%0, %1}, %2;" : "=f"(r.x), "=f"(r.y) : "l"(v));
    return r;
}

// ---------------- sm_80-era async-copy / ldmatrix / mma helpers --------
__device__ __forceinline__ uint32_t smem_u32(const void* p) {
    uint32_t a;
    asm("{ .reg .u64 t; cvta.to.shared.u64 t, %1; cvt.u32.u64 %0, t; }"
        : "=r"(a) : "l"(p));
    return a;
}
__device__ __forceinline__ void cp16(uint32_t d, const void* s) {
    asm volatile("cp.async.cg.shared.global [%0], [%1], 16;"
                 :: "r"(d), "l"(s) : "memory");
}
__device__ __forceinline__ void cp_commit() {
    asm volatile("cp.async.commit_group;" ::: "memory");
}
template<int N> __device__ __forceinline__ void cp_wait() {
    asm volatile("cp.async.wait_group %0;" :: "n"(N) : "memory");
}
__device__ __forceinline__ void ldsm4(uint32_t& r0, uint32_t& r1,
                                      uint32_t& r2, uint32_t& r3, uint32_t a) {
    asm volatile("ldmatrix.sync.aligned.m8n8.x4.shared.b16 {%0,%1,%2,%3}, [%4];"
                 : "=r"(r0), "=r"(r1), "=r"(r2), "=r"(r3) : "r"(a));
}
__device__ __forceinline__ void mma_bf16(float& c0, float& c1, float& c2, float& c3,
                                         uint32_t a0, uint32_t a1, uint32_t a2,
                                         uint32_t a3, uint32_t b0, uint32_t b1) {
    asm volatile(
        "mma.sync.aligned.m16n8k16.row.col.f32.bf16.bf16.f32 "
        "{%0,%1,%2,%3}, {%4,%5,%6,%7}, {%8,%9}, {%0,%1,%2,%3};"
        : "+f"(c0), "+f"(c1), "+f"(c2), "+f"(c3)
        : "r"(a0), "r"(a1), "r"(a2), "r"(a3), "r"(b0), "r"(b1));
}
__device__ __forceinline__ uint32_t sw128(uint32_t off) {
    return off ^ ((off >> 3) & 0x70u);
}

// ---------------- input projection ----------------
__global__ void k_lin_in(const float* __restrict__ pos,
                         const float* __restrict__ W,
                         const float* __restrict__ b) {
    __shared__ float sW[11*64];
    __shared__ float sp[11];
    const int i = blockIdx.x;
    const int f = threadIdx.x;
    for (int t = f; t < 11*64; t += 64) sW[t] = W[t];
    if (f < 11) sp[f] = pos[i*11 + f];
    __syncthreads();
    float acc = b[f];
    #pragma unroll
    for (int c = 0; c < 11; c++) acc = fmaf(sp[c], sW[c*64 + f], acc);
    g_h[i*64 + f] = acc;
}

// ---------------- bf16 hi + swizzled store + exact 0.5*sq --------------
__global__ void k_split() {
    const int node = blockIdx.x*8 + (threadIdx.x >> 5);
    const int lane = threadIdx.x & 31;
    float2 f = *(const float2*)(g_h + (size_t)node*64 + lane*2);

    __nv_bfloat16 h0 = __float2bfloat16(f.x);
    __nv_bfloat16 h1 = __float2bfloat16(f.y);

    unsigned off = (unsigned)node*128u + (unsigned)lane*4u;
    unsigned sw  = sw128(off);
    *(unsigned*)((char*)g_hb_hi + sw) =
        (unsigned)__bfloat16_as_ushort(h0) | ((unsigned)__bfloat16_as_ushort(h1) << 16);

    float s = f.x*f.x + f.y*f.y;            // exact fp32 norms
    #pragma unroll
    for (int o = 16; o > 0; o >>= 1) s += __shfl_down_sync(0xffffffffu, s, o);
    if (lane == 0) g_hsq[node] = 0.5f * s;
}

// ---------------- fused mma.sync d2 prefilter + exact rerank ------------
// smem (bytes from 1024-aligned base):
//  B bufs:  2 x 16384 = 32768  @ 0      (reused as fp32 A rows in rerank)
//  A:       16384              @ 32768
//  hsq:     2 x 512            @ 49152
//  lv:      512 lists x 17 x 4 @ 50176  (private top-16, pad stride 17)
//  li:      512 lists x 17 x 4 @ 84992
#define MC      16
#define LSTR    17
#define OB_B    0u
#define OB_A    32768u
#define OB_HSQ  49152u
#define OB_LV   50176u
#define OB_LI   84992u
#define SMEM_D2 (119808u + 1024u)

__device__ __forceinline__ void ins16(float* L, int* I, float v, int j) {
    int p = MC - 1;
    while (p > 0 && L[p-1] > v) { L[p] = L[p-1]; I[p] = I[p-1]; p--; }
    L[p] = v; I[p] = j;
}

__global__ __launch_bounds__(256) void k_d2topk() {
    extern __shared__ __align__(16) char smraw[];
    const uint32_t rawb = smem_u32(smraw);
    const uint32_t sb = (rawb + 1023u) & ~1023u;
    char* smc = smraw + (sb - rawb);

    const int tid  = threadIdx.x;
    const int w    = tid >> 5;
    const int lane = tid & 31;
    const int row0 = blockIdx.x * 128;

    float* lv  = (float*)(smc + OB_LV);
    int*   li_ = (int*)  (smc + OB_LI);

    // ---- prologue: async copies (A, B0, B1) — hi parts only ----
    {
        const char* srchi = (const char*)g_hb_hi + (size_t)row0*128;
        for (int i = tid; i < 1024; i += 256)
            cp16(sb + OB_A + i*16, srchi + i*16);
        cp_commit();
        #pragma unroll
        for (int tt = 0; tt < 2; tt++) {
            const char* bhi = (const char*)g_hb_hi + (size_t)tt*16384;
            uint32_t dst = sb + OB_B + (uint32_t)tt*16384u;
            for (int i = tid; i < 1024; i += 256)
                cp16(dst + i*16, bhi + i*16);
            if (tid < 32) cp16(sb + OB_HSQ + (uint32_t)tt*512u + tid*16,
                               (const char*)g_hsq + (size_t)tt*512 + tid*16);
            cp_commit();
        }
    }

    const int q   = lane >> 2;            // row within m16 (and +8)
    const int s3  = lane & 3;             // column pair selector
    const int lr0 = (w << 4) + q;
    const int lr1 = lr0 + 8;
    const int l0off = (lr0*4 + s3) * LSTR;
    const int l1off = (lr1*4 + s3) * LSTR;

    // init my two private lists
    #pragma unroll
    for (int p = 0; p < MC; p++) {
        lv[l0off + p] = 3.4e38f;  li_[l0off + p] = 0x7FFFFFFF;
        lv[l1off + p] = 3.4e38f;  li_[l1off + p] = 0x7FFFFFFF;
    }

    cp_wait<1>();          // A + B0 resident
    __syncthreads();

    // ---- preload A fragments (hi only, fixed across all tiles) ----
    uint32_t af[4][4];
    {
        const int m  = lane >> 3;
        const int rr = (w << 4) + ((m & 1) << 3) + (lane & 7);
        const int kb0 = (m >> 1) << 4;
        #pragma unroll
        for (int ks = 0; ks < 4; ks++) {
            uint32_t loc = (uint32_t)rr*128u + (uint32_t)(ks*32 + kb0);
            ldsm4(af[ks][0], af[ks][1], af[ks][2], af[ks][3],
                  sb + OB_A + sw128(loc));
        }
    }

    float th0 = 3.4e38f, th1 = 3.4e38f;

    const int bm = lane >> 3;             // ldmatrix B address helper
    const int bn = lane & 7;

    for (int t = 0; t < 128; t++) {
        const uint32_t bbase = sb + OB_B + (uint32_t)(t & 1)*16384u;
        const char* hsqp = smc + OB_HSQ + (uint32_t)(t & 1)*512u;
        const int jb = t * 128;

        #pragma unroll 1
        for (int nb = 0; nb < 16; nb++) {
            // ---- B fragments: hi only, 4 k-steps via 2 ldmatrix.x4 ----
            uint32_t bh[8];
            {
                uint32_t loc = (uint32_t)((nb*8 + bn)*128 + bm*16);
                ldsm4(bh[0], bh[1], bh[2], bh[3], bbase + sw128(loc));
                ldsm4(bh[4], bh[5], bh[6], bh[7], bbase + sw128(loc + 64u));
            }
            // ---- hi*hi only: 2 independent chains of 2 MMAs ----
            float h0 = 0.f, h1 = 0.f, h2 = 0.f, h3 = 0.f;
            float g0 = 0.f, g1 = 0.f, g2 = 0.f, g3 = 0.f;
            mma_bf16(h0, h1, h2, h3, af[0][0], af[0][1], af[0][2], af[0][3],
                     bh[0], bh[1]);
            mma_bf16(g0, g1, g2, g3, af[1][0], af[1][1], af[1][2], af[1][3],
                     bh[2], bh[3]);
            mma_bf16(h0, h1, h2, h3, af[2][0], af[2][1], af[2][2], af[2][3],
                     bh[4], bh[5]);
            mma_bf16(g0, g1, g2, g3, af[3][0], af[3][1], af[3][2], af[3][3],
                     bh[6], bh[7]);
            float c0 = h0 + g0;
            float c1 = h1 + g1;
            float c2 = h2 + g2;
            float c3 = h3 + g3;

            // ---- approx keys; fully private per-thread insertion ----
            float2 hs = *(const float2*)(hsqp + (nb*8 + 2*s3)*4);
            float k0 = hs.x - c0;
            float k1 = hs.y - c1;
            float k2 = hs.x - c2;
            float k3 = hs.y - c3;
            const int colb = jb + nb*8 + 2*s3;
            if (k0 < th0 || k1 < th0) {
                float* L0 = lv + l0off; int* I0 = li_ + l0off;
                if (k0 < th0) { ins16(L0, I0, k0, colb);   th0 = L0[MC-1]; }
                if (k1 < th0) { ins16(L0, I0, k1, colb+1); th0 = L0[MC-1]; }
            }
            if (k2 < th1 || k3 < th1) {
                float* L1 = lv + l1off; int* I1 = li_ + l1off;
                if (k2 < th1) { ins16(L1, I1, k2, colb);   th1 = L1[MC-1]; }
                if (k3 < th1) { ins16(L1, I1, k3, colb+1); th1 = L1[MC-1]; }
            }
        }

        __syncthreads();     // all warps done with buf[t&1]
        if (t + 2 < 128) {
            const int tt = t + 2;
            const char* bhi = (const char*)g_hb_hi + (size_t)tt*16384;
            uint32_t dst = sb + OB_B + (uint32_t)(t & 1)*16384u;
            for (int i = tid; i < 1024; i += 256)
                cp16(dst + i*16, bhi + i*16);
            if (tid < 32) cp16(sb + OB_HSQ + (uint32_t)(t & 1)*512u + tid*16,
                               (const char*)g_hsq + (size_t)tt*512 + tid*16);
            cp_commit();
            cp_wait<1>();    // tile t+1 resident
        } else {
            cp_wait<0>();
        }
        __syncthreads();
    }

    // ---- exact fp32 rerank over 64 candidates per row ----
    float* hrow = (float*)(smc + OB_B);     // reuse B buffers: 128 x 64 fp32
    {
        const float4* src = (const float4*)(g_h + (size_t)row0*64);
        float4* dst = (float4*)hrow;
        for (int i = tid; i < 2048; i += 256) dst[i] = src[i];
    }
    __syncthreads();

    for (int rr = 0; rr < 16; rr++) {
        const int row = (w << 4) + rr;
        const float4* hi4 = (const float4*)(hrow + row*64);

        float kv[2];
        int   ki[2];
        #pragma unroll
        for (int c = 0; c < 2; c++) {
            const int cand = lane + c*32;            // 0..63
            const int lidx = (row*4 + (cand >> 4)) * LSTR + (cand & 15);
            const int cidx = li_[lidx];
            const float4* hj = (const float4*)(g_h + (size_t)cidx*64);
            float s0 = 0.f, s1 = 0.f, s2 = 0.f, s3v = 0.f;
            #pragma unroll
            for (int kk = 0; kk < 16; kk++) {
                float4 a = hi4[kk];
                float4 b = hj[kk];
                s0 = fmaf(a.x, b.x, s0); s1 = fmaf(a.y, b.y, s1);
                s2 = fmaf(a.z, b.z, s2); s3v = fmaf(a.w, b.w, s3v);
            }
            kv[c] = g_hsq[cidx] - ((s0 + s1) + (s2 + s3v));
            ki[c] = cidx;
        }

        #pragma unroll
        for (int r = 0; r < KK; r++) {
            bool use0 = (kv[0] < kv[1]) || (kv[0] == kv[1] && ki[0] < ki[1]);
            float bv = use0 ? kv[0] : kv[1];
            int   bi = use0 ? ki[0] : ki[1];
            #pragma unroll
            for (int o = 16; o > 0; o >>= 1) {
                float ov = __shfl_xor_sync(0xffffffffu, bv, o);
                int   oi = __shfl_xor_sync(0xffffffffu, bi, o);
                if (ov < bv || (ov == bv && oi < bi)) { bv = ov; bi = oi; }
            }
            if (lane == 0) g_idx[(row0 + row)*KK + r] = bi;
            if (ki[0] == bi) kv[0] = 3.4e38f;
            else if (ki[1] == bi) kv[1] = 3.4e38f;
        }
    }
}

// ------------- GEMM A: depth-128 (MODE 0: msg gather, MODE 1: upd concat)
template<int MODE>
__global__ __launch_bounds__(256) void k_gemm_a(const float* __restrict__ W,
                                                const float* __restrict__ bias) {
    __shared__ float As[64][128];
    __shared__ float Ws[64][64];
    const int tid = threadIdx.x;
    const int e0  = blockIdx.x * 128;
    const int r0  = (tid >> 4) * 8;
    const int f0  = (tid & 15) * 4;
    ull acc[4][4];
    #pragma unroll
    for (int rp = 0; rp < 4; rp++)
        #pragma unroll
        for (int c = 0; c < 4; c++) acc[rp][c] = 0ull;

    for (int p = 0; p < 2; p++) {
        for (int t = tid; t < 1024; t += 256) {
            int f4 = t & 15, kk = t >> 4;
            *(float4*)&Ws[kk][f4<<2] =
                *(const float4*)(W + (size_t)((p<<6)+kk)*64 + (f4<<2));
        }
        for (int t = tid; t < 2048; t += 256) {
            int e = t & 127, k4 = t >> 7;
            int eg = e0 + e;
            const float* src;
            if (MODE == 0) {
                int i = eg & (Nn-1);
                int node = (p == 0) ? g_idx[i*KK + 1 + (eg >> 14)] : g_idx[i*KK];
                src = g_h + (size_t)node*64;
            } else {
                src = (p == 0 ? g_h : g_agg) + (size_t)eg*64;
            }
            float4 v = *(const float4*)(src + (k4<<2));
            As[(k4<<2)+0][e] = v.x; As[(k4<<2)+1][e] = v.y;
            As[(k4<<2)+2][e] = v.z; As[(k4<<2)+3][e] = v.w;
        }
        __syncthreads();
        #pragma unroll 4
        for (int k = 0; k < 64; k++) {
            ulonglong2 a01 = *(const ulonglong2*)(&As[k][r0]);
            ulonglong2 a23 = *(const ulonglong2*)(&As[k][r0+4]);
            float4 b = *(const float4*)(&Ws[k][f0]);
            ull ar[4] = { a01.x, a01.y, a23.x, a23.y };
            ull bd[4] = { dup2(b.x), dup2(b.y), dup2(b.z), dup2(b.w) };
            #pragma unroll
            for (int rp = 0; rp < 4; rp++)
                #pragma unroll
                for (int c = 0; c < 4; c++)
                    acc[rp][c] = ff2(ar[rp], bd[c], acc[rp][c]);
        }
        __syncthreads();
    }

    float* out = (MODE == 0) ? g_y1 : g_u1;
    float4 bv = *(const float4*)(bias + f0);
    #pragma unroll
    for (int rp = 0; rp < 4; rp++) {
        float2 u0 = up2(acc[rp][0]), u1 = up2(acc[rp][1]);
        float2 u2 = up2(acc[rp][2]), u3 = up2(acc[rp][3]);
        int ea = e0 + r0 + 2*rp;
        *(float4*)(out + (size_t)ea*64 + f0) =
            make_float4(u0.x + bv.x, u1.x + bv.y, u2.x + bv.z, u3.x + bv.w);
        *(float4*)(out + (size_t)(ea+1)*64 + f0) =
            make_float4(u0.y + bv.x, u1.y + bv.y, u2.y + bv.z, u3.y + bv.w);
    }
}

// ------------- GEMM B: depth-64 with fused BN-affine + ReLU on input ----
template<int MODE>
__global__ __launch_bounds__(256) void k_gemm_b(const float* __restrict__ W,
                                                const float* __restrict__ bias) {
    __shared__ float As[64][128];
    __shared__ float Ws[64][64];
    const int tid = threadIdx.x;
    const int e0  = blockIdx.x * 128;
    const int r0  = (tid >> 4) * 8;
    const int f0  = (tid & 15) * 4;

    const float* in = (MODE == 0) ? g_y1 : g_u1;

    for (int t = tid; t < 1024; t += 256) {
        int f4 = t & 15, kk = t >> 4;
        *(float4*)&Ws[kk][f4<<2] = *(const float4*)(W + (size_t)kk*64 + (f4<<2));
    }
    for (int t = tid; t < 2048; t += 256) {
        int e = t & 127, k4 = t >> 7;
        int eg = e0 + e;
        float4 v  = *(const float4*)(in + (size_t)eg*64 + (k4<<2));
        float4 sc = *(const float4*)(g_scale + (k4<<2));
        float4 sh = *(const float4*)(g_shift + (k4<<2));
        As[(k4<<2)+0][e] = fmaxf(fmaf(v.x, sc.x, sh.x), 0.f);
        As[(k4<<2)+1][e] = fmaxf(fmaf(v.y, sc.y, sh.y), 0.f);
        As[(k4<<2)+2][e] = fmaxf(fmaf(v.z, sc.z, sh.z), 0.f);
        As[(k4<<2)+3][e] = fmaxf(fmaf(v.w, sc.w, sh.w), 0.f);
    }
    __syncthreads();

    ull acc[4][4];
    #pragma unroll
    for (int rp = 0; rp < 4; rp++)
        #pragma unroll
        for (int c = 0; c < 4; c++) acc[rp][c] = 0ull;

    #pragma unroll 4
    for (int k = 0; k < 64; k++) {
        ulonglong2 a01 = *(const ulonglong2*)(&As[k][r0]);
        ulonglong2 a23 = *(const ulonglong2*)(&As[k][r0+4]);
        float4 b = *(const float4*)(&Ws[k][f0]);
        ull ar[4] = { a01.x, a01.y, a23.x, a23.y };
        ull bd[4] = { dup2(b.x), dup2(b.y), dup2(b.z), dup2(b.w) };
        #pragma unroll
        for (int rp = 0; rp < 4; rp++)
            #pragma unroll
            for (int c = 0; c < 4; c++)
                acc[rp][c] = ff2(ar[rp], bd[c], acc[rp][c]);
    }

    float* out = (MODE == 0) ? g_y2 : g_u2;
    float4 bv = *(const float4*)(bias + f0);
    #pragma unroll
    for (int rp = 0; rp < 4; rp++) {
        float2 u0 = up2(acc[rp][0]), u1 = up2(acc[rp][1]);
        float2 u2 = up2(acc[rp][2]), u3 = up2(acc[rp][3]);
        int ea = e0 + r0 + 2*rp;
        *(float4*)(out + (size_t)ea*64 + f0) =
            make_float4(u0.x + bv.x, u1.x + bv.y, u2.x + bv.z, u3.x + bv.w);
        *(float4*)(out + (size_t)(ea+1)*64 + f0) =
            make_float4(u0.y + bv.x, u1.y + bv.y, u2.y + bv.z, u3.y + bv.w);
    }
}

// ---------------- batch statistics (deterministic two-pass) ------------
__device__ __forceinline__ const float* stat_src(int sel) {
    switch (sel) {
        case 0: return g_y1;
        case 1: return g_y2;
        case 2: return g_u1;
        case 3: return g_u2;
        default: return g_h;
    }
}

__global__ void k_stats(int sel, int M, int P) {
    const float* __restrict__ x = stat_src(sel);
    const int t = threadIdx.x;
    float s = 0.f, s2 = 0.f;
    const size_t total = (size_t)M * 64;
    for (size_t idx = (size_t)blockIdx.x*256 + t; idx < total; idx += (size_t)P*256) {
        float v = x[idx];
        s += v; s2 = fmaf(v, v, s2);
    }
    __shared__ float sh[256], sh2[256];
    sh[t] = s; sh2[t] = s2;
    __syncthreads();
    if (t < 64) {
        s  = sh[t]  + sh[t+64]  + sh[t+128]  + sh[t+192];
        s2 = sh2[t] + sh2[t+64] + sh2[t+128] + sh2[t+192];
        g_part[(size_t)blockIdx.x*128 + t]      = s;
        g_part[(size_t)blockIdx.x*128 + 64 + t] = s2;
    }
}

__global__ void k_stats_fin(int M, int P,
                            const float* __restrict__ g,
                            const float* __restrict__ be) {
    const int f = threadIdx.x;
    float s = 0.f, s2 = 0.f;
    for (int p = 0; p < P; p++) {
        s  += g_part[(size_t)p*128 + f];
        s2 += g_part[(size_t)p*128 + 64 + f];
    }
    const float inv  = 1.f / (float)M;
    const float mean = s * inv;
    const float var  = fmaf(-mean, mean, s2 * inv);
    const float sc   = g[f] * rsqrtf(var + 1e-5f);
    g_scale[f] = sc;
    g_shift[f] = fmaf(-mean, sc, be[f]);
}

// ---------------- zero, scatter, residual ----------------
__global__ void k_zero_agg() {
    int i = blockIdx.x*blockDim.x + threadIdx.x;
    g_agg[i] = 0.f;
}

__global__ void k_scatter() {
    const int gid = blockIdx.x*256 + threadIdx.x;
    const int q = gid & 15;
    const int e = gid >> 4;
    const int i = e & (Nn-1);
    const int to = g_idx[i*KK + 1 + (e >> 14)];
    const int f = q << 2;
    float4 v  = *(const float4*)(g_y2 + (size_t)e*64 + f);
    float4 sc = *(const float4*)(g_scale + f);
    float4 sh = *(const float4*)(g_shift + f);
    float* dst = g_agg + (size_t)to*64 + f;
    atomicAdd(dst+0, fmaxf(fmaf(v.x, sc.x, sh.x), 0.f));
    atomicAdd(dst+1, fmaxf(fmaf(v.y, sc.y, sh.y), 0.f));
    atomicAdd(dst+2, fmaxf(fmaf(v.z, sc.z, sh.z), 0.f));
    atomicAdd(dst+3, fmaxf(fmaf(v.w, sc.w, sh.w), 0.f));
}

__global__ void k_resid() {
    const int gid = blockIdx.x*blockDim.x + threadIdx.x;
    const int f = gid & 63;
    const float v = g_u2[gid];
    g_h[gid] += fmaxf(fmaf(v, g_scale[f], g_shift[f]), 0.f);
}

// ---------------- final pool + prediction ----------------
__global__ void k_fin(const float* __restrict__ pW,
                      const float* __restrict__ pb,
                      float* __restrict__ out, int P) {
    const int f = threadIdx.x;
    float s = 0.f;
    for (int p = 0; p < P; p++) s += g_part[(size_t)p*128 + f];
    float v = (s / (float)Nn) * pW[f];
    __shared__ float red[64];
    red[f] = v;
    __syncthreads();
    if (f < 32) {
        float x = red[f] + red[f+32];
        #pragma unroll
        for (int o = 16; o > 0; o >>= 1) x += __shfl_down_sync(0xffffffffu, x, o);
        if (f == 0) out[0] = x + pb[0];
    }
}

// ---------------- host driver ----------------
extern "C" void kernel_launch(void* const* d_in, const int* in_sizes, int n_in,
                              void* d_out, int out_size) {
    const float* pos    = (const float*)d_in[0];
    const float* linW   = (const float*)d_in[1];
    const float* linb   = (const float*)d_in[2];
    const float* predW  = (const float*)d_in[3];
    const float* predb  = (const float*)d_in[4];
    const float* msgW1  = (const float*)d_in[5];
    const float* msgb1  = (const float*)d_in[6];
    const float* msgg1  = (const float*)d_in[7];
    const float* msgbe1 = (const float*)d_in[8];
    const float* msgW2  = (const float*)d_in[9];
    const float* msgb2  = (const float*)d_in[10];
    const float* msgg2  = (const float*)d_in[11];
    const float* msgbe2 = (const float*)d_in[12];
    const float* updW1  = (const float*)d_in[13];
    const float* updb1  = (const float*)d_in[14];
    const float* updg1  = (const float*)d_in[15];
    const float* updbe1 = (const float*)d_in[16];
    const float* updW2  = (const float*)d_in[17];
    const float* updb2  = (const float*)d_in[18];
    const float* updg2  = (const float*)d_in[19];
    const float* updbe2 = (const float*)d_in[20];
    float* out = (float*)d_out;

    static int smem_set = 0;
    if (!smem_set) {
        cudaFuncSetAttribute(k_d2topk, cudaFuncAttributeMaxDynamicSharedMemorySize,
                             SMEM_D2);
        smem_set = 1;
    }

    k_lin_in<<<Nn, 64>>>(pos, linW, linb);

    for (int l = 0; l < Ll; l++) {
        // ---- KNN: bf16-hi prefilter (private lists) + exact fp32 rerank ----
        k_split<<<Nn/8, 256>>>();
        k_d2topk<<<Nn/128, 256, SMEM_D2>>>();

        // ---- message MLP over E edges ----
        k_gemm_a<0><<<Ee/128, 256>>>(msgW1 + (size_t)l*128*64, msgb1 + l*64);
        k_stats<<<2048, 256>>>(0, Ee, 2048);
        k_stats_fin<<<1, 64>>>(Ee, 2048, msgg1 + l*64, msgbe1 + l*64);
        k_gemm_b<0><<<Ee/128, 256>>>(msgW2 + (size_t)l*64*64, msgb2 + l*64);
        k_stats<<<2048, 256>>>(1, Ee, 2048);
        k_stats_fin<<<1, 64>>>(Ee, 2048, msgg2 + l*64, msgbe2 + l*64);

        // ---- aggregate ----
        k_zero_agg<<<Nn*64/256, 256>>>();
        k_scatter<<<Ee*16/256, 256>>>();

        // ---- update MLP + residual ----
        k_gemm_a<1><<<Nn/128, 256>>>(updW1 + (size_t)l*128*64, updb1 + l*64);
        k_stats<<<64, 256>>>(2, Nn, 64);
        k_stats_fin<<<1, 64>>>(Nn, 64, updg1 + l*64, updbe1 + l*64);
        k_gemm_b<1><<<Nn/128, 256>>>(updW2 + (size_t)l*64*64, updb2 + l*64);
        k_stats<<<64, 256>>>(3, Nn, 64);
        k_stats_fin<<<1, 64>>>(Nn, 64, updg2 + l*64, updbe2 + l*64);
        k_resid<<<Nn*64/256, 256>>>();
    }

    k_stats<<<64, 256>>>(4, Nn, 64);
    k_fin<<<1, 64>>>(predW, predb, out, 64);
}

// round 9
// speedup vs baseline: 2.1879x; 1.1619x over previous
#include <cuda_runtime.h>
#include <cuda_bf16.h>
#include <cstdint>

#define Nn 16384
#define Dd 64
#define KK 17
#define Ee (Nn*16)
#define Ll 4

typedef unsigned long long ull;

// ---------------- scratch (static device allocations) ----------------
__device__ float g_h[Nn*Dd];
__device__ float g_hsq[Nn];                     // exact 0.5 * ||h_i||^2
__device__ int   g_idx[Nn*KK];
__device__ int   g_cand[(size_t)Nn*128];        // 128 prefilter candidates/row
__device__ float g_y1[(size_t)Ee*Dd];
__device__ float g_y2[(size_t)Ee*Dd];
__device__ float g_agg[Nn*Dd];
__device__ float g_u1[Nn*Dd];
__device__ float g_u2[Nn*Dd];
__device__ float g_part[2048*128];
__device__ float g_scale[Dd];
__device__ float g_shift[Dd];
// pre-SW128-swizzled bf16 hi parts of h (row = node, 128 bytes/row)
__device__ unsigned g_hb_hi[Nn*32];

// ---------------- packed f32x2 helpers (for MLP GEMMs) ----------------
__device__ __forceinline__ ull ff2(ull a, ull b, ull c) {
    ull d;
    asm("fma.rn.f32x2 %0, %1, %2, %3;" : "=l"(d) : "l"(a), "l"(b), "l"(c));
    return d;
}
__device__ __forceinline__ ull dup2(float x) {
    ull d;
    unsigned u = __float_as_uint(x);
    asm("mov.b64 %0, {%1, %1};" : "=l"(d) : "r"(u));
    return d;
}
__device__ __forceinline__ float2 up2(ull v) {
    float2 r;
    asm("mov.b64 {%0, %1}, %2;" : "=f"(r.x), "=f"(r.y) : "l"(v));
    return r;
}

// ---------------- sm_80-era async-copy / ldmatrix / mma helpers --------
__device__ __forceinline__ uint32_t smem_u32(const void* p) {
    uint32_t a;
    asm("{ .reg .u64 t; cvta.to.shared.u64 t, %1; cvt.u32.u64 %0, t; }"
        : "=r"(a) : "l"(p));
    return a;
}
__device__ __forceinline__ void cp16(uint32_t d, const void* s) {
    asm volatile("cp.async.cg.shared.global [%0], [%1], 16;"
                 :: "r"(d), "l"(s) : "memory");
}
__device__ __forceinline__ void cp_commit() {
    asm volatile("cp.async.commit_group;" ::: "memory");
}
template<int N> __device__ __forceinline__ void cp_wait() {
    asm volatile("cp.async.wait_group %0;" :: "n"(N) : "memory");
}
__device__ __forceinline__ void ldsm4(uint32_t& r0, uint32_t& r1,
                                      uint32_t& r2, uint32_t& r3, uint32_t a) {
    asm volatile("ldmatrix.sync.aligned.m8n8.x4.shared.b16 {%0,%1,%2,%3}, [%4];"
                 : "=r"(r0), "=r"(r1), "=r"(r2), "=r"(r3) : "r"(a));
}
__device__ __forceinline__ void mma_bf16(float& c0, float& c1, float& c2, float& c3,
                                         uint32_t a0, uint32_t a1, uint32_t a2,
                                         uint32_t a3, uint32_t b0, uint32_t b1) {
    asm volatile(
        "mma.sync.aligned.m16n8k16.row.col.f32.bf16.bf16.f32 "
        "{%0,%1,%2,%3}, {%4,%5,%6,%7}, {%8,%9}, {%0,%1,%2,%3};"
        : "+f"(c0), "+f"(c1), "+f"(c2), "+f"(c3)
        : "r"(a0), "r"(a1), "r"(a2), "r"(a3), "r"(b0), "r"(b1));
}
__device__ __forceinline__ uint32_t sw128(uint32_t off) {
    return off ^ ((off >> 3) & 0x70u);
}

// ---------------- input projection ----------------
__global__ void k_lin_in(const float* __restrict__ pos,
                         const float* __restrict__ W,
                         const float* __restrict__ b) {
    __shared__ float sW[11*64];
    __shared__ float sp[11];
    const int i = blockIdx.x;
    const int f = threadIdx.x;
    for (int t = f; t < 11*64; t += 64) sW[t] = W[t];
    if (f < 11) sp[f] = pos[i*11 + f];
    __syncthreads();
    float acc = b[f];
    #pragma unroll
    for (int c = 0; c < 11; c++) acc = fmaf(sp[c], sW[c*64 + f], acc);
    g_h[i*64 + f] = acc;
}

// ---------------- bf16 hi + swizzled store + exact 0.5*sq --------------
__global__ void k_split() {
    const int node = blockIdx.x*8 + (threadIdx.x >> 5);
    const int lane = threadIdx.x & 31;
    float2 f = *(const float2*)(g_h + (size_t)node*64 + lane*2);

    __nv_bfloat16 h0 = __float2bfloat16(f.x);
    __nv_bfloat16 h1 = __float2bfloat16(f.y);

    unsigned off = (unsigned)node*128u + (unsigned)lane*4u;
    unsigned sw  = sw128(off);
    *(unsigned*)((char*)g_hb_hi + sw) =
        (unsigned)__bfloat16_as_ushort(h0) | ((unsigned)__bfloat16_as_ushort(h1) << 16);

    float s = f.x*f.x + f.y*f.y;            // exact fp32 norms
    #pragma unroll
    for (int o = 16; o > 0; o >>= 1) s += __shfl_down_sync(0xffffffffu, s, o);
    if (lane == 0) g_hsq[node] = 0.5f * s;
}

// ---------------- prefilter: column-split mma.sync d2, packed top-16 ----
// grid 256: blockIdx = rowblk*2 + half. 128 rows x 8192 cols per CTA.
// smem (bytes from 1024-aligned base):
//  B bufs:  2 x 16384 = 32768  @ 0      (buf0 also stages A at start)
//  hsq:     2 x 512            @ 32768
//  lists:   512 x 17 u32       @ 33792  (packed key18|idx14, pad stride 17)
#define MCQ     16
#define LSTRQ   17
#define OB_B    0u
#define OB_HSQ  32768u
#define OB_L    33792u
#define SMEM_D2 (68608u + 1024u)

__device__ __forceinline__ uint32_t enc_key(float f, int idx) {
    uint32_t u = __float_as_uint(f);
    u = ((int)u < 0) ? ~u : (u | 0x80000000u);   // monotone float->uint
    return (u & 0xFFFFC000u) | (uint32_t)idx;    // key[18] | idx[14]
}
__device__ __forceinline__ void ins16p(uint32_t* L, uint32_t v) {
    int p = MCQ - 1;
    while (p > 0 && L[p-1] > v) { L[p] = L[p-1]; p--; }
    L[p] = v;
}

__global__ __launch_bounds__(256) void k_d2pref() {
    extern __shared__ __align__(16) char smraw[];
    const uint32_t rawb = smem_u32(smraw);
    const uint32_t sb = (rawb + 1023u) & ~1023u;
    char* smc = smraw + (sb - rawb);

    const int tid  = threadIdx.x;
    const int w    = tid >> 5;
    const int lane = tid & 31;
    const int rowblk = blockIdx.x >> 1;
    const int half   = blockIdx.x & 1;
    const int row0 = rowblk * 128;
    const int t0   = half * 64;

    uint32_t* Ls = (uint32_t*)(smc + OB_L);

    // ---- stage A (128 rows, hi) through B buf0 ----
    {
        const char* srchi = (const char*)g_hb_hi + (size_t)row0*128;
        for (int i = tid; i < 1024; i += 256)
            cp16(sb + OB_B + i*16, srchi + i*16);
        cp_commit();
        cp_wait<0>();
    }
    __syncthreads();

    uint32_t af[4][4];
    {
        const int m  = lane >> 3;
        const int rr = (w << 4) + ((m & 1) << 3) + (lane & 7);
        const int kb0 = (m >> 1) << 4;
        #pragma unroll
        for (int ks = 0; ks < 4; ks++) {
            uint32_t loc = (uint32_t)rr*128u + (uint32_t)(ks*32 + kb0);
            ldsm4(af[ks][0], af[ks][1], af[ks][2], af[ks][3],
                  sb + OB_B + sw128(loc));
        }
    }
    __syncthreads();      // A frags in regs; buf0 reusable

    // ---- private packed lists (two per thread) ----
    const int q   = lane >> 2;
    const int s3  = lane & 3;
    const int lr0 = (w << 4) + q;
    const int lr1 = lr0 + 8;
    uint32_t* L0 = Ls + (lr0*4 + s3) * LSTRQ;
    uint32_t* L1 = Ls + (lr1*4 + s3) * LSTRQ;
    #pragma unroll
    for (int p = 0; p < MCQ; p++) { L0[p] = 0xFFFFFFFFu; L1[p] = 0xFFFFFFFFu; }

    // ---- prefetch B tiles t0, t0+1 (+ hsq) ----
    #pragma unroll
    for (int u = 0; u < 2; u++) {
        const char* bhi = (const char*)g_hb_hi + (size_t)(t0 + u)*16384;
        uint32_t dst = sb + OB_B + (uint32_t)u*16384u;
        for (int i = tid; i < 1024; i += 256)
            cp16(dst + i*16, bhi + i*16);
        if (tid < 32) cp16(sb + OB_HSQ + (uint32_t)u*512u + tid*16,
                           (const char*)g_hsq + (size_t)(t0 + u)*512 + tid*16);
        cp_commit();
    }
    cp_wait<1>();
    __syncthreads();

    uint32_t th0 = 0xFFFFFFFFu, th1 = 0xFFFFFFFFu;
    const int bm = lane >> 3;
    const int bn = lane & 7;

    for (int tl = 0; tl < 64; tl++) {
        const uint32_t bbase = sb + OB_B + (uint32_t)(tl & 1)*16384u;
        const char* hsqp = smc + OB_HSQ + (uint32_t)(tl & 1)*512u;
        const int jb = (t0 + tl) * 128;

        #pragma unroll 1
        for (int nb = 0; nb < 16; nb++) {
            uint32_t bh[8];
            {
                uint32_t loc = (uint32_t)((nb*8 + bn)*128 + bm*16);
                ldsm4(bh[0], bh[1], bh[2], bh[3], bbase + sw128(loc));
                ldsm4(bh[4], bh[5], bh[6], bh[7], bbase + sw128(loc + 64u));
            }
            float h0 = 0.f, h1 = 0.f, h2 = 0.f, h3 = 0.f;
            float g0 = 0.f, g1 = 0.f, g2 = 0.f, g3 = 0.f;
            mma_bf16(h0, h1, h2, h3, af[0][0], af[0][1], af[0][2], af[0][3],
                     bh[0], bh[1]);
            mma_bf16(g0, g1, g2, g3, af[1][0], af[1][1], af[1][2], af[1][3],
                     bh[2], bh[3]);
            mma_bf16(h0, h1, h2, h3, af[2][0], af[2][1], af[2][2], af[2][3],
                     bh[4], bh[5]);
            mma_bf16(g0, g1, g2, g3, af[3][0], af[3][1], af[3][2], af[3][3],
                     bh[6], bh[7]);
            float c0 = h0 + g0;
            float c1 = h1 + g1;
            float c2 = h2 + g2;
            float c3 = h3 + g3;

            float2 hs = *(const float2*)(hsqp + (nb*8 + 2*s3)*4);
            const int colb = jb + nb*8 + 2*s3;
            uint32_t e0 = enc_key(hs.x - c0, colb);
            uint32_t e1 = enc_key(hs.y - c1, colb + 1);
            uint32_t e2 = enc_key(hs.x - c2, colb);
            uint32_t e3 = enc_key(hs.y - c3, colb + 1);
            if (e0 < th0 || e1 < th0) {
                if (e0 < th0) { ins16p(L0, e0); th0 = L0[MCQ-1]; }
                if (e1 < th0) { ins16p(L0, e1); th0 = L0[MCQ-1]; }
            }
            if (e2 < th1 || e3 < th1) {
                if (e2 < th1) { ins16p(L1, e2); th1 = L1[MCQ-1]; }
                if (e3 < th1) { ins16p(L1, e3); th1 = L1[MCQ-1]; }
            }
        }

        __syncthreads();     // all warps done with buf[tl&1]
        if (tl + 2 < 64) {
            const int tt = t0 + tl + 2;
            const char* bhi = (const char*)g_hb_hi + (size_t)tt*16384;
            uint32_t dst = sb + OB_B + (uint32_t)(tl & 1)*16384u;
            for (int i = tid; i < 1024; i += 256)
                cp16(dst + i*16, bhi + i*16);
            if (tid < 32) cp16(sb + OB_HSQ + (uint32_t)(tl & 1)*512u + tid*16,
                               (const char*)g_hsq + (size_t)tt*512 + tid*16);
            cp_commit();
            cp_wait<1>();
        } else {
            cp_wait<0>();
        }
        __syncthreads();
    }

    // ---- dump candidate indices ----
    #pragma unroll
    for (int p = 0; p < MCQ; p++) {
        g_cand[(size_t)(row0 + lr0)*128 + half*64 + s3*16 + p] = (int)(L0[p] & 0x3FFFu);
        g_cand[(size_t)(row0 + lr1)*128 + half*64 + s3*16 + p] = (int)(L1[p] & 0x3FFFu);
    }
}

// ---------------- exact fp32 rerank: 128 candidates -> top-17 ----------
__global__ __launch_bounds__(256) void k_rerank() {
    __shared__ float hi_s[8*64];
    const int tid  = threadIdx.x;
    const int w    = tid >> 5;
    const int lane = tid & 31;
    const int rbase = blockIdx.x * 8;

    for (int i = tid; i < 8*16; i += 256) {
        int r = i >> 4, k4 = i & 15;
        *(float4*)(hi_s + r*64 + k4*4) =
            *(const float4*)(g_h + (size_t)(rbase + r)*64 + k4*4);
    }
    __syncthreads();

    const int row = rbase + w;
    const float* hi4 = hi_s + w*64;

    float kv[4];
    int   ki[4];
    #pragma unroll
    for (int c = 0; c < 4; c++) {
        const int cidx = g_cand[(size_t)row*128 + lane + 32*c];
        const float4* hj = (const float4*)(g_h + (size_t)cidx*64);
        float s0 = 0.f, s1 = 0.f, s2 = 0.f, s3 = 0.f;
        #pragma unroll
        for (int kk = 0; kk < 16; kk++) {
            float4 a = *(const float4*)(hi4 + kk*4);
            float4 b = hj[kk];
            s0 = fmaf(a.x, b.x, s0); s1 = fmaf(a.y, b.y, s1);
            s2 = fmaf(a.z, b.z, s2); s3 = fmaf(a.w, b.w, s3);
        }
        kv[c] = g_hsq[cidx] - ((s0 + s1) + (s2 + s3));
        ki[c] = cidx;
    }

    #pragma unroll
    for (int r = 0; r < KK; r++) {
        float bv = kv[0]; int bi = ki[0];
        #pragma unroll
        for (int c = 1; c < 4; c++)
            if (kv[c] < bv || (kv[c] == bv && ki[c] < bi)) { bv = kv[c]; bi = ki[c]; }
        #pragma unroll
        for (int o = 16; o > 0; o >>= 1) {
            float ov = __shfl_xor_sync(0xffffffffu, bv, o);
            int   oi = __shfl_xor_sync(0xffffffffu, bi, o);
            if (ov < bv || (ov == bv && oi < bi)) { bv = ov; bi = oi; }
        }
        if (lane == 0) g_idx[row*KK + r] = bi;
        #pragma unroll
        for (int c = 0; c < 4; c++)
            if (ki[c] == bi) kv[c] = 3.4e38f;
    }
}

// ------------- GEMM A: depth-128 (MODE 0: msg gather, MODE 1: upd concat)
template<int MODE>
__global__ __launch_bounds__(256) void k_gemm_a(const float* __restrict__ W,
                                                const float* __restrict__ bias) {
    __shared__ float As[64][128];
    __shared__ float Ws[64][64];
    const int tid = threadIdx.x;
    const int e0  = blockIdx.x * 128;
    const int r0  = (tid >> 4) * 8;
    const int f0  = (tid & 15) * 4;
    ull acc[4][4];
    #pragma unroll
    for (int rp = 0; rp < 4; rp++)
        #pragma unroll
        for (int c = 0; c < 4; c++) acc[rp][c] = 0ull;

    for (int p = 0; p < 2; p++) {
        for (int t = tid; t < 1024; t += 256) {
            int f4 = t & 15, kk = t >> 4;
            *(float4*)&Ws[kk][f4<<2] =
                *(const float4*)(W + (size_t)((p<<6)+kk)*64 + (f4<<2));
        }
        for (int t = tid; t < 2048; t += 256) {
            int e = t & 127, k4 = t >> 7;
            int eg = e0 + e;
            const float* src;
            if (MODE == 0) {
                int i = eg & (Nn-1);
                int node = (p == 0) ? g_idx[i*KK + 1 + (eg >> 14)] : g_idx[i*KK];
                src = g_h + (size_t)node*64;
            } else {
                src = (p == 0 ? g_h : g_agg) + (size_t)eg*64;
            }
            float4 v = *(const float4*)(src + (k4<<2));
            As[(k4<<2)+0][e] = v.x; As[(k4<<2)+1][e] = v.y;
            As[(k4<<2)+2][e] = v.z; As[(k4<<2)+3][e] = v.w;
        }
        __syncthreads();
        #pragma unroll 4
        for (int k = 0; k < 64; k++) {
            ulonglong2 a01 = *(const ulonglong2*)(&As[k][r0]);
            ulonglong2 a23 = *(const ulonglong2*)(&As[k][r0+4]);
            float4 b = *(const float4*)(&Ws[k][f0]);
            ull ar[4] = { a01.x, a01.y, a23.x, a23.y };
            ull bd[4] = { dup2(b.x), dup2(b.y), dup2(b.z), dup2(b.w) };
            #pragma unroll
            for (int rp = 0; rp < 4; rp++)
                #pragma unroll
                for (int c = 0; c < 4; c++)
                    acc[rp][c] = ff2(ar[rp], bd[c], acc[rp][c]);
        }
        __syncthreads();
    }

    float* out = (MODE == 0) ? g_y1 : g_u1;
    float4 bv = *(const float4*)(bias + f0);
    #pragma unroll
    for (int rp = 0; rp < 4; rp++) {
        float2 u0 = up2(acc[rp][0]), u1 = up2(acc[rp][1]);
        float2 u2 = up2(acc[rp][2]), u3 = up2(acc[rp][3]);
        int ea = e0 + r0 + 2*rp;
        *(float4*)(out + (size_t)ea*64 + f0) =
            make_float4(u0.x + bv.x, u1.x + bv.y, u2.x + bv.z, u3.x + bv.w);
        *(float4*)(out + (size_t)(ea+1)*64 + f0) =
            make_float4(u0.y + bv.x, u1.y + bv.y, u2.y + bv.z, u3.y + bv.w);
    }
}

// ------------- GEMM B: depth-64 with fused BN-affine + ReLU on input ----
template<int MODE>
__global__ __launch_bounds__(256) void k_gemm_b(const float* __restrict__ W,
                                                const float* __restrict__ bias) {
    __shared__ float As[64][128];
    __shared__ float Ws[64][64];
    const int tid = threadIdx.x;
    const int e0  = blockIdx.x * 128;
    const int r0  = (tid >> 4) * 8;
    const int f0  = (tid & 15) * 4;

    const float* in = (MODE == 0) ? g_y1 : g_u1;

    for (int t = tid; t < 1024; t += 256) {
        int f4 = t & 15, kk = t >> 4;
        *(float4*)&Ws[kk][f4<<2] = *(const float4*)(W + (size_t)kk*64 + (f4<<2));
    }
    for (int t = tid; t < 2048; t += 256) {
        int e = t & 127, k4 = t >> 7;
        int eg = e0 + e;
        float4 v  = *(const float4*)(in + (size_t)eg*64 + (k4<<2));
        float4 sc = *(const float4*)(g_scale + (k4<<2));
        float4 sh = *(const float4*)(g_shift + (k4<<2));
        As[(k4<<2)+0][e] = fmaxf(fmaf(v.x, sc.x, sh.x), 0.f);
        As[(k4<<2)+1][e] = fmaxf(fmaf(v.y, sc.y, sh.y), 0.f);
        As[(k4<<2)+2][e] = fmaxf(fmaf(v.z, sc.z, sh.z), 0.f);
        As[(k4<<2)+3][e] = fmaxf(fmaf(v.w, sc.w, sh.w), 0.f);
    }
    __syncthreads();

    ull acc[4][4];
    #pragma unroll
    for (int rp = 0; rp < 4; rp++)
        #pragma unroll
        for (int c = 0; c < 4; c++) acc[rp][c] = 0ull;

    #pragma unroll 4
    for (int k = 0; k < 64; k++) {
        ulonglong2 a01 = *(const ulonglong2*)(&As[k][r0]);
        ulonglong2 a23 = *(const ulonglong2*)(&As[k][r0+4]);
        float4 b = *(const float4*)(&Ws[k][f0]);
        ull ar[4] = { a01.x, a01.y, a23.x, a23.y };
        ull bd[4] = { dup2(b.x), dup2(b.y), dup2(b.z), dup2(b.w) };
        #pragma unroll
        for (int rp = 0; rp < 4; rp++)
            #pragma unroll
            for (int c = 0; c < 4; c++)
                acc[rp][c] = ff2(ar[rp], bd[c], acc[rp][c]);
    }

    float* out = (MODE == 0) ? g_y2 : g_u2;
    float4 bv = *(const float4*)(bias + f0);
    #pragma unroll
    for (int rp = 0; rp < 4; rp++) {
        float2 u0 = up2(acc[rp][0]), u1 = up2(acc[rp][1]);
        float2 u2 = up2(acc[rp][2]), u3 = up2(acc[rp][3]);
        int ea = e0 + r0 + 2*rp;
        *(float4*)(out + (size_t)ea*64 + f0) =
            make_float4(u0.x + bv.x, u1.x + bv.y, u2.x + bv.z, u3.x + bv.w);
        *(float4*)(out + (size_t)(ea+1)*64 + f0) =
            make_float4(u0.y + bv.x, u1.y + bv.y, u2.y + bv.z, u3.y + bv.w);
    }
}

// ---------------- batch statistics (deterministic two-pass) ------------
__device__ __forceinline__ const float* stat_src(int sel) {
    switch (sel) {
        case 0: return g_y1;
        case 1: return g_y2;
        case 2: return g_u1;
        case 3: return g_u2;
        default: return g_h;
    }
}

__global__ void k_stats(int sel, int M, int P) {
    const float* __restrict__ x = stat_src(sel);
    const int t = threadIdx.x;
    float s = 0.f, s2 = 0.f;
    const size_t total = (size_t)M * 64;
    for (size_t idx = (size_t)blockIdx.x*256 + t; idx < total; idx += (size_t)P*256) {
        float v = x[idx];
        s += v; s2 = fmaf(v, v, s2);
    }
    __shared__ float sh[256], sh2[256];
    sh[t] = s; sh2[t] = s2;
    __syncthreads();
    if (t < 64) {
        s  = sh[t]  + sh[t+64]  + sh[t+128]  + sh[t+192];
        s2 = sh2[t] + sh2[t+64] + sh2[t+128] + sh2[t+192];
        g_part[(size_t)blockIdx.x*128 + t]      = s;
        g_part[(size_t)blockIdx.x*128 + 64 + t] = s2;
    }
}

__global__ void k_stats_fin(int M, int P,
                            const float* __restrict__ g,
                            const float* __restrict__ be) {
    const int f = threadIdx.x;
    float s = 0.f, s2 = 0.f;
    for (int p = 0; p < P; p++) {
        s  += g_part[(size_t)p*128 + f];
        s2 += g_part[(size_t)p*128 + 64 + f];
    }
    const float inv  = 1.f / (float)M;
    const float mean = s * inv;
    const float var  = fmaf(-mean, mean, s2 * inv);
    const float sc   = g[f] * rsqrtf(var + 1e-5f);
    g_scale[f] = sc;
    g_shift[f] = fmaf(-mean, sc, be[f]);
}

// ---------------- zero, scatter, residual ----------------
__global__ void k_zero_agg() {
    int i = blockIdx.x*blockDim.x + threadIdx.x;
    g_agg[i] = 0.f;
}

__global__ void k_scatter() {
    const int gid = blockIdx.x*256 + threadIdx.x;
    const int q = gid & 15;
    const int e = gid >> 4;
    const int i = e & (Nn-1);
    const int to = g_idx[i*KK + 1 + (e >> 14)];
    const int f = q << 2;
    float4 v  = *(const float4*)(g_y2 + (size_t)e*64 + f);
    float4 sc = *(const float4*)(g_scale + f);
    float4 sh = *(const float4*)(g_shift + f);
    float* dst = g_agg + (size_t)to*64 + f;
    atomicAdd(dst+0, fmaxf(fmaf(v.x, sc.x, sh.x), 0.f));
    atomicAdd(dst+1, fmaxf(fmaf(v.y, sc.y, sh.y), 0.f));
    atomicAdd(dst+2, fmaxf(fmaf(v.z, sc.z, sh.z), 0.f));
    atomicAdd(dst+3, fmaxf(fmaf(v.w, sc.w, sh.w), 0.f));
}

__global__ void k_resid() {
    const int gid = blockIdx.x*blockDim.x + threadIdx.x;
    const int f = gid & 63;
    const float v = g_u2[gid];
    g_h[gid] += fmaxf(fmaf(v, g_scale[f], g_shift[f]), 0.f);
}

// ---------------- final pool + prediction ----------------
__global__ void k_fin(const float* __restrict__ pW,
                      const float* __restrict__ pb,
                      float* __restrict__ out, int P) {
    const int f = threadIdx.x;
    float s = 0.f;
    for (int p = 0; p < P; p++) s += g_part[(size_t)p*128 + f];
    float v = (s / (float)Nn) * pW[f];
    __shared__ float red[64];
    red[f] = v;
    __syncthreads();
    if (f < 32) {
        float x = red[f] + red[f+32];
        #pragma unroll
        for (int o = 16; o > 0; o >>= 1) x += __shfl_down_sync(0xffffffffu, x, o);
        if (f == 0) out[0] = x + pb[0];
    }
}

// ---------------- host driver ----------------
extern "C" void kernel_launch(void* const* d_in, const int* in_sizes, int n_in,
                              void* d_out, int out_size) {
    const float* pos    = (const float*)d_in[0];
    const float* linW   = (const float*)d_in[1];
    const float* linb   = (const float*)d_in[2];
    const float* predW  = (const float*)d_in[3];
    const float* predb  = (const float*)d_in[4];
    const float* msgW1  = (const float*)d_in[5];
    const float* msgb1  = (const float*)d_in[6];
    const float* msgg1  = (const float*)d_in[7];
    const float* msgbe1 = (const float*)d_in[8];
    const float* msgW2  = (const float*)d_in[9];
    const float* msgb2  = (const float*)d_in[10];
    const float* msgg2  = (const float*)d_in[11];
    const float* msgbe2 = (const float*)d_in[12];
    const float* updW1  = (const float*)d_in[13];
    const float* updb1  = (const float*)d_in[14];
    const float* updg1  = (const float*)d_in[15];
    const float* updbe1 = (const float*)d_in[16];
    const float* updW2  = (const float*)d_in[17];
    const float* updb2  = (const float*)d_in[18];
    const float* updg2  = (const float*)d_in[19];
    const float* updbe2 = (const float*)d_in[20];
    float* out = (float*)d_out;

    static int smem_set = 0;
    if (!smem_set) {
        cudaFuncSetAttribute(k_d2pref, cudaFuncAttributeMaxDynamicSharedMemorySize,
                             SMEM_D2);
        smem_set = 1;
    }

    k_lin_in<<<Nn, 64>>>(pos, linW, linb);

    for (int l = 0; l < Ll; l++) {
        // ---- KNN: column-split prefilter + exact fp32 rerank ----
        k_split<<<Nn/8, 256>>>();
        k_d2pref<<<256, 256, SMEM_D2>>>();
        k_rerank<<<Nn/8, 256>>>();

        // ---- message MLP over E edges ----
        k_gemm_a<0><<<Ee/128, 256>>>(msgW1 + (size_t)l*128*64, msgb1 + l*64);
        k_stats<<<2048, 256>>>(0, Ee, 2048);
        k_stats_fin<<<1, 64>>>(Ee, 2048, msgg1 + l*64, msgbe1 + l*64);
        k_gemm_b<0><<<Ee/128, 256>>>(msgW2 + (size_t)l*64*64, msgb2 + l*64);
        k_stats<<<2048, 256>>>(1, Ee, 2048);
        k_stats_fin<<<1, 64>>>(Ee, 2048, msgg2 + l*64, msgbe2 + l*64);

        // ---- aggregate ----
        k_zero_agg<<<Nn*64/256, 256>>>();
        k_scatter<<<Ee*16/256, 256>>>();

        // ---- update MLP + residual ----
        k_gemm_a<1><<<Nn/128, 256>>>(updW1 + (size_t)l*128*64, updb1 + l*64);
        k_stats<<<64, 256>>>(2, Nn, 64);
        k_stats_fin<<<1, 64>>>(Nn, 64, updg1 + l*64, updbe1 + l*64);
        k_gemm_b<1><<<Nn/128, 256>>>(updW2 + (size_t)l*64*64, updb2 + l*64);
        k_stats<<<64, 256>>>(3, Nn, 64);
        k_stats_fin<<<1, 64>>>(Nn, 64, updg2 + l*64, updbe2 + l*64);
        k_resid<<<Nn*64/256, 256>>>();
    }

    k_stats<<<64, 256>>>(4, Nn, 64);
    k_fin<<<1, 64>>>(predW, predb, out, 64);
}

// round 10
// speedup vs baseline: 3.6281x; 1.6583x over previous
#include <cuda_runtime.h>
#include <cuda_bf16.h>
#include <cstdint>

#define Nn 16384
#define Dd 64
#define KK 17
#define Ee (Nn*16)
#define Ll 4

typedef unsigned long long ull;

// ---------------- scratch (static device allocations) ----------------
__device__ float g_h[Nn*Dd];
__device__ float g_hsq[Nn];                     // exact 0.5 * ||h_i||^2
__device__ int   g_idx[Nn*KK];
__device__ int   g_cand[(size_t)Nn*128];        // 128 prefilter candidates/row
__device__ float g_y1[(size_t)Ee*Dd];
__device__ float g_y2[(size_t)Ee*Dd];
__device__ float g_agg[Nn*Dd];
__device__ float g_u1[Nn*Dd];
__device__ float g_u2[Nn*Dd];
__device__ float g_part[2048*128];
__device__ float g_scale[Dd];
__device__ float g_shift[Dd];
// pre-SW128-swizzled bf16 hi parts of h (row = node, 128 bytes/row)
__device__ unsigned g_hb_hi[Nn*32];

// ---------------- packed f32x2 helpers (for MLP GEMMs) ----------------
__device__ __forceinline__ ull ff2(ull a, ull b, ull c) {
    ull d;
    asm("fma.rn.f32x2 %0, %1, %2, %3;" : "=l"(d) : "l"(a), "l"(b), "l"(c));
    return d;
}
__device__ __forceinline__ ull dup2(float x) {
    ull d;
    unsigned u = __float_as_uint(x);
    asm("mov.b64 %0, {%1, %1};" : "=l"(d) : "r"(u));
    return d;
}
__device__ __forceinline__ float2 up2(ull v) {
    float2 r;
    asm("mov.b64 {%0, %1}, %2;" : "=f"(r.x), "=f"(r.y) : "l"(v));
    return r;
}

// ---------------- sm_80-era async-copy / ldmatrix / mma helpers --------
__device__ __forceinline__ uint32_t smem_u32(const void* p) {
    uint32_t a;
    asm("{ .reg .u64 t; cvta.to.shared.u64 t, %1; cvt.u32.u64 %0, t; }"
        : "=r"(a) : "l"(p));
    return a;
}
__device__ __forceinline__ void cp16(uint32_t d, const void* s) {
    asm volatile("cp.async.cg.shared.global [%0], [%1], 16;"
                 :: "r"(d), "l"(s) : "memory");
}
__device__ __forceinline__ void cp_commit() {
    asm volatile("cp.async.commit_group;" ::: "memory");
}
template<int N> __device__ __forceinline__ void cp_wait() {
    asm volatile("cp.async.wait_group %0;" :: "n"(N) : "memory");
}
__device__ __forceinline__ void ldsm4(uint32_t& r0, uint32_t& r1,
                                      uint32_t& r2, uint32_t& r3, uint32_t a) {
    asm volatile("ldmatrix.sync.aligned.m8n8.x4.shared.b16 {%0,%1,%2,%3}, [%4];"
                 : "=r"(r0), "=r"(r1), "=r"(r2), "=r"(r3) : "r"(a));
}
__device__ __forceinline__ void mma_bf16(float& c0, float& c1, float& c2, float& c3,
                                         uint32_t a0, uint32_t a1, uint32_t a2,
                                         uint32_t a3, uint32_t b0, uint32_t b1) {
    asm volatile(
        "mma.sync.aligned.m16n8k16.row.col.f32.bf16.bf16.f32 "
        "{%0,%1,%2,%3}, {%4,%5,%6,%7}, {%8,%9}, {%0,%1,%2,%3};"
        : "+f"(c0), "+f"(c1), "+f"(c2), "+f"(c3)
        : "r"(a0), "r"(a1), "r"(a2), "r"(a3), "r"(b0), "r"(b1));
}
__device__ __forceinline__ uint32_t sw128(uint32_t off) {
    return off ^ ((off >> 3) & 0x70u);
}

// ---------------- input projection ----------------
__global__ void k_lin_in(const float* __restrict__ pos,
                         const float* __restrict__ W,
                         const float* __restrict__ b) {
    __shared__ float sW[11*64];
    __shared__ float sp[11];
    const int i = blockIdx.x;
    const int f = threadIdx.x;
    for (int t = f; t < 11*64; t += 64) sW[t] = W[t];
    if (f < 11) sp[f] = pos[i*11 + f];
    __syncthreads();
    float acc = b[f];
    #pragma unroll
    for (int c = 0; c < 11; c++) acc = fmaf(sp[c], sW[c*64 + f], acc);
    g_h[i*64 + f] = acc;
}

// ---------------- bf16 hi + swizzled store + exact 0.5*sq --------------
__global__ void k_split() {
    const int node = blockIdx.x*8 + (threadIdx.x >> 5);
    const int lane = threadIdx.x & 31;
    float2 f = *(const float2*)(g_h + (size_t)node*64 + lane*2);

    __nv_bfloat16 h0 = __float2bfloat16(f.x);
    __nv_bfloat16 h1 = __float2bfloat16(f.y);

    unsigned off = (unsigned)node*128u + (unsigned)lane*4u;
    unsigned sw  = sw128(off);
    *(unsigned*)((char*)g_hb_hi + sw) =
        (unsigned)__bfloat16_as_ushort(h0) | ((unsigned)__bfloat16_as_ushort(h1) << 16);

    float s = f.x*f.x + f.y*f.y;            // exact fp32 norms
    #pragma unroll
    for (int o = 16; o > 0; o >>= 1) s += __shfl_down_sync(0xffffffffu, s, o);
    if (lane == 0) g_hsq[node] = 0.5f * s;
}

// ---------------- prefilter: quarter-split mma.sync d2, register lists --
// grid 512: blockIdx = rowblk*4 + quarter. 128 rows x 4096 cols per CTA.
// smem: B bufs 2 x 16384 @0 (buf0 stages A at start), hsq 2 x 512 @32768
#define OB_B    0u
#define OB_HSQ  32768u
#define SMEM_D2 (33792u + 2048u)

__device__ __forceinline__ uint32_t enc_key(float f, int idx) {
    uint32_t u = __float_as_uint(f);
    u = ((int)u < 0) ? ~u : (u | 0x80000000u);   // monotone float->uint
    return (u & 0xFFFFC000u) | (uint32_t)idx;    // key[18] | idx[14]
}
// sorted-insert via unrolled min/max bubble (register-resident list)
__device__ __forceinline__ void ins8r(uint32_t* L, uint32_t v) {
    #pragma unroll
    for (int p = 0; p < 8; p++) {
        uint32_t lo = umin(L[p], v);
        v = umax(L[p], v);
        L[p] = lo;
    }
}

__global__ __launch_bounds__(256, 3) void k_d2pref() {
    extern __shared__ __align__(16) char smraw[];
    const uint32_t rawb = smem_u32(smraw);
    const uint32_t sb = (rawb + 1023u) & ~1023u;
    char* smc = smraw + (sb - rawb);

    const int tid  = threadIdx.x;
    const int w    = tid >> 5;
    const int lane = tid & 31;
    const int rowblk  = blockIdx.x >> 2;
    const int quarter = blockIdx.x & 3;
    const int row0 = rowblk * 128;
    const int t0   = quarter * 32;

    // ---- stage A (128 rows, hi) through B buf0 ----
    {
        const char* srchi = (const char*)g_hb_hi + (size_t)row0*128;
        for (int i = tid; i < 1024; i += 256)
            cp16(sb + OB_B + i*16, srchi + i*16);
        cp_commit();
        cp_wait<0>();
    }
    __syncthreads();

    uint32_t af[4][4];
    {
        const int m  = lane >> 3;
        const int rr = (w << 4) + ((m & 1) << 3) + (lane & 7);
        const int kb0 = (m >> 1) << 4;
        #pragma unroll
        for (int ks = 0; ks < 4; ks++) {
            uint32_t loc = (uint32_t)rr*128u + (uint32_t)(ks*32 + kb0);
            ldsm4(af[ks][0], af[ks][1], af[ks][2], af[ks][3],
                  sb + OB_B + sw128(loc));
        }
    }
    __syncthreads();      // A frags in regs; buf0 reusable

    // ---- register-resident private top-8 lists ----
    const int q   = lane >> 2;
    const int s3  = lane & 3;
    const int lr0 = (w << 4) + q;
    const int lr1 = lr0 + 8;
    uint32_t La[8], Lb[8];
    #pragma unroll
    for (int p = 0; p < 8; p++) { La[p] = 0xFFFFFFFFu; Lb[p] = 0xFFFFFFFFu; }
    uint32_t th0 = 0xFFFFFFFFu, th1 = 0xFFFFFFFFu;

    // ---- prefetch B tiles t0, t0+1 (+ hsq) ----
    #pragma unroll
    for (int u = 0; u < 2; u++) {
        const char* bhi = (const char*)g_hb_hi + (size_t)(t0 + u)*16384;
        uint32_t dst = sb + OB_B + (uint32_t)u*16384u;
        for (int i = tid; i < 1024; i += 256)
            cp16(dst + i*16, bhi + i*16);
        if (tid < 32) cp16(sb + OB_HSQ + (uint32_t)u*512u + tid*16,
                           (const char*)g_hsq + (size_t)(t0 + u)*512 + tid*16);
        cp_commit();
    }
    cp_wait<1>();
    __syncthreads();

    const int bm = lane >> 3;
    const int bn = lane & 7;

    for (int tl = 0; tl < 32; tl++) {
        const uint32_t bbase = sb + OB_B + (uint32_t)(tl & 1)*16384u;
        const char* hsqp = smc + OB_HSQ + (uint32_t)(tl & 1)*512u;
        const int jb = (t0 + tl) * 128;

        #pragma unroll 1
        for (int nb = 0; nb < 16; nb++) {
            uint32_t bh[8];
            {
                uint32_t loc = (uint32_t)((nb*8 + bn)*128 + bm*16);
                ldsm4(bh[0], bh[1], bh[2], bh[3], bbase + sw128(loc));
                ldsm4(bh[4], bh[5], bh[6], bh[7], bbase + sw128(loc + 64u));
            }
            float h0 = 0.f, h1 = 0.f, h2 = 0.f, h3 = 0.f;
            float g0 = 0.f, g1 = 0.f, g2 = 0.f, g3 = 0.f;
            mma_bf16(h0, h1, h2, h3, af[0][0], af[0][1], af[0][2], af[0][3],
                     bh[0], bh[1]);
            mma_bf16(g0, g1, g2, g3, af[1][0], af[1][1], af[1][2], af[1][3],
                     bh[2], bh[3]);
            mma_bf16(h0, h1, h2, h3, af[2][0], af[2][1], af[2][2], af[2][3],
                     bh[4], bh[5]);
            mma_bf16(g0, g1, g2, g3, af[3][0], af[3][1], af[3][2], af[3][3],
                     bh[6], bh[7]);
            float c0 = h0 + g0;
            float c1 = h1 + g1;
            float c2 = h2 + g2;
            float c3 = h3 + g3;

            float2 hs = *(const float2*)(hsqp + (nb*8 + 2*s3)*4);
            const int colb = jb + nb*8 + 2*s3;
            uint32_t e0 = enc_key(hs.x - c0, colb);
            uint32_t e1 = enc_key(hs.y - c1, colb + 1);
            uint32_t e2 = enc_key(hs.x - c2, colb);
            uint32_t e3 = enc_key(hs.y - c3, colb + 1);
            if (e0 < th0) { ins8r(La, e0); th0 = La[7]; }
            if (e1 < th0) { ins8r(La, e1); th0 = La[7]; }
            if (e2 < th1) { ins8r(Lb, e2); th1 = Lb[7]; }
            if (e3 < th1) { ins8r(Lb, e3); th1 = Lb[7]; }
        }

        __syncthreads();     // all warps done with buf[tl&1]
        if (tl + 2 < 32) {
            const int tt = t0 + tl + 2;
            const char* bhi = (const char*)g_hb_hi + (size_t)tt*16384;
            uint32_t dst = sb + OB_B + (uint32_t)(tl & 1)*16384u;
            for (int i = tid; i < 1024; i += 256)
                cp16(dst + i*16, bhi + i*16);
            if (tid < 32) cp16(sb + OB_HSQ + (uint32_t)(tl & 1)*512u + tid*16,
                               (const char*)g_hsq + (size_t)tt*512 + tid*16);
            cp_commit();
            cp_wait<1>();
        } else {
            cp_wait<0>();
        }
        __syncthreads();
    }

    // ---- dump candidate indices ----
    int* d0 = g_cand + (size_t)(row0 + lr0)*128 + quarter*32 + s3*8;
    int* d1 = g_cand + (size_t)(row0 + lr1)*128 + quarter*32 + s3*8;
    #pragma unroll
    for (int p = 0; p < 8; p++) {
        d0[p] = (int)(La[p] & 0x3FFFu);
        d1[p] = (int)(Lb[p] & 0x3FFFu);
    }
}

// ---------------- exact fp32 rerank: 128 candidates -> top-17 ----------
__global__ __launch_bounds__(256, 3) void k_rerank() {
    __shared__ float hi_s[8*64];
    const int tid  = threadIdx.x;
    const int w    = tid >> 5;
    const int lane = tid & 31;
    const int rbase = blockIdx.x * 8;

    for (int i = tid; i < 8*16; i += 256) {
        int r = i >> 4, k4 = i & 15;
        *(float4*)(hi_s + r*64 + k4*4) =
            *(const float4*)(g_h + (size_t)(rbase + r)*64 + k4*4);
    }
    __syncthreads();

    const int row = rbase + w;
    const float* hi4 = hi_s + w*64;

    float kv[4];
    int   ki[4];
    #pragma unroll
    for (int c = 0; c < 4; c++) {
        const int cidx = g_cand[(size_t)row*128 + lane + 32*c];
        const float4* hj = (const float4*)(g_h + (size_t)cidx*64);
        float s0 = 0.f, s1 = 0.f, s2 = 0.f, s3 = 0.f;
        #pragma unroll 4
        for (int kk = 0; kk < 16; kk++) {
            float4 a = *(const float4*)(hi4 + kk*4);
            float4 b = hj[kk];
            s0 = fmaf(a.x, b.x, s0); s1 = fmaf(a.y, b.y, s1);
            s2 = fmaf(a.z, b.z, s2); s3 = fmaf(a.w, b.w, s3);
        }
        kv[c] = g_hsq[cidx] - ((s0 + s1) + (s2 + s3));
        ki[c] = cidx;
    }

    #pragma unroll
    for (int r = 0; r < KK; r++) {
        float bv = kv[0]; int bi = ki[0];
        #pragma unroll
        for (int c = 1; c < 4; c++)
            if (kv[c] < bv || (kv[c] == bv && ki[c] < bi)) { bv = kv[c]; bi = ki[c]; }
        #pragma unroll
        for (int o = 16; o > 0; o >>= 1) {
            float ov = __shfl_xor_sync(0xffffffffu, bv, o);
            int   oi = __shfl_xor_sync(0xffffffffu, bi, o);
            if (ov < bv || (ov == bv && oi < bi)) { bv = ov; bi = oi; }
        }
        if (lane == 0) g_idx[row*KK + r] = bi;
        #pragma unroll
        for (int c = 0; c < 4; c++)
            if (ki[c] == bi) kv[c] = 3.4e38f;
    }
}

// ------------- GEMM A: depth-128 (MODE 0: msg gather, MODE 1: upd concat)
template<int MODE>
__global__ __launch_bounds__(256) void k_gemm_a(const float* __restrict__ W,
                                                const float* __restrict__ bias) {
    __shared__ float As[64][128];
    __shared__ float Ws[64][64];
    const int tid = threadIdx.x;
    const int e0  = blockIdx.x * 128;
    const int r0  = (tid >> 4) * 8;
    const int f0  = (tid & 15) * 4;
    ull acc[4][4];
    #pragma unroll
    for (int rp = 0; rp < 4; rp++)
        #pragma unroll
        for (int c = 0; c < 4; c++) acc[rp][c] = 0ull;

    for (int p = 0; p < 2; p++) {
        for (int t = tid; t < 1024; t += 256) {
            int f4 = t & 15, kk = t >> 4;
            *(float4*)&Ws[kk][f4<<2] =
                *(const float4*)(W + (size_t)((p<<6)+kk)*64 + (f4<<2));
        }
        for (int t = tid; t < 2048; t += 256) {
            int e = t & 127, k4 = t >> 7;
            int eg = e0 + e;
            const float* src;
            if (MODE == 0) {
                int i = eg & (Nn-1);
                int node = (p == 0) ? g_idx[i*KK + 1 + (eg >> 14)] : g_idx[i*KK];
                src = g_h + (size_t)node*64;
            } else {
                src = (p == 0 ? g_h : g_agg) + (size_t)eg*64;
            }
            float4 v = *(const float4*)(src + (k4<<2));
            As[(k4<<2)+0][e] = v.x; As[(k4<<2)+1][e] = v.y;
            As[(k4<<2)+2][e] = v.z; As[(k4<<2)+3][e] = v.w;
        }
        __syncthreads();
        #pragma unroll 4
        for (int k = 0; k < 64; k++) {
            ulonglong2 a01 = *(const ulonglong2*)(&As[k][r0]);
            ulonglong2 a23 = *(const ulonglong2*)(&As[k][r0+4]);
            float4 b = *(const float4*)(&Ws[k][f0]);
            ull ar[4] = { a01.x, a01.y, a23.x, a23.y };
            ull bd[4] = { dup2(b.x), dup2(b.y), dup2(b.z), dup2(b.w) };
            #pragma unroll
            for (int rp = 0; rp < 4; rp++)
                #pragma unroll
                for (int c = 0; c < 4; c++)
                    acc[rp][c] = ff2(ar[rp], bd[c], acc[rp][c]);
        }
        __syncthreads();
    }

    float* out = (MODE == 0) ? g_y1 : g_u1;
    float4 bv = *(const float4*)(bias + f0);
    #pragma unroll
    for (int rp = 0; rp < 4; rp++) {
        float2 u0 = up2(acc[rp][0]), u1 = up2(acc[rp][1]);
        float2 u2 = up2(acc[rp][2]), u3 = up2(acc[rp][3]);
        int ea = e0 + r0 + 2*rp;
        *(float4*)(out + (size_t)ea*64 + f0) =
            make_float4(u0.x + bv.x, u1.x + bv.y, u2.x + bv.z, u3.x + bv.w);
        *(float4*)(out + (size_t)(ea+1)*64 + f0) =
            make_float4(u0.y + bv.x, u1.y + bv.y, u2.y + bv.z, u3.y + bv.w);
    }
}

// ------------- GEMM B: depth-64 with fused BN-affine + ReLU on input ----
template<int MODE>
__global__ __launch_bounds__(256) void k_gemm_b(const float* __restrict__ W,
                                                const float* __restrict__ bias) {
    __shared__ float As[64][128];
    __shared__ float Ws[64][64];
    const int tid = threadIdx.x;
    const int e0  = blockIdx.x * 128;
    const int r0  = (tid >> 4) * 8;
    const int f0  = (tid & 15) * 4;

    const float* in = (MODE == 0) ? g_y1 : g_u1;

    for (int t = tid; t < 1024; t += 256) {
        int f4 = t & 15, kk = t >> 4;
        *(float4*)&Ws[kk][f4<<2] = *(const float4*)(W + (size_t)kk*64 + (f4<<2));
    }
    for (int t = tid; t < 2048; t += 256) {
        int e = t & 127, k4 = t >> 7;
        int eg = e0 + e;
        float4 v  = *(const float4*)(in + (size_t)eg*64 + (k4<<2));
        float4 sc = *(const float4*)(g_scale + (k4<<2));
        float4 sh = *(const float4*)(g_shift + (k4<<2));
        As[(k4<<2)+0][e] = fmaxf(fmaf(v.x, sc.x, sh.x), 0.f);
        As[(k4<<2)+1][e] = fmaxf(fmaf(v.y, sc.y, sh.y), 0.f);
        As[(k4<<2)+2][e] = fmaxf(fmaf(v.z, sc.z, sh.z), 0.f);
        As[(k4<<2)+3][e] = fmaxf(fmaf(v.w, sc.w, sh.w), 0.f);
    }
    __syncthreads();

    ull acc[4][4];
    #pragma unroll
    for (int rp = 0; rp < 4; rp++)
        #pragma unroll
        for (int c = 0; c < 4; c++) acc[rp][c] = 0ull;

    #pragma unroll 4
    for (int k = 0; k < 64; k++) {
        ulonglong2 a01 = *(const ulonglong2*)(&As[k][r0]);
        ulonglong2 a23 = *(const ulonglong2*)(&As[k][r0+4]);
        float4 b = *(const float4*)(&Ws[k][f0]);
        ull ar[4] = { a01.x, a01.y, a23.x, a23.y };
        ull bd[4] = { dup2(b.x), dup2(b.y), dup2(b.z), dup2(b.w) };
        #pragma unroll
        for (int rp = 0; rp < 4; rp++)
            #pragma unroll
            for (int c = 0; c < 4; c++)
                acc[rp][c] = ff2(ar[rp], bd[c], acc[rp][c]);
    }

    float* out = (MODE == 0) ? g_y2 : g_u2;
    float4 bv = *(const float4*)(bias + f0);
    #pragma unroll
    for (int rp = 0; rp < 4; rp++) {
        float2 u0 = up2(acc[rp][0]), u1 = up2(acc[rp][1]);
        float2 u2 = up2(acc[rp][2]), u3 = up2(acc[rp][3]);
        int ea = e0 + r0 + 2*rp;
        *(float4*)(out + (size_t)ea*64 + f0) =
            make_float4(u0.x + bv.x, u1.x + bv.y, u2.x + bv.z, u3.x + bv.w);
        *(float4*)(out + (size_t)(ea+1)*64 + f0) =
            make_float4(u0.y + bv.x, u1.y + bv.y, u2.y + bv.z, u3.y + bv.w);
    }
}

// ---------------- batch statistics (deterministic two-pass) ------------
__device__ __forceinline__ const float* stat_src(int sel) {
    switch (sel) {
        case 0: return g_y1;
        case 1: return g_y2;
        case 2: return g_u1;
        case 3: return g_u2;
        default: return g_h;
    }
}

__global__ void k_stats(int sel, int M, int P) {
    const float* __restrict__ x = stat_src(sel);
    const int t = threadIdx.x;
    float s = 0.f, s2 = 0.f;
    const size_t total = (size_t)M * 64;
    for (size_t idx = (size_t)blockIdx.x*256 + t; idx < total; idx += (size_t)P*256) {
        float v = x[idx];
        s += v; s2 = fmaf(v, v, s2);
    }
    __shared__ float sh[256], sh2[256];
    sh[t] = s; sh2[t] = s2;
    __syncthreads();
    if (t < 64) {
        s  = sh[t]  + sh[t+64]  + sh[t+128]  + sh[t+192];
        s2 = sh2[t] + sh2[t+64] + sh2[t+128] + sh2[t+192];
        g_part[(size_t)blockIdx.x*128 + t]      = s;
        g_part[(size_t)blockIdx.x*128 + 64 + t] = s2;
    }
}

__global__ void k_stats_fin(int M, int P,
                            const float* __restrict__ g,
                            const float* __restrict__ be) {
    const int f = threadIdx.x;
    float s = 0.f, s2 = 0.f;
    for (int p = 0; p < P; p++) {
        s  += g_part[(size_t)p*128 + f];
        s2 += g_part[(size_t)p*128 + 64 + f];
    }
    const float inv  = 1.f / (float)M;
    const float mean = s * inv;
    const float var  = fmaf(-mean, mean, s2 * inv);
    const float sc   = g[f] * rsqrtf(var + 1e-5f);
    g_scale[f] = sc;
    g_shift[f] = fmaf(-mean, sc, be[f]);
}

// ---------------- zero, scatter, residual ----------------
__global__ void k_zero_agg() {
    int i = blockIdx.x*blockDim.x + threadIdx.x;
    g_agg[i] = 0.f;
}

__global__ void k_scatter() {
    const int gid = blockIdx.x*256 + threadIdx.x;
    const int q = gid & 15;
    const int e = gid >> 4;
    const int i = e & (Nn-1);
    const int to = g_idx[i*KK + 1 + (e >> 14)];
    const int f = q << 2;
    float4 v  = *(const float4*)(g_y2 + (size_t)e*64 + f);
    float4 sc = *(const float4*)(g_scale + f);
    float4 sh = *(const float4*)(g_shift + f);
    float* dst = g_agg + (size_t)to*64 + f;
    atomicAdd(dst+0, fmaxf(fmaf(v.x, sc.x, sh.x), 0.f));
    atomicAdd(dst+1, fmaxf(fmaf(v.y, sc.y, sh.y), 0.f));
    atomicAdd(dst+2, fmaxf(fmaf(v.z, sc.z, sh.z), 0.f));
    atomicAdd(dst+3, fmaxf(fmaf(v.w, sc.w, sh.w), 0.f));
}

__global__ void k_resid() {
    const int gid = blockIdx.x*blockDim.x + threadIdx.x;
    const int f = gid & 63;
    const float v = g_u2[gid];
    g_h[gid] += fmaxf(fmaf(v, g_scale[f], g_shift[f]), 0.f);
}

// ---------------- final pool + prediction ----------------
__global__ void k_fin(const float* __restrict__ pW,
                      const float* __restrict__ pb,
                      float* __restrict__ out, int P) {
    const int f = threadIdx.x;
    float s = 0.f;
    for (int p = 0; p < P; p++) s += g_part[(size_t)p*128 + f];
    float v = (s / (float)Nn) * pW[f];
    __shared__ float red[64];
    red[f] = v;
    __syncthreads();
    if (f < 32) {
        float x = red[f] + red[f+32];
        #pragma unroll
        for (int o = 16; o > 0; o >>= 1) x += __shfl_down_sync(0xffffffffu, x, o);
        if (f == 0) out[0] = x + pb[0];
    }
}

// ---------------- host driver ----------------
extern "C" void kernel_launch(void* const* d_in, const int* in_sizes, int n_in,
                              void* d_out, int out_size) {
    const float* pos    = (const float*)d_in[0];
    const float* linW   = (const float*)d_in[1];
    const float* linb   = (const float*)d_in[2];
    const float* predW  = (const float*)d_in[3];
    const float* predb  = (const float*)d_in[4];
    const float* msgW1  = (const float*)d_in[5];
    const float* msgb1  = (const float*)d_in[6];
    const float* msgg1  = (const float*)d_in[7];
    const float* msgbe1 = (const float*)d_in[8];
    const float* msgW2  = (const float*)d_in[9];
    const float* msgb2  = (const float*)d_in[10];
    const float* msgg2  = (const float*)d_in[11];
    const float* msgbe2 = (const float*)d_in[12];
    const float* updW1  = (const float*)d_in[13];
    const float* updb1  = (const float*)d_in[14];
    const float* updg1  = (const float*)d_in[15];
    const float* updbe1 = (const float*)d_in[16];
    const float* updW2  = (const float*)d_in[17];
    const float* updb2  = (const float*)d_in[18];
    const float* updg2  = (const float*)d_in[19];
    const float* updbe2 = (const float*)d_in[20];
    float* out = (float*)d_out;

    static int smem_set = 0;
    if (!smem_set) {
        cudaFuncSetAttribute(k_d2pref, cudaFuncAttributeMaxDynamicSharedMemorySize,
                             SMEM_D2);
        smem_set = 1;
    }

    k_lin_in<<<Nn, 64>>>(pos, linW, linb);

    for (int l = 0; l < Ll; l++) {
        // ---- KNN: quarter-split prefilter (reg lists) + exact rerank ----
        k_split<<<Nn/8, 256>>>();
        k_d2pref<<<512, 256, SMEM_D2>>>();
        k_rerank<<<Nn/8, 256>>>();

        // ---- message MLP over E edges ----
        k_gemm_a<0><<<Ee/128, 256>>>(msgW1 + (size_t)l*128*64, msgb1 + l*64);
        k_stats<<<2048, 256>>>(0, Ee, 2048);
        k_stats_fin<<<1, 64>>>(Ee, 2048, msgg1 + l*64, msgbe1 + l*64);
        k_gemm_b<0><<<Ee/128, 256>>>(msgW2 + (size_t)l*64*64, msgb2 + l*64);
        k_stats<<<2048, 256>>>(1, Ee, 2048);
        k_stats_fin<<<1, 64>>>(Ee, 2048, msgg2 + l*64, msgbe2 + l*64);

        // ---- aggregate ----
        k_zero_agg<<<Nn*64/256, 256>>>();
        k_scatter<<<Ee*16/256, 256>>>();

        // ---- update MLP + residual ----
        k_gemm_a<1><<<Nn/128, 256>>>(updW1 + (size_t)l*128*64, updb1 + l*64);
        k_stats<<<64, 256>>>(2, Nn, 64);
        k_stats_fin<<<1, 64>>>(Nn, 64, updg1 + l*64, updbe1 + l*64);
        k_gemm_b<1><<<Nn/128, 256>>>(updW2 + (size_t)l*64*64, updb2 + l*64);
        k_stats<<<64, 256>>>(3, Nn, 64);
        k_stats_fin<<<1, 64>>>(Nn, 64, updg2 + l*64, updbe2 + l*64);
        k_resid<<<Nn*64/256, 256>>>();
    }

    k_stats<<<64, 256>>>(4, Nn, 64);
    k_fin<<<1, 64>>>(predW, predb, out, 64);
}

// round 11
// speedup vs baseline: 4.3438x; 1.1972x over previous
#include <cuda_runtime.h>
#include <cuda_bf16.h>
#include <cstdint>

#define Nn 16384
#define Dd 64
#define KK 17
#define Ee (Nn*16)
#define Ll 4

typedef unsigned long long ull;

// ---------------- scratch (static device allocations) ----------------
__device__ float g_h[Nn*Dd];
__device__ float g_hsq[Nn];                     // exact 0.5 * ||h_i||^2
__device__ int   g_idx[Nn*KK];
__device__ int   g_cand[(size_t)Nn*128];        // 128 prefilter candidates/row
__device__ float g_y1[(size_t)Ee*Dd];
__device__ float g_y2[(size_t)Ee*Dd];
__device__ float g_agg[Nn*Dd];
__device__ float g_u1[Nn*Dd];
__device__ float g_u2[Nn*Dd];
__device__ float g_part[2048*128];
__device__ float g_scale[Dd];
__device__ float g_shift[Dd];
// pre-SW128-swizzled bf16 hi parts of h (row = node, 128 bytes/row)
__device__ unsigned g_hb_hi[Nn*32];

// ---------------- packed f32x2 helpers (for MLP GEMMs) ----------------
__device__ __forceinline__ ull ff2(ull a, ull b, ull c) {
    ull d;
    asm("fma.rn.f32x2 %0, %1, %2, %3;" : "=l"(d) : "l"(a), "l"(b), "l"(c));
    return d;
}
__device__ __forceinline__ ull dup2(float x) {
    ull d;
    unsigned u = __float_as_uint(x);
    asm("mov.b64 %0, {%1, %1};" : "=l"(d) : "r"(u));
    return d;
}
__device__ __forceinline__ float2 up2(ull v) {
    float2 r;
    asm("mov.b64 {%0, %1}, %2;" : "=f"(r.x), "=f"(r.y) : "l"(v));
    return r;
}

// ---------------- sm_80-era async-copy / ldmatrix / mma helpers --------
__device__ __forceinline__ uint32_t smem_u32(const void* p) {
    uint32_t a;
    asm("{ .reg .u64 t; cvta.to.shared.u64 t, %1; cvt.u32.u64 %0, t; }"
        : "=r"(a) : "l"(p));
    return a;
}
__device__ __forceinline__ void cp16(uint32_t d, const void* s) {
    asm volatile("cp.async.cg.shared.global [%0], [%1], 16;"
                 :: "r"(d), "l"(s) : "memory");
}
__device__ __forceinline__ void cp_commit() {
    asm volatile("cp.async.commit_group;" ::: "memory");
}
template<int N> __device__ __forceinline__ void cp_wait() {
    asm volatile("cp.async.wait_group %0;" :: "n"(N) : "memory");
}
__device__ __forceinline__ void ldsm4(uint32_t& r0, uint32_t& r1,
                                      uint32_t& r2, uint32_t& r3, uint32_t a) {
    asm volatile("ldmatrix.sync.aligned.m8n8.x4.shared.b16 {%0,%1,%2,%3}, [%4];"
                 : "=r"(r0), "=r"(r1), "=r"(r2), "=r"(r3) : "r"(a));
}
__device__ __forceinline__ void mma_bf16(float& c0, float& c1, float& c2, float& c3,
                                         uint32_t a0, uint32_t a1, uint32_t a2,
                                         uint32_t a3, uint32_t b0, uint32_t b1) {
    asm volatile(
        "mma.sync.aligned.m16n8k16.row.col.f32.bf16.bf16.f32 "
        "{%0,%1,%2,%3}, {%4,%5,%6,%7}, {%8,%9}, {%0,%1,%2,%3};"
        : "+f"(c0), "+f"(c1), "+f"(c2), "+f"(c3)
        : "r"(a0), "r"(a1), "r"(a2), "r"(a3), "r"(b0), "r"(b1));
}
__device__ __forceinline__ uint32_t sw128(uint32_t off) {
    return off ^ ((off >> 3) & 0x70u);
}

// ---------------- input projection ----------------
__global__ void k_lin_in(const float* __restrict__ pos,
                         const float* __restrict__ W,
                         const float* __restrict__ b) {
    __shared__ float sW[11*64];
    __shared__ float sp[11];
    const int i = blockIdx.x;
    const int f = threadIdx.x;
    for (int t = f; t < 11*64; t += 64) sW[t] = W[t];
    if (f < 11) sp[f] = pos[i*11 + f];
    __syncthreads();
    float acc = b[f];
    #pragma unroll
    for (int c = 0; c < 11; c++) acc = fmaf(sp[c], sW[c*64 + f], acc);
    g_h[i*64 + f] = acc;
}

// ---------------- bf16 hi + swizzled store + exact 0.5*sq --------------
__global__ void k_split() {
    const int node = blockIdx.x*8 + (threadIdx.x >> 5);
    const int lane = threadIdx.x & 31;
    float2 f = *(const float2*)(g_h + (size_t)node*64 + lane*2);

    __nv_bfloat16 h0 = __float2bfloat16(f.x);
    __nv_bfloat16 h1 = __float2bfloat16(f.y);

    unsigned off = (unsigned)node*128u + (unsigned)lane*4u;
    unsigned sw  = sw128(off);
    *(unsigned*)((char*)g_hb_hi + sw) =
        (unsigned)__bfloat16_as_ushort(h0) | ((unsigned)__bfloat16_as_ushort(h1) << 16);

    float s = f.x*f.x + f.y*f.y;            // exact fp32 norms
    #pragma unroll
    for (int o = 16; o > 0; o >>= 1) s += __shfl_down_sync(0xffffffffu, s, o);
    if (lane == 0) g_hsq[node] = 0.5f * s;
}

// ---------------- prefilter: quarter-split mma.sync d2, register lists --
// grid 512: blockIdx = rowblk*4 + quarter. 128 rows x 4096 cols per CTA.
#define OB_B    0u
#define OB_HSQ  32768u
#define SMEM_D2 (33792u + 2048u)

__device__ __forceinline__ uint32_t enc_key(float f, int idx) {
    uint32_t u = __float_as_uint(f);
    u = ((int)u < 0) ? ~u : (u | 0x80000000u);   // monotone float->uint
    return (u & 0xFFFFC000u) | (uint32_t)idx;    // key[18] | idx[14]
}
__device__ __forceinline__ void ins8r(uint32_t* L, uint32_t v) {
    #pragma unroll
    for (int p = 0; p < 8; p++) {
        uint32_t lo = umin(L[p], v);
        v = umax(L[p], v);
        L[p] = lo;
    }
}

__global__ __launch_bounds__(256, 3) void k_d2pref() {
    extern __shared__ __align__(16) char smraw[];
    const uint32_t rawb = smem_u32(smraw);
    const uint32_t sb = (rawb + 1023u) & ~1023u;
    char* smc = smraw + (sb - rawb);

    const int tid  = threadIdx.x;
    const int w    = tid >> 5;
    const int lane = tid & 31;
    const int rowblk  = blockIdx.x >> 2;
    const int quarter = blockIdx.x & 3;
    const int row0 = rowblk * 128;
    const int t0   = quarter * 32;

    // ---- stage A (128 rows, hi) through B buf0 ----
    {
        const char* srchi = (const char*)g_hb_hi + (size_t)row0*128;
        for (int i = tid; i < 1024; i += 256)
            cp16(sb + OB_B + i*16, srchi + i*16);
        cp_commit();
        cp_wait<0>();
    }
    __syncthreads();

    uint32_t af[4][4];
    {
        const int m  = lane >> 3;
        const int rr = (w << 4) + ((m & 1) << 3) + (lane & 7);
        const int kb0 = (m >> 1) << 4;
        #pragma unroll
        for (int ks = 0; ks < 4; ks++) {
            uint32_t loc = (uint32_t)rr*128u + (uint32_t)(ks*32 + kb0);
            ldsm4(af[ks][0], af[ks][1], af[ks][2], af[ks][3],
                  sb + OB_B + sw128(loc));
        }
    }
    __syncthreads();      // A frags in regs; buf0 reusable

    const int q   = lane >> 2;
    const int s3  = lane & 3;
    const int lr0 = (w << 4) + q;
    const int lr1 = lr0 + 8;
    uint32_t La[8], Lb[8];
    #pragma unroll
    for (int p = 0; p < 8; p++) { La[p] = 0xFFFFFFFFu; Lb[p] = 0xFFFFFFFFu; }
    uint32_t th0 = 0xFFFFFFFFu, th1 = 0xFFFFFFFFu;

    #pragma unroll
    for (int u = 0; u < 2; u++) {
        const char* bhi = (const char*)g_hb_hi + (size_t)(t0 + u)*16384;
        uint32_t dst = sb + OB_B + (uint32_t)u*16384u;
        for (int i = tid; i < 1024; i += 256)
            cp16(dst + i*16, bhi + i*16);
        if (tid < 32) cp16(sb + OB_HSQ + (uint32_t)u*512u + tid*16,
                           (const char*)g_hsq + (size_t)(t0 + u)*512 + tid*16);
        cp_commit();
    }
    cp_wait<1>();
    __syncthreads();

    const int bm = lane >> 3;
    const int bn = lane & 7;

    for (int tl = 0; tl < 32; tl++) {
        const uint32_t bbase = sb + OB_B + (uint32_t)(tl & 1)*16384u;
        const char* hsqp = smc + OB_HSQ + (uint32_t)(tl & 1)*512u;
        const int jb = (t0 + tl) * 128;

        #pragma unroll 1
        for (int nb = 0; nb < 16; nb++) {
            uint32_t bh[8];
            {
                uint32_t loc = (uint32_t)((nb*8 + bn)*128 + bm*16);
                ldsm4(bh[0], bh[1], bh[2], bh[3], bbase + sw128(loc));
                ldsm4(bh[4], bh[5], bh[6], bh[7], bbase + sw128(loc + 64u));
            }
            float h0 = 0.f, h1 = 0.f, h2 = 0.f, h3 = 0.f;
            float g0 = 0.f, g1 = 0.f, g2 = 0.f, g3 = 0.f;
            mma_bf16(h0, h1, h2, h3, af[0][0], af[0][1], af[0][2], af[0][3],
                     bh[0], bh[1]);
            mma_bf16(g0, g1, g2, g3, af[1][0], af[1][1], af[1][2], af[1][3],
                     bh[2], bh[3]);
            mma_bf16(h0, h1, h2, h3, af[2][0], af[2][1], af[2][2], af[2][3],
                     bh[4], bh[5]);
            mma_bf16(g0, g1, g2, g3, af[3][0], af[3][1], af[3][2], af[3][3],
                     bh[6], bh[7]);
            float c0 = h0 + g0;
            float c1 = h1 + g1;
            float c2 = h2 + g2;
            float c3 = h3 + g3;

            float2 hs = *(const float2*)(hsqp + (nb*8 + 2*s3)*4);
            const int colb = jb + nb*8 + 2*s3;
            uint32_t e0 = enc_key(hs.x - c0, colb);
            uint32_t e1 = enc_key(hs.y - c1, colb + 1);
            uint32_t e2 = enc_key(hs.x - c2, colb);
            uint32_t e3 = enc_key(hs.y - c3, colb + 1);
            if (e0 < th0) { ins8r(La, e0); th0 = La[7]; }
            if (e1 < th0) { ins8r(La, e1); th0 = La[7]; }
            if (e2 < th1) { ins8r(Lb, e2); th1 = Lb[7]; }
            if (e3 < th1) { ins8r(Lb, e3); th1 = Lb[7]; }
        }

        __syncthreads();
        if (tl + 2 < 32) {
            const int tt = t0 + tl + 2;
            const char* bhi = (const char*)g_hb_hi + (size_t)tt*16384;
            uint32_t dst = sb + OB_B + (uint32_t)(tl & 1)*16384u;
            for (int i = tid; i < 1024; i += 256)
                cp16(dst + i*16, bhi + i*16);
            if (tid < 32) cp16(sb + OB_HSQ + (uint32_t)(tl & 1)*512u + tid*16,
                               (const char*)g_hsq + (size_t)tt*512 + tid*16);
            cp_commit();
            cp_wait<1>();
        } else {
            cp_wait<0>();
        }
        __syncthreads();
    }

    int* d0 = g_cand + (size_t)(row0 + lr0)*128 + quarter*32 + s3*8;
    int* d1 = g_cand + (size_t)(row0 + lr1)*128 + quarter*32 + s3*8;
    #pragma unroll
    for (int p = 0; p < 8; p++) {
        d0[p] = (int)(La[p] & 0x3FFFu);
        d1[p] = (int)(Lb[p] & 0x3FFFu);
    }
}

// ---------------- exact fp32 rerank (interleaved gather streams) -------
__global__ __launch_bounds__(256, 3) void k_rerank() {
    __shared__ float hi_s[8*64];
    const int tid  = threadIdx.x;
    const int w    = tid >> 5;
    const int lane = tid & 31;
    const int rbase = blockIdx.x * 8;

    for (int i = tid; i < 8*16; i += 256) {
        int r = i >> 4, k4 = i & 15;
        *(float4*)(hi_s + r*64 + k4*4) =
            *(const float4*)(g_h + (size_t)(rbase + r)*64 + k4*4);
    }
    __syncthreads();

    const int row = rbase + w;
    const float* hi4 = hi_s + w*64;

    int ki[4];
    const float4* hj[4];
    #pragma unroll
    for (int c = 0; c < 4; c++) {
        ki[c] = g_cand[(size_t)row*128 + lane + 32*c];
        hj[c] = (const float4*)(g_h + (size_t)ki[c]*64);
    }

    float sa[4] = {0.f, 0.f, 0.f, 0.f};
    float sb_[4] = {0.f, 0.f, 0.f, 0.f};
    #pragma unroll 4
    for (int kk = 0; kk < 16; kk++) {
        float4 a = *(const float4*)(hi4 + kk*4);
        #pragma unroll
        for (int c = 0; c < 4; c++) {
            float4 b = hj[c][kk];
            sa[c] = fmaf(a.x, b.x, fmaf(a.z, b.z, sa[c]));
            sb_[c] = fmaf(a.y, b.y, fmaf(a.w, b.w, sb_[c]));
        }
    }
    float kv[4];
    #pragma unroll
    for (int c = 0; c < 4; c++)
        kv[c] = g_hsq[ki[c]] - (sa[c] + sb_[c]);

    #pragma unroll
    for (int r = 0; r < KK; r++) {
        float bv = kv[0]; int bi = ki[0];
        #pragma unroll
        for (int c = 1; c < 4; c++)
            if (kv[c] < bv || (kv[c] == bv && ki[c] < bi)) { bv = kv[c]; bi = ki[c]; }
        #pragma unroll
        for (int o = 16; o > 0; o >>= 1) {
            float ov = __shfl_xor_sync(0xffffffffu, bv, o);
            int   oi = __shfl_xor_sync(0xffffffffu, bi, o);
            if (ov < bv || (ov == bv && oi < bi)) { bv = ov; bi = oi; }
        }
        if (lane == 0) g_idx[row*KK + r] = bi;
        #pragma unroll
        for (int c = 0; c < 4; c++)
            if (ki[c] == bi) kv[c] = 3.4e38f;
    }
}

// ------------- GEMM A: depth-128, FUSED per-CTA BN stats partials -------
template<int MODE>
__global__ __launch_bounds__(256) void k_gemm_a(const float* __restrict__ W,
                                                const float* __restrict__ bias) {
    __shared__ float As[64][128];
    __shared__ float Ws[64][64];
    const int tid = threadIdx.x;
    const int e0  = blockIdx.x * 128;
    const int r0  = (tid >> 4) * 8;
    const int f0  = (tid & 15) * 4;
    ull acc[4][4];
    #pragma unroll
    for (int rp = 0; rp < 4; rp++)
        #pragma unroll
        for (int c = 0; c < 4; c++) acc[rp][c] = 0ull;

    for (int p = 0; p < 2; p++) {
        for (int t = tid; t < 1024; t += 256) {
            int f4 = t & 15, kk = t >> 4;
            *(float4*)&Ws[kk][f4<<2] =
                *(const float4*)(W + (size_t)((p<<6)+kk)*64 + (f4<<2));
        }
        for (int t = tid; t < 2048; t += 256) {
            int e = t & 127, k4 = t >> 7;
            int eg = e0 + e;
            const float* src;
            if (MODE == 0) {
                int i = eg & (Nn-1);
                int node = (p == 0) ? g_idx[i*KK + 1 + (eg >> 14)] : g_idx[i*KK];
                src = g_h + (size_t)node*64;
            } else {
                src = (p == 0 ? g_h : g_agg) + (size_t)eg*64;
            }
            float4 v = *(const float4*)(src + (k4<<2));
            As[(k4<<2)+0][e] = v.x; As[(k4<<2)+1][e] = v.y;
            As[(k4<<2)+2][e] = v.z; As[(k4<<2)+3][e] = v.w;
        }
        __syncthreads();
        #pragma unroll 4
        for (int k = 0; k < 64; k++) {
            ulonglong2 a01 = *(const ulonglong2*)(&As[k][r0]);
            ulonglong2 a23 = *(const ulonglong2*)(&As[k][r0+4]);
            float4 b = *(const float4*)(&Ws[k][f0]);
            ull ar[4] = { a01.x, a01.y, a23.x, a23.y };
            ull bd[4] = { dup2(b.x), dup2(b.y), dup2(b.z), dup2(b.w) };
            #pragma unroll
            for (int rp = 0; rp < 4; rp++)
                #pragma unroll
                for (int c = 0; c < 4; c++)
                    acc[rp][c] = ff2(ar[rp], bd[c], acc[rp][c]);
        }
        __syncthreads();
    }

    float* out = (MODE == 0) ? g_y1 : g_u1;
    float4 bv = *(const float4*)(bias + f0);
    float fs[4] = {0.f,0.f,0.f,0.f}, fq[4] = {0.f,0.f,0.f,0.f};
    #pragma unroll
    for (int rp = 0; rp < 4; rp++) {
        float2 u0 = up2(acc[rp][0]), u1 = up2(acc[rp][1]);
        float2 u2 = up2(acc[rp][2]), u3 = up2(acc[rp][3]);
        int ea = e0 + r0 + 2*rp;
        float4 oA = make_float4(u0.x + bv.x, u1.x + bv.y, u2.x + bv.z, u3.x + bv.w);
        float4 oB = make_float4(u0.y + bv.x, u1.y + bv.y, u2.y + bv.z, u3.y + bv.w);
        *(float4*)(out + (size_t)ea*64 + f0) = oA;
        *(float4*)(out + (size_t)(ea+1)*64 + f0) = oB;
        fs[0] += oA.x + oB.x; fq[0] += oA.x*oA.x + oB.x*oB.x;
        fs[1] += oA.y + oB.y; fq[1] += oA.y*oA.y + oB.y*oB.y;
        fs[2] += oA.z + oB.z; fq[2] += oA.z*oA.z + oB.z*oB.z;
        fs[3] += oA.w + oB.w; fq[3] += oA.w*oA.w + oB.w*oB.w;
    }

    // per-CTA stats partials via As scratch (free after last sync)
    float* scr = &As[0][0];
    #pragma unroll
    for (int c = 0; c < 4; c++) {
        scr[tid*4 + c]        = fs[c];
        scr[1024 + tid*4 + c] = fq[c];
    }
    __syncthreads();
    if (tid < 64) {
        const int fg = tid >> 2, c = tid & 3;
        float S = 0.f, Q = 0.f;
        #pragma unroll
        for (int g = 0; g < 16; g++) {
            int idx = (g*16 + fg)*4 + c;
            S += scr[idx]; Q += scr[1024 + idx];
        }
        g_part[(size_t)blockIdx.x*128 + tid]      = S;
        g_part[(size_t)blockIdx.x*128 + 64 + tid] = Q;
    }
}

// ------------- GEMM B: depth-64, fused BN-affine+ReLU in, stats out ----
template<int MODE>
__global__ __launch_bounds__(256) void k_gemm_b(const float* __restrict__ W,
                                                const float* __restrict__ bias) {
    __shared__ float As[64][128];
    __shared__ float Ws[64][64];
    const int tid = threadIdx.x;
    const int e0  = blockIdx.x * 128;
    const int r0  = (tid >> 4) * 8;
    const int f0  = (tid & 15) * 4;

    const float* in = (MODE == 0) ? g_y1 : g_u1;

    for (int t = tid; t < 1024; t += 256) {
        int f4 = t & 15, kk = t >> 4;
        *(float4*)&Ws[kk][f4<<2] = *(const float4*)(W + (size_t)kk*64 + (f4<<2));
    }
    for (int t = tid; t < 2048; t += 256) {
        int e = t & 127, k4 = t >> 7;
        int eg = e0 + e;
        float4 v  = *(const float4*)(in + (size_t)eg*64 + (k4<<2));
        float4 sc = *(const float4*)(g_scale + (k4<<2));
        float4 sh = *(const float4*)(g_shift + (k4<<2));
        As[(k4<<2)+0][e] = fmaxf(fmaf(v.x, sc.x, sh.x), 0.f);
        As[(k4<<2)+1][e] = fmaxf(fmaf(v.y, sc.y, sh.y), 0.f);
        As[(k4<<2)+2][e] = fmaxf(fmaf(v.z, sc.z, sh.z), 0.f);
        As[(k4<<2)+3][e] = fmaxf(fmaf(v.w, sc.w, sh.w), 0.f);
    }
    __syncthreads();

    ull acc[4][4];
    #pragma unroll
    for (int rp = 0; rp < 4; rp++)
        #pragma unroll
        for (int c = 0; c < 4; c++) acc[rp][c] = 0ull;

    #pragma unroll 4
    for (int k = 0; k < 64; k++) {
        ulonglong2 a01 = *(const ulonglong2*)(&As[k][r0]);
        ulonglong2 a23 = *(const ulonglong2*)(&As[k][r0+4]);
        float4 b = *(const float4*)(&Ws[k][f0]);
        ull ar[4] = { a01.x, a01.y, a23.x, a23.y };
        ull bd[4] = { dup2(b.x), dup2(b.y), dup2(b.z), dup2(b.w) };
        #pragma unroll
        for (int rp = 0; rp < 4; rp++)
            #pragma unroll
            for (int c = 0; c < 4; c++)
                acc[rp][c] = ff2(ar[rp], bd[c], acc[rp][c]);
    }

    float* out = (MODE == 0) ? g_y2 : g_u2;
    float4 bv = *(const float4*)(bias + f0);
    float fs[4] = {0.f,0.f,0.f,0.f}, fq[4] = {0.f,0.f,0.f,0.f};
    #pragma unroll
    for (int rp = 0; rp < 4; rp++) {
        float2 u0 = up2(acc[rp][0]), u1 = up2(acc[rp][1]);
        float2 u2 = up2(acc[rp][2]), u3 = up2(acc[rp][3]);
        int ea = e0 + r0 + 2*rp;
        float4 oA = make_float4(u0.x + bv.x, u1.x + bv.y, u2.x + bv.z, u3.x + bv.w);
        float4 oB = make_float4(u0.y + bv.x, u1.y + bv.y, u2.y + bv.z, u3.y + bv.w);
        *(float4*)(out + (size_t)ea*64 + f0) = oA;
        *(float4*)(out + (size_t)(ea+1)*64 + f0) = oB;
        fs[0] += oA.x + oB.x; fq[0] += oA.x*oA.x + oB.x*oB.x;
        fs[1] += oA.y + oB.y; fq[1] += oA.y*oA.y + oB.y*oB.y;
        fs[2] += oA.z + oB.z; fq[2] += oA.z*oA.z + oB.z*oB.z;
        fs[3] += oA.w + oB.w; fq[3] += oA.w*oA.w + oB.w*oB.w;
    }

    __syncthreads();         // all As reads done before scratch reuse
    float* scr = &As[0][0];
    #pragma unroll
    for (int c = 0; c < 4; c++) {
        scr[tid*4 + c]        = fs[c];
        scr[1024 + tid*4 + c] = fq[c];
    }
    __syncthreads();
    if (tid < 64) {
        const int fg = tid >> 2, c = tid & 3;
        float S = 0.f, Q = 0.f;
        #pragma unroll
        for (int g = 0; g < 16; g++) {
            int idx = (g*16 + fg)*4 + c;
            S += scr[idx]; Q += scr[1024 + idx];
        }
        g_part[(size_t)blockIdx.x*128 + tid]      = S;
        g_part[(size_t)blockIdx.x*128 + 64 + tid] = Q;
    }
}

// ---------------- final-pool stats (over g_h) ----------------
__global__ void k_stats(int M, int P) {
    const float* __restrict__ x = g_h;
    const int t = threadIdx.x;
    float s = 0.f, s2 = 0.f;
    const size_t total = (size_t)M * 64;
    for (size_t idx = (size_t)blockIdx.x*256 + t; idx < total; idx += (size_t)P*256) {
        float v = x[idx];
        s += v; s2 = fmaf(v, v, s2);
    }
    __shared__ float sh[256], sh2[256];
    sh[t] = s; sh2[t] = s2;
    __syncthreads();
    if (t < 64) {
        s  = sh[t]  + sh[t+64]  + sh[t+128]  + sh[t+192];
        s2 = sh2[t] + sh2[t+64] + sh2[t+128] + sh2[t+192];
        g_part[(size_t)blockIdx.x*128 + t]      = s;
        g_part[(size_t)blockIdx.x*128 + 64 + t] = s2;
    }
}

// ---------------- stats finalize: 256-thread parallel reduce ----------
__global__ void k_stats_fin(int M, int P,
                            const float* __restrict__ g,
                            const float* __restrict__ be) {
    const int tid = threadIdx.x;
    const int f = tid & 63;
    const int part = tid >> 6;               // 0..3
    float s = 0.f, s2 = 0.f;
    for (int p = part; p < P; p += 4) {
        s  += g_part[(size_t)p*128 + f];
        s2 += g_part[(size_t)p*128 + 64 + f];
    }
    __shared__ float sh[256], sh2[256];
    sh[tid] = s; sh2[tid] = s2;
    __syncthreads();
    if (tid < 64) {
        s  = sh[tid]  + sh[tid+64]  + sh[tid+128]  + sh[tid+192];
        s2 = sh2[tid] + sh2[tid+64] + sh2[tid+128] + sh2[tid+192];
        const float inv  = 1.f / (float)M;
        const float mean = s * inv;
        const float var  = fmaf(-mean, mean, s2 * inv);
        const float sc   = g[tid] * rsqrtf(var + 1e-5f);
        g_scale[tid] = sc;
        g_shift[tid] = fmaf(-mean, sc, be[tid]);
    }
}

// ---------------- zero, scatter, residual ----------------
__global__ void k_zero_agg() {
    int i = blockIdx.x*blockDim.x + threadIdx.x;
    g_agg[i] = 0.f;
}

__global__ void k_scatter() {
    const int gid = blockIdx.x*256 + threadIdx.x;
    const int q = gid & 15;
    const int e = gid >> 4;
    const int i = e & (Nn-1);
    const int to = g_idx[i*KK + 1 + (e >> 14)];
    const int f = q << 2;
    float4 v  = *(const float4*)(g_y2 + (size_t)e*64 + f);
    float4 sc = *(const float4*)(g_scale + f);
    float4 sh = *(const float4*)(g_shift + f);
    float* dst = g_agg + (size_t)to*64 + f;
    atomicAdd(dst+0, fmaxf(fmaf(v.x, sc.x, sh.x), 0.f));
    atomicAdd(dst+1, fmaxf(fmaf(v.y, sc.y, sh.y), 0.f));
    atomicAdd(dst+2, fmaxf(fmaf(v.z, sc.z, sh.z), 0.f));
    atomicAdd(dst+3, fmaxf(fmaf(v.w, sc.w, sh.w), 0.f));
}

__global__ void k_resid() {
    const int gid = blockIdx.x*blockDim.x + threadIdx.x;
    const int f = gid & 63;
    const float v = g_u2[gid];
    g_h[gid] += fmaxf(fmaf(v, g_scale[f], g_shift[f]), 0.f);
}

// ---------------- final pool + prediction ----------------
__global__ void k_fin(const float* __restrict__ pW,
                      const float* __restrict__ pb,
                      float* __restrict__ out, int P) {
    const int f = threadIdx.x;
    float s = 0.f;
    for (int p = 0; p < P; p++) s += g_part[(size_t)p*128 + f];
    float v = (s / (float)Nn) * pW[f];
    __shared__ float red[64];
    red[f] = v;
    __syncthreads();
    if (f < 32) {
        float x = red[f] + red[f+32];
        #pragma unroll
        for (int o = 16; o > 0; o >>= 1) x += __shfl_down_sync(0xffffffffu, x, o);
        if (f == 0) out[0] = x + pb[0];
    }
}

// ---------------- host driver ----------------
extern "C" void kernel_launch(void* const* d_in, const int* in_sizes, int n_in,
                              void* d_out, int out_size) {
    const float* pos    = (const float*)d_in[0];
    const float* linW   = (const float*)d_in[1];
    const float* linb   = (const float*)d_in[2];
    const float* predW  = (const float*)d_in[3];
    const float* predb  = (const float*)d_in[4];
    const float* msgW1  = (const float*)d_in[5];
    const float* msgb1  = (const float*)d_in[6];
    const float* msgg1  = (const float*)d_in[7];
    const float* msgbe1 = (const float*)d_in[8];
    const float* msgW2  = (const float*)d_in[9];
    const float* msgb2  = (const float*)d_in[10];
    const float* msgg2  = (const float*)d_in[11];
    const float* msgbe2 = (const float*)d_in[12];
    const float* updW1  = (const float*)d_in[13];
    const float* updb1  = (const float*)d_in[14];
    const float* updg1  = (const float*)d_in[15];
    const float* updbe1 = (const float*)d_in[16];
    const float* updW2  = (const float*)d_in[17];
    const float* updb2  = (const float*)d_in[18];
    const float* updg2  = (const float*)d_in[19];
    const float* updbe2 = (const float*)d_in[20];
    float* out = (float*)d_out;

    static int smem_set = 0;
    if (!smem_set) {
        cudaFuncSetAttribute(k_d2pref, cudaFuncAttributeMaxDynamicSharedMemorySize,
                             SMEM_D2);
        smem_set = 1;
    }

    k_lin_in<<<Nn, 64>>>(pos, linW, linb);

    for (int l = 0; l < Ll; l++) {
        // ---- KNN: quarter-split prefilter (reg lists) + exact rerank ----
        k_split<<<Nn/8, 256>>>();
        k_d2pref<<<512, 256, SMEM_D2>>>();
        k_rerank<<<Nn/8, 256>>>();

        // ---- message MLP over E edges (stats fused into GEMMs) ----
        k_gemm_a<0><<<Ee/128, 256>>>(msgW1 + (size_t)l*128*64, msgb1 + l*64);
        k_stats_fin<<<1, 256>>>(Ee, 2048, msgg1 + l*64, msgbe1 + l*64);
        k_gemm_b<0><<<Ee/128, 256>>>(msgW2 + (size_t)l*64*64, msgb2 + l*64);
        k_stats_fin<<<1, 256>>>(Ee, 2048, msgg2 + l*64, msgbe2 + l*64);

        // ---- aggregate ----
        k_zero_agg<<<Nn*64/256, 256>>>();
        k_scatter<<<Ee*16/256, 256>>>();

        // ---- update MLP + residual (stats fused) ----
        k_gemm_a<1><<<Nn/128, 256>>>(updW1 + (size_t)l*128*64, updb1 + l*64);
        k_stats_fin<<<1, 256>>>(Nn, 128, updg1 + l*64, updbe1 + l*64);
        k_gemm_b<1><<<Nn/128, 256>>>(updW2 + (size_t)l*64*64, updb2 + l*64);
        k_stats_fin<<<1, 256>>>(Nn, 128, updg2 + l*64, updbe2 + l*64);
        k_resid<<<Nn*64/256, 256>>>();
    }

    k_stats<<<64, 256>>>(Nn, 64);
    k_fin<<<1, 64>>>(predW, predb, out, 64);
}

// round 12
// speedup vs baseline: 4.8048x; 1.1061x over previous
#include <cuda_runtime.h>
#include <cuda_bf16.h>
#include <cstdint>

#define Nn 16384
#define Dd 64
#define KK 17
#define Ee (Nn*16)
#define Ll 4

typedef unsigned long long ull;

// ---------------- scratch (static device allocations) ----------------
__device__ float g_h[Nn*Dd];
__device__ float g_hsq[Nn];                     // exact 0.5 * ||h_i||^2
__device__ int   g_idx[Nn*KK];
__device__ int   g_cand[(size_t)Nn*128];        // 128 prefilter candidates/row
__device__ float g_P[Nn*Dd];                    // h @ W1_top          (msg)
__device__ float g_Q[Nn*Dd];                    // h @ W1_bot + b1     (msg)
__device__ float g_y2[(size_t)Ee*Dd];
__device__ float g_agg[Nn*Dd];
__device__ float g_u1[Nn*Dd];
__device__ float g_u2[Nn*Dd];
__device__ float g_part[2048*128];
__device__ float g_scale[Dd];
__device__ float g_shift[Dd];
// pre-SW128-swizzled bf16 hi parts of h (row = node, 128 bytes/row)
__device__ unsigned g_hb_hi[Nn*32];

// ---------------- packed f32x2 helpers (for MLP GEMMs) ----------------
__device__ __forceinline__ ull ff2(ull a, ull b, ull c) {
    ull d;
    asm("fma.rn.f32x2 %0, %1, %2, %3;" : "=l"(d) : "l"(a), "l"(b), "l"(c));
    return d;
}
__device__ __forceinline__ ull dup2(float x) {
    ull d;
    unsigned u = __float_as_uint(x);
    asm("mov.b64 %0, {%1, %1};" : "=l"(d) : "r"(u));
    return d;
}
__device__ __forceinline__ float2 up2(ull v) {
    float2 r;
    asm("mov.b64 {%0, %1}, %2;" : "=f"(r.x), "=f"(r.y) : "l"(v));
    return r;
}

// ---------------- sm_80-era async-copy / ldmatrix / mma helpers --------
__device__ __forceinline__ uint32_t smem_u32(const void* p) {
    uint32_t a;
    asm("{ .reg .u64 t; cvta.to.shared.u64 t, %1; cvt.u32.u64 %0, t; }"
        : "=r"(a) : "l"(p));
    return a;
}
__device__ __forceinline__ void cp16(uint32_t d, const void* s) {
    asm volatile("cp.async.cg.shared.global [%0], [%1], 16;"
                 :: "r"(d), "l"(s) : "memory");
}
__device__ __forceinline__ void cp_commit() {
    asm volatile("cp.async.commit_group;" ::: "memory");
}
template<int N> __device__ __forceinline__ void cp_wait() {
    asm volatile("cp.async.wait_group %0;" :: "n"(N) : "memory");
}
__device__ __forceinline__ void ldsm4(uint32_t& r0, uint32_t& r1,
                                      uint32_t& r2, uint32_t& r3, uint32_t a) {
    asm volatile("ldmatrix.sync.aligned.m8n8.x4.shared.b16 {%0,%1,%2,%3}, [%4];"
                 : "=r"(r0), "=r"(r1), "=r"(r2), "=r"(r3) : "r"(a));
}
__device__ __forceinline__ void mma_bf16(float& c0, float& c1, float& c2, float& c3,
                                         uint32_t a0, uint32_t a1, uint32_t a2,
                                         uint32_t a3, uint32_t b0, uint32_t b1) {
    asm volatile(
        "mma.sync.aligned.m16n8k16.row.col.f32.bf16.bf16.f32 "
        "{%0,%1,%2,%3}, {%4,%5,%6,%7}, {%8,%9}, {%0,%1,%2,%3};"
        : "+f"(c0), "+f"(c1), "+f"(c2), "+f"(c3)
        : "r"(a0), "r"(a1), "r"(a2), "r"(a3), "r"(b0), "r"(b1));
}
__device__ __forceinline__ uint32_t sw128(uint32_t off) {
    return off ^ ((off >> 3) & 0x70u);
}

// ---------------- input projection ----------------
__global__ void k_lin_in(const float* __restrict__ pos,
                         const float* __restrict__ W,
                         const float* __restrict__ b) {
    __shared__ float sW[11*64];
    __shared__ float sp[11];
    const int i = blockIdx.x;
    const int f = threadIdx.x;
    for (int t = f; t < 11*64; t += 64) sW[t] = W[t];
    if (f < 11) sp[f] = pos[i*11 + f];
    __syncthreads();
    float acc = b[f];
    #pragma unroll
    for (int c = 0; c < 11; c++) acc = fmaf(sp[c], sW[c*64 + f], acc);
    g_h[i*64 + f] = acc;
}

// ---------------- bf16 hi + swizzled store + exact 0.5*sq --------------
__global__ void k_split() {
    const int node = blockIdx.x*8 + (threadIdx.x >> 5);
    const int lane = threadIdx.x & 31;
    float2 f = *(const float2*)(g_h + (size_t)node*64 + lane*2);

    __nv_bfloat16 h0 = __float2bfloat16(f.x);
    __nv_bfloat16 h1 = __float2bfloat16(f.y);

    unsigned off = (unsigned)node*128u + (unsigned)lane*4u;
    unsigned sw  = sw128(off);
    *(unsigned*)((char*)g_hb_hi + sw) =
        (unsigned)__bfloat16_as_ushort(h0) | ((unsigned)__bfloat16_as_ushort(h1) << 16);

    float s = f.x*f.x + f.y*f.y;            // exact fp32 norms
    #pragma unroll
    for (int o = 16; o > 0; o >>= 1) s += __shfl_down_sync(0xffffffffu, s, o);
    if (lane == 0) g_hsq[node] = 0.5f * s;
}

// ---------------- prefilter: quarter-split mma.sync d2, register lists --
#define OB_B    0u
#define OB_HSQ  32768u
#define SMEM_D2 (33792u + 2048u)

__device__ __forceinline__ uint32_t enc_key(float f, int idx) {
    uint32_t u = __float_as_uint(f);
    u = ((int)u < 0) ? ~u : (u | 0x80000000u);   // monotone float->uint
    return (u & 0xFFFFC000u) | (uint32_t)idx;    // key[18] | idx[14]
}
__device__ __forceinline__ void ins8r(uint32_t* L, uint32_t v) {
    #pragma unroll
    for (int p = 0; p < 8; p++) {
        uint32_t lo = umin(L[p], v);
        v = umax(L[p], v);
        L[p] = lo;
    }
}

__global__ __launch_bounds__(256, 3) void k_d2pref() {
    extern __shared__ __align__(16) char smraw[];
    const uint32_t rawb = smem_u32(smraw);
    const uint32_t sb = (rawb + 1023u) & ~1023u;
    char* smc = smraw + (sb - rawb);

    const int tid  = threadIdx.x;
    const int w    = tid >> 5;
    const int lane = tid & 31;
    const int rowblk  = blockIdx.x >> 2;
    const int quarter = blockIdx.x & 3;
    const int row0 = rowblk * 128;
    const int t0   = quarter * 32;

    // ---- stage A (128 rows, hi) through B buf0 ----
    {
        const char* srchi = (const char*)g_hb_hi + (size_t)row0*128;
        for (int i = tid; i < 1024; i += 256)
            cp16(sb + OB_B + i*16, srchi + i*16);
        cp_commit();
        cp_wait<0>();
    }
    __syncthreads();

    uint32_t af[4][4];
    {
        const int m  = lane >> 3;
        const int rr = (w << 4) + ((m & 1) << 3) + (lane & 7);
        const int kb0 = (m >> 1) << 4;
        #pragma unroll
        for (int ks = 0; ks < 4; ks++) {
            uint32_t loc = (uint32_t)rr*128u + (uint32_t)(ks*32 + kb0);
            ldsm4(af[ks][0], af[ks][1], af[ks][2], af[ks][3],
                  sb + OB_B + sw128(loc));
        }
    }
    __syncthreads();      // A frags in regs; buf0 reusable

    const int q   = lane >> 2;
    const int s3  = lane & 3;
    const int lr0 = (w << 4) + q;
    const int lr1 = lr0 + 8;
    uint32_t La[8], Lb[8];
    #pragma unroll
    for (int p = 0; p < 8; p++) { La[p] = 0xFFFFFFFFu; Lb[p] = 0xFFFFFFFFu; }
    uint32_t th0 = 0xFFFFFFFFu, th1 = 0xFFFFFFFFu;

    #pragma unroll
    for (int u = 0; u < 2; u++) {
        const char* bhi = (const char*)g_hb_hi + (size_t)(t0 + u)*16384;
        uint32_t dst = sb + OB_B + (uint32_t)u*16384u;
        for (int i = tid; i < 1024; i += 256)
            cp16(dst + i*16, bhi + i*16);
        if (tid < 32) cp16(sb + OB_HSQ + (uint32_t)u*512u + tid*16,
                           (const char*)g_hsq + (size_t)(t0 + u)*512 + tid*16);
        cp_commit();
    }
    cp_wait<1>();
    __syncthreads();

    const int bm = lane >> 3;
    const int bn = lane & 7;

    for (int tl = 0; tl < 32; tl++) {
        const uint32_t bbase = sb + OB_B + (uint32_t)(tl & 1)*16384u;
        const char* hsqp = smc + OB_HSQ + (uint32_t)(tl & 1)*512u;
        const int jb = (t0 + tl) * 128;

        #pragma unroll 1
        for (int nb = 0; nb < 16; nb++) {
            uint32_t bh[8];
            {
                uint32_t loc = (uint32_t)((nb*8 + bn)*128 + bm*16);
                ldsm4(bh[0], bh[1], bh[2], bh[3], bbase + sw128(loc));
                ldsm4(bh[4], bh[5], bh[6], bh[7], bbase + sw128(loc + 64u));
            }
            float h0 = 0.f, h1 = 0.f, h2 = 0.f, h3 = 0.f;
            float g0 = 0.f, g1 = 0.f, g2 = 0.f, g3 = 0.f;
            mma_bf16(h0, h1, h2, h3, af[0][0], af[0][1], af[0][2], af[0][3],
                     bh[0], bh[1]);
            mma_bf16(g0, g1, g2, g3, af[1][0], af[1][1], af[1][2], af[1][3],
                     bh[2], bh[3]);
            mma_bf16(h0, h1, h2, h3, af[2][0], af[2][1], af[2][2], af[2][3],
                     bh[4], bh[5]);
            mma_bf16(g0, g1, g2, g3, af[3][0], af[3][1], af[3][2], af[3][3],
                     bh[6], bh[7]);
            float c0 = h0 + g0;
            float c1 = h1 + g1;
            float c2 = h2 + g2;
            float c3 = h3 + g3;

            float2 hs = *(const float2*)(hsqp + (nb*8 + 2*s3)*4);
            const int colb = jb + nb*8 + 2*s3;
            uint32_t e0 = enc_key(hs.x - c0, colb);
            uint32_t e1 = enc_key(hs.y - c1, colb + 1);
            uint32_t e2 = enc_key(hs.x - c2, colb);
            uint32_t e3 = enc_key(hs.y - c3, colb + 1);
            if (e0 < th0) { ins8r(La, e0); th0 = La[7]; }
            if (e1 < th0) { ins8r(La, e1); th0 = La[7]; }
            if (e2 < th1) { ins8r(Lb, e2); th1 = Lb[7]; }
            if (e3 < th1) { ins8r(Lb, e3); th1 = Lb[7]; }
        }

        __syncthreads();
        if (tl + 2 < 32) {
            const int tt = t0 + tl + 2;
            const char* bhi = (const char*)g_hb_hi + (size_t)tt*16384;
            uint32_t dst = sb + OB_B + (uint32_t)(tl & 1)*16384u;
            for (int i = tid; i < 1024; i += 256)
                cp16(dst + i*16, bhi + i*16);
            if (tid < 32) cp16(sb + OB_HSQ + (uint32_t)(tl & 1)*512u + tid*16,
                               (const char*)g_hsq + (size_t)tt*512 + tid*16);
            cp_commit();
            cp_wait<1>();
        } else {
            cp_wait<0>();
        }
        __syncthreads();
    }

    int* d0 = g_cand + (size_t)(row0 + lr0)*128 + quarter*32 + s3*8;
    int* d1 = g_cand + (size_t)(row0 + lr1)*128 + quarter*32 + s3*8;
    #pragma unroll
    for (int p = 0; p < 8; p++) {
        d0[p] = (int)(La[p] & 0x3FFFu);
        d1[p] = (int)(Lb[p] & 0x3FFFu);
    }
}

// ---------------- exact fp32 rerank (interleaved gather streams) -------
__global__ __launch_bounds__(256, 3) void k_rerank() {
    __shared__ float hi_s[8*64];
    const int tid  = threadIdx.x;
    const int w    = tid >> 5;
    const int lane = tid & 31;
    const int rbase = blockIdx.x * 8;

    for (int i = tid; i < 8*16; i += 256) {
        int r = i >> 4, k4 = i & 15;
        *(float4*)(hi_s + r*64 + k4*4) =
            *(const float4*)(g_h + (size_t)(rbase + r)*64 + k4*4);
    }
    __syncthreads();

    const int row = rbase + w;
    const float* hi4 = hi_s + w*64;

    int ki[4];
    const float4* hj[4];
    #pragma unroll
    for (int c = 0; c < 4; c++) {
        ki[c] = g_cand[(size_t)row*128 + lane + 32*c];
        hj[c] = (const float4*)(g_h + (size_t)ki[c]*64);
    }

    float sa[4] = {0.f, 0.f, 0.f, 0.f};
    float sb_[4] = {0.f, 0.f, 0.f, 0.f};
    #pragma unroll 4
    for (int kk = 0; kk < 16; kk++) {
        float4 a = *(const float4*)(hi4 + kk*4);
        #pragma unroll
        for (int c = 0; c < 4; c++) {
            float4 b = hj[c][kk];
            sa[c] = fmaf(a.x, b.x, fmaf(a.z, b.z, sa[c]));
            sb_[c] = fmaf(a.y, b.y, fmaf(a.w, b.w, sb_[c]));
        }
    }
    float kv[4];
    #pragma unroll
    for (int c = 0; c < 4; c++)
        kv[c] = g_hsq[ki[c]] - (sa[c] + sb_[c]);

    #pragma unroll
    for (int r = 0; r < KK; r++) {
        float bv = kv[0]; int bi = ki[0];
        #pragma unroll
        for (int c = 1; c < 4; c++)
            if (kv[c] < bv || (kv[c] == bv && ki[c] < bi)) { bv = kv[c]; bi = ki[c]; }
        #pragma unroll
        for (int o = 16; o > 0; o >>= 1) {
            float ov = __shfl_xor_sync(0xffffffffu, bv, o);
            int   oi = __shfl_xor_sync(0xffffffffu, bi, o);
            if (ov < bv || (ov == bv && oi < bi)) { bv = ov; bi = oi; }
        }
        if (lane == 0) g_idx[row*KK + r] = bi;
        #pragma unroll
        for (int c = 0; c < 4; c++)
            if (ki[c] == bi) kv[c] = 3.4e38f;
    }
}

// ------------- P/Q factorization: P = h@W1_top, Q = h@W1_bot + b1 -------
__global__ __launch_bounds__(256) void k_pq(const float* __restrict__ W,
                                            const float* __restrict__ b1) {
    __shared__ float As[64][128];
    __shared__ float Ws[64][64];
    const int tid = threadIdx.x;
    const int e0  = blockIdx.x * 128;
    const int r0  = (tid >> 4) * 8;
    const int f0  = (tid & 15) * 4;

    for (int t = tid; t < 2048; t += 256) {
        int e = t & 127, k4 = t >> 7;
        float4 v = *(const float4*)(g_h + (size_t)(e0 + e)*64 + (k4<<2));
        As[(k4<<2)+0][e] = v.x; As[(k4<<2)+1][e] = v.y;
        As[(k4<<2)+2][e] = v.z; As[(k4<<2)+3][e] = v.w;
    }

    for (int p = 0; p < 2; p++) {
        __syncthreads();
        for (int t = tid; t < 1024; t += 256) {
            int f4 = t & 15, kk = t >> 4;
            *(float4*)&Ws[kk][f4<<2] =
                *(const float4*)(W + (size_t)((p<<6)+kk)*64 + (f4<<2));
        }
        __syncthreads();

        ull acc[4][4];
        #pragma unroll
        for (int rp = 0; rp < 4; rp++)
            #pragma unroll
            for (int c = 0; c < 4; c++) acc[rp][c] = 0ull;

        #pragma unroll 4
        for (int k = 0; k < 64; k++) {
            ulonglong2 a01 = *(const ulonglong2*)(&As[k][r0]);
            ulonglong2 a23 = *(const ulonglong2*)(&As[k][r0+4]);
            float4 b = *(const float4*)(&Ws[k][f0]);
            ull ar[4] = { a01.x, a01.y, a23.x, a23.y };
            ull bd[4] = { dup2(b.x), dup2(b.y), dup2(b.z), dup2(b.w) };
            #pragma unroll
            for (int rp = 0; rp < 4; rp++)
                #pragma unroll
                for (int c = 0; c < 4; c++)
                    acc[rp][c] = ff2(ar[rp], bd[c], acc[rp][c]);
        }

        float* out = (p == 0) ? g_P : g_Q;
        float4 bv = (p == 0) ? make_float4(0.f, 0.f, 0.f, 0.f)
                             : *(const float4*)(b1 + f0);
        #pragma unroll
        for (int rp = 0; rp < 4; rp++) {
            float2 u0 = up2(acc[rp][0]), u1 = up2(acc[rp][1]);
            float2 u2 = up2(acc[rp][2]), u3 = up2(acc[rp][3]);
            int ea = e0 + r0 + 2*rp;
            *(float4*)(out + (size_t)ea*64 + f0) =
                make_float4(u0.x + bv.x, u1.x + bv.y, u2.x + bv.z, u3.x + bv.w);
            *(float4*)(out + (size_t)(ea+1)*64 + f0) =
                make_float4(u0.y + bv.x, u1.y + bv.y, u2.y + bv.z, u3.y + bv.w);
        }
    }
}

// ------------- edge stats: batch stats of y1 = P[to] + Q[frm] ----------
__global__ __launch_bounds__(256) void k_estats() {
    const int tid = threadIdx.x;
    const int e0  = blockIdx.x * 128;
    const int f4  = tid & 15;
    const int el0 = tid >> 4;

    float4 s  = make_float4(0.f, 0.f, 0.f, 0.f);
    float4 s2 = make_float4(0.f, 0.f, 0.f, 0.f);
    for (int e = el0; e < 128; e += 16) {
        int eg = e0 + e;
        int i = eg & (Nn-1);
        int to  = g_idx[i*KK + 1 + (eg >> 14)];
        int frm = g_idx[i*KK];
        float4 p = *(const float4*)(g_P + (size_t)to*64  + (f4<<2));
        float4 q = *(const float4*)(g_Q + (size_t)frm*64 + (f4<<2));
        float4 v = make_float4(p.x+q.x, p.y+q.y, p.z+q.z, p.w+q.w);
        s.x += v.x; s.y += v.y; s.z += v.z; s.w += v.w;
        s2.x = fmaf(v.x, v.x, s2.x); s2.y = fmaf(v.y, v.y, s2.y);
        s2.z = fmaf(v.z, v.z, s2.z); s2.w = fmaf(v.w, v.w, s2.w);
    }
    __shared__ float4 sh[256], sh2[256];
    sh[tid] = s; sh2[tid] = s2;
    __syncthreads();
    if (tid < 16) {
        float4 S  = make_float4(0.f, 0.f, 0.f, 0.f);
        float4 S2 = make_float4(0.f, 0.f, 0.f, 0.f);
        #pragma unroll
        for (int g = 0; g < 16; g++) {
            float4 a = sh[g*16 + tid], b = sh2[g*16 + tid];
            S.x += a.x; S.y += a.y; S.z += a.z; S.w += a.w;
            S2.x += b.x; S2.y += b.y; S2.z += b.z; S2.w += b.w;
        }
        float* d = g_part + (size_t)blockIdx.x*128 + tid*4;
        d[0] = S.x; d[1] = S.y; d[2] = S.z; d[3] = S.w;
        d[64] = S2.x; d[65] = S2.y; d[66] = S2.z; d[67] = S2.w;
    }
}

// ------------- GEMM B: depth-64, fused BN-affine+ReLU in, stats out ----
// MODE 0: A = bn(P[to]+Q[frm]) (msg), MODE 1: A = bn(g_u1) (upd)
template<int MODE>
__global__ __launch_bounds__(256) void k_gemm_b(const float* __restrict__ W,
                                                const float* __restrict__ bias) {
    __shared__ float As[64][128];
    __shared__ float Ws[64][64];
    const int tid = threadIdx.x;
    const int e0  = blockIdx.x * 128;
    const int r0  = (tid >> 4) * 8;
    const int f0  = (tid & 15) * 4;

    for (int t = tid; t < 1024; t += 256) {
        int f4 = t & 15, kk = t >> 4;
        *(float4*)&Ws[kk][f4<<2] = *(const float4*)(W + (size_t)kk*64 + (f4<<2));
    }
    for (int t = tid; t < 2048; t += 256) {
        int e = t & 127, k4 = t >> 7;
        int eg = e0 + e;
        float4 v;
        if (MODE == 0) {
            int i = eg & (Nn-1);
            int to  = g_idx[i*KK + 1 + (eg >> 14)];
            int frm = g_idx[i*KK];
            float4 p = *(const float4*)(g_P + (size_t)to*64  + (k4<<2));
            float4 q = *(const float4*)(g_Q + (size_t)frm*64 + (k4<<2));
            v = make_float4(p.x+q.x, p.y+q.y, p.z+q.z, p.w+q.w);
        } else {
            v = *(const float4*)(g_u1 + (size_t)eg*64 + (k4<<2));
        }
        float4 sc = *(const float4*)(g_scale + (k4<<2));
        float4 sh = *(const float4*)(g_shift + (k4<<2));
        As[(k4<<2)+0][e] = fmaxf(fmaf(v.x, sc.x, sh.x), 0.f);
        As[(k4<<2)+1][e] = fmaxf(fmaf(v.y, sc.y, sh.y), 0.f);
        As[(k4<<2)+2][e] = fmaxf(fmaf(v.z, sc.z, sh.z), 0.f);
        As[(k4<<2)+3][e] = fmaxf(fmaf(v.w, sc.w, sh.w), 0.f);
    }
    __syncthreads();

    ull acc[4][4];
    #pragma unroll
    for (int rp = 0; rp < 4; rp++)
        #pragma unroll
        for (int c = 0; c < 4; c++) acc[rp][c] = 0ull;

    #pragma unroll 4
    for (int k = 0; k < 64; k++) {
        ulonglong2 a01 = *(const ulonglong2*)(&As[k][r0]);
        ulonglong2 a23 = *(const ulonglong2*)(&As[k][r0+4]);
        float4 b = *(const float4*)(&Ws[k][f0]);
        ull ar[4] = { a01.x, a01.y, a23.x, a23.y };
        ull bd[4] = { dup2(b.x), dup2(b.y), dup2(b.z), dup2(b.w) };
        #pragma unroll
        for (int rp = 0; rp < 4; rp++)
            #pragma unroll
            for (int c = 0; c < 4; c++)
                acc[rp][c] = ff2(ar[rp], bd[c], acc[rp][c]);
    }

    float* out = (MODE == 0) ? g_y2 : g_u2;
    float4 bv = *(const float4*)(bias + f0);
    float fs[4] = {0.f,0.f,0.f,0.f}, fq[4] = {0.f,0.f,0.f,0.f};
    #pragma unroll
    for (int rp = 0; rp < 4; rp++) {
        float2 u0 = up2(acc[rp][0]), u1 = up2(acc[rp][1]);
        float2 u2 = up2(acc[rp][2]), u3 = up2(acc[rp][3]);
        int ea = e0 + r0 + 2*rp;
        float4 oA = make_float4(u0.x + bv.x, u1.x + bv.y, u2.x + bv.z, u3.x + bv.w);
        float4 oB = make_float4(u0.y + bv.x, u1.y + bv.y, u2.y + bv.z, u3.y + bv.w);
        *(float4*)(out + (size_t)ea*64 + f0) = oA;
        *(float4*)(out + (size_t)(ea+1)*64 + f0) = oB;
        fs[0] += oA.x + oB.x; fq[0] += oA.x*oA.x + oB.x*oB.x;
        fs[1] += oA.y + oB.y; fq[1] += oA.y*oA.y + oB.y*oB.y;
        fs[2] += oA.z + oB.z; fq[2] += oA.z*oA.z + oB.z*oB.z;
        fs[3] += oA.w + oB.w; fq[3] += oA.w*oA.w + oB.w*oB.w;
    }

    __syncthreads();         // all As reads done before scratch reuse
    float* scr = &As[0][0];
    #pragma unroll
    for (int c = 0; c < 4; c++) {
        scr[tid*4 + c]        = fs[c];
        scr[1024 + tid*4 + c] = fq[c];
    }
    __syncthreads();
    if (tid < 64) {
        const int fg = tid >> 2, c = tid & 3;
        float S = 0.f, Q = 0.f;
        #pragma unroll
        for (int g = 0; g < 16; g++) {
            int idx = (g*16 + fg)*4 + c;
            S += scr[idx]; Q += scr[1024 + idx];
        }
        g_part[(size_t)blockIdx.x*128 + tid]      = S;
        g_part[(size_t)blockIdx.x*128 + 64 + tid] = Q;
    }
}

// ------------- GEMM A (upd only): depth-128, fused stats partials ------
__global__ __launch_bounds__(256) void k_gemm_a1(const float* __restrict__ W,
                                                 const float* __restrict__ bias) {
    __shared__ float As[64][128];
    __shared__ float Ws[64][64];
    const int tid = threadIdx.x;
    const int e0  = blockIdx.x * 128;
    const int r0  = (tid >> 4) * 8;
    const int f0  = (tid & 15) * 4;
    ull acc[4][4];
    #pragma unroll
    for (int rp = 0; rp < 4; rp++)
        #pragma unroll
        for (int c = 0; c < 4; c++) acc[rp][c] = 0ull;

    for (int p = 0; p < 2; p++) {
        for (int t = tid; t < 1024; t += 256) {
            int f4 = t & 15, kk = t >> 4;
            *(float4*)&Ws[kk][f4<<2] =
                *(const float4*)(W + (size_t)((p<<6)+kk)*64 + (f4<<2));
        }
        for (int t = tid; t < 2048; t += 256) {
            int e = t & 127, k4 = t >> 7;
            int eg = e0 + e;
            const float* src = (p == 0 ? g_h : g_agg) + (size_t)eg*64;
            float4 v = *(const float4*)(src + (k4<<2));
            As[(k4<<2)+0][e] = v.x; As[(k4<<2)+1][e] = v.y;
            As[(k4<<2)+2][e] = v.z; As[(k4<<2)+3][e] = v.w;
        }
        __syncthreads();
        #pragma unroll 4
        for (int k = 0; k < 64; k++) {
            ulonglong2 a01 = *(const ulonglong2*)(&As[k][r0]);
            ulonglong2 a23 = *(const ulonglong2*)(&As[k][r0+4]);
            float4 b = *(const float4*)(&Ws[k][f0]);
            ull ar[4] = { a01.x, a01.y, a23.x, a23.y };
            ull bd[4] = { dup2(b.x), dup2(b.y), dup2(b.z), dup2(b.w) };
            #pragma unroll
            for (int rp = 0; rp < 4; rp++)
                #pragma unroll
                for (int c = 0; c < 4; c++)
                    acc[rp][c] = ff2(ar[rp], bd[c], acc[rp][c]);
        }
        __syncthreads();
    }

    float4 bv = *(const float4*)(bias + f0);
    float fs[4] = {0.f,0.f,0.f,0.f}, fq[4] = {0.f,0.f,0.f,0.f};
    #pragma unroll
    for (int rp = 0; rp < 4; rp++) {
        float2 u0 = up2(acc[rp][0]), u1 = up2(acc[rp][1]);
        float2 u2 = up2(acc[rp][2]), u3 = up2(acc[rp][3]);
        int ea = e0 + r0 + 2*rp;
        float4 oA = make_float4(u0.x + bv.x, u1.x + bv.y, u2.x + bv.z, u3.x + bv.w);
        float4 oB = make_float4(u0.y + bv.x, u1.y + bv.y, u2.y + bv.z, u3.y + bv.w);
        *(float4*)(g_u1 + (size_t)ea*64 + f0) = oA;
        *(float4*)(g_u1 + (size_t)(ea+1)*64 + f0) = oB;
        fs[0] += oA.x + oB.x; fq[0] += oA.x*oA.x + oB.x*oB.x;
        fs[1] += oA.y + oB.y; fq[1] += oA.y*oA.y + oB.y*oB.y;
        fs[2] += oA.z + oB.z; fq[2] += oA.z*oA.z + oB.z*oB.z;
        fs[3] += oA.w + oB.w; fq[3] += oA.w*oA.w + oB.w*oB.w;
    }

    float* scr = &As[0][0];
    #pragma unroll
    for (int c = 0; c < 4; c++) {
        scr[tid*4 + c]        = fs[c];
        scr[1024 + tid*4 + c] = fq[c];
    }
    __syncthreads();
    if (tid < 64) {
        const int fg = tid >> 2, c = tid & 3;
        float S = 0.f, Q = 0.f;
        #pragma unroll
        for (int g = 0; g < 16; g++) {
            int idx = (g*16 + fg)*4 + c;
            S += scr[idx]; Q += scr[1024 + idx];
        }
        g_part[(size_t)blockIdx.x*128 + tid]      = S;
        g_part[(size_t)blockIdx.x*128 + 64 + tid] = Q;
    }
}

// ---------------- final-pool stats (over g_h) ----------------
__global__ void k_stats(int M, int P) {
    const float* __restrict__ x = g_h;
    const int t = threadIdx.x;
    float s = 0.f, s2 = 0.f;
    const size_t total = (size_t)M * 64;
    for (size_t idx = (size_t)blockIdx.x*256 + t; idx < total; idx += (size_t)P*256) {
        float v = x[idx];
        s += v; s2 = fmaf(v, v, s2);
    }
    __shared__ float sh[256], sh2[256];
    sh[t] = s; sh2[t] = s2;
    __syncthreads();
    if (t < 64) {
        s  = sh[t]  + sh[t+64]  + sh[t+128]  + sh[t+192];
        s2 = sh2[t] + sh2[t+64] + sh2[t+128] + sh2[t+192];
        g_part[(size_t)blockIdx.x*128 + t]      = s;
        g_part[(size_t)blockIdx.x*128 + 64 + t] = s2;
    }
}

// ---------------- stats finalize: 256-thread parallel reduce ----------
__global__ void k_stats_fin(int M, int P,
                            const float* __restrict__ g,
                            const float* __restrict__ be) {
    const int tid = threadIdx.x;
    const int f = tid & 63;
    const int part = tid >> 6;               // 0..3
    float s = 0.f, s2 = 0.f;
    for (int p = part; p < P; p += 4) {
        s  += g_part[(size_t)p*128 + f];
        s2 += g_part[(size_t)p*128 + 64 + f];
    }
    __shared__ float sh[256], sh2[256];
    sh[tid] = s; sh2[tid] = s2;
    __syncthreads();
    if (tid < 64) {
        s  = sh[tid]  + sh[tid+64]  + sh[tid+128]  + sh[tid+192];
        s2 = sh2[tid] + sh2[tid+64] + sh2[tid+128] + sh2[tid+192];
        const float inv  = 1.f / (float)M;
        const float mean = s * inv;
        const float var  = fmaf(-mean, mean, s2 * inv);
        const float sc   = g[tid] * rsqrtf(var + 1e-5f);
        g_scale[tid] = sc;
        g_shift[tid] = fmaf(-mean, sc, be[tid]);
    }
}

// ---------------- zero, scatter, residual ----------------
__global__ void k_zero_agg() {
    int i = blockIdx.x*blockDim.x + threadIdx.x;
    g_agg[i] = 0.f;
}

__global__ void k_scatter() {
    const int gid = blockIdx.x*256 + threadIdx.x;
    const int q = gid & 15;
    const int e = gid >> 4;
    const int i = e & (Nn-1);
    const int to = g_idx[i*KK + 1 + (e >> 14)];
    const int f = q << 2;
    float4 v  = *(const float4*)(g_y2 + (size_t)e*64 + f);
    float4 sc = *(const float4*)(g_scale + f);
    float4 sh = *(const float4*)(g_shift + f);
    float* dst = g_agg + (size_t)to*64 + f;
    atomicAdd(dst+0, fmaxf(fmaf(v.x, sc.x, sh.x), 0.f));
    atomicAdd(dst+1, fmaxf(fmaf(v.y, sc.y, sh.y), 0.f));
    atomicAdd(dst+2, fmaxf(fmaf(v.z, sc.z, sh.z), 0.f));
    atomicAdd(dst+3, fmaxf(fmaf(v.w, sc.w, sh.w), 0.f));
}

__global__ void k_resid() {
    const int gid = blockIdx.x*blockDim.x + threadIdx.x;
    const int f = gid & 63;
    const float v = g_u2[gid];
    g_h[gid] += fmaxf(fmaf(v, g_scale[f], g_shift[f]), 0.f);
}

// ---------------- final pool + prediction ----------------
__global__ void k_fin(const float* __restrict__ pW,
                      const float* __restrict__ pb,
                      float* __restrict__ out, int P) {
    const int f = threadIdx.x;
    float s = 0.f;
    for (int p = 0; p < P; p++) s += g_part[(size_t)p*128 + f];
    float v = (s / (float)Nn) * pW[f];
    __shared__ float red[64];
    red[f] = v;
    __syncthreads();
    if (f < 32) {
        float x = red[f] + red[f+32];
        #pragma unroll
        for (int o = 16; o > 0; o >>= 1) x += __shfl_down_sync(0xffffffffu, x, o);
        if (f == 0) out[0] = x + pb[0];
    }
}

// ---------------- host driver ----------------
extern "C" void kernel_launch(void* const* d_in, const int* in_sizes, int n_in,
                              void* d_out, int out_size) {
    const float* pos    = (const float*)d_in[0];
    const float* linW   = (const float*)d_in[1];
    const float* linb   = (const float*)d_in[2];
    const float* predW  = (const float*)d_in[3];
    const float* predb  = (const float*)d_in[4];
    const float* msgW1  = (const float*)d_in[5];
    const float* msgb1  = (const float*)d_in[6];
    const float* msgg1  = (const float*)d_in[7];
    const float* msgbe1 = (const float*)d_in[8];
    const float* msgW2  = (const float*)d_in[9];
    const float* msgb2  = (const float*)d_in[10];
    const float* msgg2  = (const float*)d_in[11];
    const float* msgbe2 = (const float*)d_in[12];
    const float* updW1  = (const float*)d_in[13];
    const float* updb1  = (const float*)d_in[14];
    const float* updg1  = (const float*)d_in[15];
    const float* updbe1 = (const float*)d_in[16];
    const float* updW2  = (const float*)d_in[17];
    const float* updb2  = (const float*)d_in[18];
    const float* updg2  = (const float*)d_in[19];
    const float* updbe2 = (const float*)d_in[20];
    float* out = (float*)d_out;

    static int smem_set = 0;
    if (!smem_set) {
        cudaFuncSetAttribute(k_d2pref, cudaFuncAttributeMaxDynamicSharedMemorySize,
                             SMEM_D2);
        smem_set = 1;
    }

    k_lin_in<<<Nn, 64>>>(pos, linW, linb);

    for (int l = 0; l < Ll; l++) {
        // ---- KNN: quarter-split prefilter (reg lists) + exact rerank ----
        k_split<<<Nn/8, 256>>>();
        k_d2pref<<<512, 256, SMEM_D2>>>();
        k_rerank<<<Nn/8, 256>>>();

        // ---- message MLP: P/Q factorization ----
        k_pq<<<Nn/128, 256>>>(msgW1 + (size_t)l*128*64, msgb1 + l*64);
        k_estats<<<2048, 256>>>();
        k_stats_fin<<<1, 256>>>(Ee, 2048, msgg1 + l*64, msgbe1 + l*64);
        k_gemm_b<0><<<Ee/128, 256>>>(msgW2 + (size_t)l*64*64, msgb2 + l*64);
        k_stats_fin<<<1, 256>>>(Ee, 2048, msgg2 + l*64, msgbe2 + l*64);

        // ---- aggregate ----
        k_zero_agg<<<Nn*64/256, 256>>>();
        k_scatter<<<Ee*16/256, 256>>>();

        // ---- update MLP + residual (stats fused) ----
        k_gemm_a1<<<Nn/128, 256>>>(updW1 + (size_t)l*128*64, updb1 + l*64);
        k_stats_fin<<<1, 256>>>(Nn, 128, updg1 + l*64, updbe1 + l*64);
        k_gemm_b<1><<<Nn/128, 256>>>(updW2 + (size_t)l*64*64, updb2 + l*64);
        k_stats_fin<<<1, 256>>>(Nn, 128, updg2 + l*64, updbe2 + l*64);
        k_resid<<<Nn*64/256, 256>>>();
    }

    k_stats<<<64, 256>>>(Nn, 64);
    k_fin<<<1, 64>>>(predW, predb, out, 64);
}

// round 13
// speedup vs baseline: 5.4083x; 1.1256x over previous
#include <cuda_runtime.h>
#include <cuda_bf16.h>
#include <cstdint>

#define Nn 16384
#define Dd 64
#define KK 17
#define Ee (Nn*16)
#define Ll 4

typedef unsigned long long ull;

// ---------------- scratch (static device allocations) ----------------
__device__ float g_h[Nn*Dd];
__device__ float g_hsq[Nn];                     // exact 0.5 * ||h_i||^2
__device__ int   g_idx[Nn*KK];
__device__ int   g_cand[(size_t)Nn*128];        // 128 prefilter candidates/row
__device__ float g_P[Nn*Dd];                    // h @ W1_top          (msg)
__device__ float g_Q[Nn*Dd];                    // h @ W1_bot + b1     (msg)
__device__ float g_y2[(size_t)Ee*Dd];
__device__ float g_agg[Nn*Dd];
__device__ float g_u1[Nn*Dd];
__device__ float g_u2[Nn*Dd];
__device__ float g_part[2048*128];
__device__ float g_scale[Dd];
__device__ float g_shift[Dd];
// pre-SW128-swizzled bf16 hi parts of h (row = node, 128 bytes/row)
__device__ unsigned g_hb_hi[Nn*32];

// ---------------- packed f32x2 helpers (for MLP GEMMs) ----------------
__device__ __forceinline__ ull ff2(ull a, ull b, ull c) {
    ull d;
    asm("fma.rn.f32x2 %0, %1, %2, %3;" : "=l"(d) : "l"(a), "l"(b), "l"(c));
    return d;
}
__device__ __forceinline__ ull dup2(float x) {
    ull d;
    unsigned u = __float_as_uint(x);
    asm("mov.b64 %0, {%1, %1};" : "=l"(d) : "r"(u));
    return d;
}
__device__ __forceinline__ float2 up2(ull v) {
    float2 r;
    asm("mov.b64 {%0, %1}, %2;" : "=f"(r.x), "=f"(r.y) : "l"(v));
    return r;
}

// ---------------- sm_80-era async-copy / ldmatrix / mma helpers --------
__device__ __forceinline__ uint32_t smem_u32(const void* p) {
    uint32_t a;
    asm("{ .reg .u64 t; cvta.to.shared.u64 t, %1; cvt.u32.u64 %0, t; }"
        : "=r"(a) : "l"(p));
    return a;
}
__device__ __forceinline__ void cp16(uint32_t d, const void* s) {
    asm volatile("cp.async.cg.shared.global [%0], [%1], 16;"
                 :: "r"(d), "l"(s) : "memory");
}
__device__ __forceinline__ void cp_commit() {
    asm volatile("cp.async.commit_group;" ::: "memory");
}
template<int N> __device__ __forceinline__ void cp_wait() {
    asm volatile("cp.async.wait_group %0;" :: "n"(N) : "memory");
}
__device__ __forceinline__ void ldsm4(uint32_t& r0, uint32_t& r1,
                                      uint32_t& r2, uint32_t& r3, uint32_t a) {
    asm volatile("ldmatrix.sync.aligned.m8n8.x4.shared.b16 {%0,%1,%2,%3}, [%4];"
                 : "=r"(r0), "=r"(r1), "=r"(r2), "=r"(r3) : "r"(a));
}
__device__ __forceinline__ void mma_bf16(float& c0, float& c1, float& c2, float& c3,
                                         uint32_t a0, uint32_t a1, uint32_t a2,
                                         uint32_t a3, uint32_t b0, uint32_t b1) {
    asm volatile(
        "mma.sync.aligned.m16n8k16.row.col.f32.bf16.bf16.f32 "
        "{%0,%1,%2,%3}, {%4,%5,%6,%7}, {%8,%9}, {%0,%1,%2,%3};"
        : "+f"(c0), "+f"(c1), "+f"(c2), "+f"(c3)
        : "r"(a0), "r"(a1), "r"(a2), "r"(a3), "r"(b0), "r"(b1));
}
__device__ __forceinline__ uint32_t sw128(uint32_t off) {
    return off ^ ((off >> 3) & 0x70u);
}

// ---------------- input projection ----------------
__global__ void k_lin_in(const float* __restrict__ pos,
                         const float* __restrict__ W,
                         const float* __restrict__ b) {
    __shared__ float sW[11*64];
    __shared__ float sp[11];
    const int i = blockIdx.x;
    const int f = threadIdx.x;
    for (int t = f; t < 11*64; t += 64) sW[t] = W[t];
    if (f < 11) sp[f] = pos[i*11 + f];
    __syncthreads();
    float acc = b[f];
    #pragma unroll
    for (int c = 0; c < 11; c++) acc = fmaf(sp[c], sW[c*64 + f], acc);
    g_h[i*64 + f] = acc;
}

// ---------------- bf16 hi + swizzled store + exact 0.5*sq --------------
__global__ void k_split() {
    const int node = blockIdx.x*8 + (threadIdx.x >> 5);
    const int lane = threadIdx.x & 31;
    float2 f = *(const float2*)(g_h + (size_t)node*64 + lane*2);

    __nv_bfloat16 h0 = __float2bfloat16(f.x);
    __nv_bfloat16 h1 = __float2bfloat16(f.y);

    unsigned off = (unsigned)node*128u + (unsigned)lane*4u;
    unsigned sw  = sw128(off);
    *(unsigned*)((char*)g_hb_hi + sw) =
        (unsigned)__bfloat16_as_ushort(h0) | ((unsigned)__bfloat16_as_ushort(h1) << 16);

    float s = f.x*f.x + f.y*f.y;            // exact fp32 norms
    #pragma unroll
    for (int o = 16; o > 0; o >>= 1) s += __shfl_down_sync(0xffffffffu, s, o);
    if (lane == 0) g_hsq[node] = 0.5f * s;
}

// ---------------- prefilter: eighth-split mma.sync d2, top-4 reg lists --
// grid 1024: blockIdx = rowblk*8 + eighth. 128 rows x 2048 cols per CTA.
#define OB_B    0u
#define OB_HSQ  32768u
#define SMEM_D2 (33792u + 2048u)

__device__ __forceinline__ uint32_t enc_key(float f, int idx) {
    uint32_t u = __float_as_uint(f);
    u = ((int)u < 0) ? ~u : (u | 0x80000000u);   // monotone float->uint
    return (u & 0xFFFFC000u) | (uint32_t)idx;    // key[18] | idx[14]
}
__device__ __forceinline__ void ins4r(uint32_t* L, uint32_t v) {
    #pragma unroll
    for (int p = 0; p < 4; p++) {
        uint32_t lo = umin(L[p], v);
        v = umax(L[p], v);
        L[p] = lo;
    }
}

__global__ __launch_bounds__(256, 3) void k_d2pref() {
    extern __shared__ __align__(16) char smraw[];
    const uint32_t rawb = smem_u32(smraw);
    const uint32_t sb = (rawb + 1023u) & ~1023u;
    char* smc = smraw + (sb - rawb);

    const int tid  = threadIdx.x;
    const int w    = tid >> 5;
    const int lane = tid & 31;
    const int rowblk = blockIdx.x >> 3;
    const int eighth = blockIdx.x & 7;
    const int row0 = rowblk * 128;
    const int t0   = eighth * 16;

    // ---- stage A (128 rows, hi) through B buf0 ----
    {
        const char* srchi = (const char*)g_hb_hi + (size_t)row0*128;
        for (int i = tid; i < 1024; i += 256)
            cp16(sb + OB_B + i*16, srchi + i*16);
        cp_commit();
        cp_wait<0>();
    }
    __syncthreads();

    uint32_t af[4][4];
    {
        const int m  = lane >> 3;
        const int rr = (w << 4) + ((m & 1) << 3) + (lane & 7);
        const int kb0 = (m >> 1) << 4;
        #pragma unroll
        for (int ks = 0; ks < 4; ks++) {
            uint32_t loc = (uint32_t)rr*128u + (uint32_t)(ks*32 + kb0);
            ldsm4(af[ks][0], af[ks][1], af[ks][2], af[ks][3],
                  sb + OB_B + sw128(loc));
        }
    }
    __syncthreads();      // A frags in regs; buf0 reusable

    const int q   = lane >> 2;
    const int s3  = lane & 3;
    const int lr0 = (w << 4) + q;
    const int lr1 = lr0 + 8;
    uint32_t La[4], Lb[4];
    #pragma unroll
    for (int p = 0; p < 4; p++) { La[p] = 0xFFFFFFFFu; Lb[p] = 0xFFFFFFFFu; }
    uint32_t th0 = 0xFFFFFFFFu, th1 = 0xFFFFFFFFu;

    #pragma unroll
    for (int u = 0; u < 2; u++) {
        const char* bhi = (const char*)g_hb_hi + (size_t)(t0 + u)*16384;
        uint32_t dst = sb + OB_B + (uint32_t)u*16384u;
        for (int i = tid; i < 1024; i += 256)
            cp16(dst + i*16, bhi + i*16);
        if (tid < 32) cp16(sb + OB_HSQ + (uint32_t)u*512u + tid*16,
                           (const char*)g_hsq + (size_t)(t0 + u)*512 + tid*16);
        cp_commit();
    }
    cp_wait<1>();
    __syncthreads();

    const int bm = lane >> 3;
    const int bn = lane & 7;

    for (int tl = 0; tl < 16; tl++) {
        const uint32_t bbase = sb + OB_B + (uint32_t)(tl & 1)*16384u;
        const char* hsqp = smc + OB_HSQ + (uint32_t)(tl & 1)*512u;
        const int jb = (t0 + tl) * 128;

        #pragma unroll 1
        for (int nb = 0; nb < 16; nb++) {
            uint32_t bh[8];
            {
                uint32_t loc = (uint32_t)((nb*8 + bn)*128 + bm*16);
                ldsm4(bh[0], bh[1], bh[2], bh[3], bbase + sw128(loc));
                ldsm4(bh[4], bh[5], bh[6], bh[7], bbase + sw128(loc + 64u));
            }
            float h0 = 0.f, h1 = 0.f, h2 = 0.f, h3 = 0.f;
            float g0 = 0.f, g1 = 0.f, g2 = 0.f, g3 = 0.f;
            mma_bf16(h0, h1, h2, h3, af[0][0], af[0][1], af[0][2], af[0][3],
                     bh[0], bh[1]);
            mma_bf16(g0, g1, g2, g3, af[1][0], af[1][1], af[1][2], af[1][3],
                     bh[2], bh[3]);
            mma_bf16(h0, h1, h2, h3, af[2][0], af[2][1], af[2][2], af[2][3],
                     bh[4], bh[5]);
            mma_bf16(g0, g1, g2, g3, af[3][0], af[3][1], af[3][2], af[3][3],
                     bh[6], bh[7]);
            float c0 = h0 + g0;
            float c1 = h1 + g1;
            float c2 = h2 + g2;
            float c3 = h3 + g3;

            float2 hs = *(const float2*)(hsqp + (nb*8 + 2*s3)*4);
            const int colb = jb + nb*8 + 2*s3;
            uint32_t e0 = enc_key(hs.x - c0, colb);
            uint32_t e1 = enc_key(hs.y - c1, colb + 1);
            uint32_t e2 = enc_key(hs.x - c2, colb);
            uint32_t e3 = enc_key(hs.y - c3, colb + 1);
            if (e0 < th0) { ins4r(La, e0); th0 = La[3]; }
            if (e1 < th0) { ins4r(La, e1); th0 = La[3]; }
            if (e2 < th1) { ins4r(Lb, e2); th1 = Lb[3]; }
            if (e3 < th1) { ins4r(Lb, e3); th1 = Lb[3]; }
        }

        __syncthreads();
        if (tl + 2 < 16) {
            const int tt = t0 + tl + 2;
            const char* bhi = (const char*)g_hb_hi + (size_t)tt*16384;
            uint32_t dst = sb + OB_B + (uint32_t)(tl & 1)*16384u;
            for (int i = tid; i < 1024; i += 256)
                cp16(dst + i*16, bhi + i*16);
            if (tid < 32) cp16(sb + OB_HSQ + (uint32_t)(tl & 1)*512u + tid*16,
                               (const char*)g_hsq + (size_t)tt*512 + tid*16);
            cp_commit();
            cp_wait<1>();
        } else {
            cp_wait<0>();
        }
        __syncthreads();
    }

    int* d0 = g_cand + (size_t)(row0 + lr0)*128 + eighth*16 + s3*4;
    int* d1 = g_cand + (size_t)(row0 + lr1)*128 + eighth*16 + s3*4;
    #pragma unroll
    for (int p = 0; p < 4; p++) {
        d0[p] = (int)(La[p] & 0x3FFFu);
        d1[p] = (int)(Lb[p] & 0x3FFFu);
    }
}

// ---------------- exact fp32 rerank (interleaved gather streams) -------
__global__ __launch_bounds__(256, 4) void k_rerank() {
    __shared__ float hi_s[8*64];
    const int tid  = threadIdx.x;
    const int w    = tid >> 5;
    const int lane = tid & 31;
    const int rbase = blockIdx.x * 8;

    for (int i = tid; i < 8*16; i += 256) {
        int r = i >> 4, k4 = i & 15;
        *(float4*)(hi_s + r*64 + k4*4) =
            *(const float4*)(g_h + (size_t)(rbase + r)*64 + k4*4);
    }
    __syncthreads();

    const int row = rbase + w;
    const float* hi4 = hi_s + w*64;

    int ki[4];
    const float4* hj[4];
    #pragma unroll
    for (int c = 0; c < 4; c++) {
        ki[c] = g_cand[(size_t)row*128 + lane + 32*c];
        hj[c] = (const float4*)(g_h + (size_t)ki[c]*64);
    }

    float sa[4] = {0.f, 0.f, 0.f, 0.f};
    float sb_[4] = {0.f, 0.f, 0.f, 0.f};
    #pragma unroll 4
    for (int kk = 0; kk < 16; kk++) {
        float4 a = *(const float4*)(hi4 + kk*4);
        #pragma unroll
        for (int c = 0; c < 4; c++) {
            float4 b = hj[c][kk];
            sa[c] = fmaf(a.x, b.x, fmaf(a.z, b.z, sa[c]));
            sb_[c] = fmaf(a.y, b.y, fmaf(a.w, b.w, sb_[c]));
        }
    }
    float kv[4];
    #pragma unroll
    for (int c = 0; c < 4; c++)
        kv[c] = g_hsq[ki[c]] - (sa[c] + sb_[c]);

    #pragma unroll
    for (int r = 0; r < KK; r++) {
        float bv = kv[0]; int bi = ki[0];
        #pragma unroll
        for (int c = 1; c < 4; c++)
            if (kv[c] < bv || (kv[c] == bv && ki[c] < bi)) { bv = kv[c]; bi = ki[c]; }
        #pragma unroll
        for (int o = 16; o > 0; o >>= 1) {
            float ov = __shfl_xor_sync(0xffffffffu, bv, o);
            int   oi = __shfl_xor_sync(0xffffffffu, bi, o);
            if (ov < bv || (ov == bv && oi < bi)) { bv = ov; bi = oi; }
        }
        if (lane == 0) g_idx[row*KK + r] = bi;
        #pragma unroll
        for (int c = 0; c < 4; c++)
            if (ki[c] == bi) kv[c] = 3.4e38f;
    }
}

// ------------- P/Q factorization: P = h@W1_top, Q = h@W1_bot + b1 -------
__global__ __launch_bounds__(256) void k_pq(const float* __restrict__ W,
                                            const float* __restrict__ b1) {
    __shared__ float As[64][128];
    __shared__ float Ws[64][64];
    const int tid = threadIdx.x;
    const int e0  = blockIdx.x * 128;
    const int r0  = (tid >> 4) * 8;
    const int f0  = (tid & 15) * 4;

    for (int t = tid; t < 2048; t += 256) {
        int e = t & 127, k4 = t >> 7;
        float4 v = *(const float4*)(g_h + (size_t)(e0 + e)*64 + (k4<<2));
        As[(k4<<2)+0][e] = v.x; As[(k4<<2)+1][e] = v.y;
        As[(k4<<2)+2][e] = v.z; As[(k4<<2)+3][e] = v.w;
    }

    for (int p = 0; p < 2; p++) {
        __syncthreads();
        for (int t = tid; t < 1024; t += 256) {
            int f4 = t & 15, kk = t >> 4;
            *(float4*)&Ws[kk][f4<<2] =
                *(const float4*)(W + (size_t)((p<<6)+kk)*64 + (f4<<2));
        }
        __syncthreads();

        ull acc[4][4];
        #pragma unroll
        for (int rp = 0; rp < 4; rp++)
            #pragma unroll
            for (int c = 0; c < 4; c++) acc[rp][c] = 0ull;

        #pragma unroll 4
        for (int k = 0; k < 64; k++) {
            ulonglong2 a01 = *(const ulonglong2*)(&As[k][r0]);
            ulonglong2 a23 = *(const ulonglong2*)(&As[k][r0+4]);
            float4 b = *(const float4*)(&Ws[k][f0]);
            ull ar[4] = { a01.x, a01.y, a23.x, a23.y };
            ull bd[4] = { dup2(b.x), dup2(b.y), dup2(b.z), dup2(b.w) };
            #pragma unroll
            for (int rp = 0; rp < 4; rp++)
                #pragma unroll
                for (int c = 0; c < 4; c++)
                    acc[rp][c] = ff2(ar[rp], bd[c], acc[rp][c]);
        }

        float* out = (p == 0) ? g_P : g_Q;
        float4 bv = (p == 0) ? make_float4(0.f, 0.f, 0.f, 0.f)
                             : *(const float4*)(b1 + f0);
        #pragma unroll
        for (int rp = 0; rp < 4; rp++) {
            float2 u0 = up2(acc[rp][0]), u1 = up2(acc[rp][1]);
            float2 u2 = up2(acc[rp][2]), u3 = up2(acc[rp][3]);
            int ea = e0 + r0 + 2*rp;
            *(float4*)(out + (size_t)ea*64 + f0) =
                make_float4(u0.x + bv.x, u1.x + bv.y, u2.x + bv.z, u3.x + bv.w);
            *(float4*)(out + (size_t)(ea+1)*64 + f0) =
                make_float4(u0.y + bv.x, u1.y + bv.y, u2.y + bv.z, u3.y + bv.w);
        }
    }
}

// ------------- edge stats: batch stats of y1 = P[to] + Q[frm] ----------
__global__ __launch_bounds__(256) void k_estats() {
    const int tid = threadIdx.x;
    const int e0  = blockIdx.x * 128;
    const int f4  = tid & 15;
    const int el0 = tid >> 4;

    float4 s  = make_float4(0.f, 0.f, 0.f, 0.f);
    float4 s2 = make_float4(0.f, 0.f, 0.f, 0.f);
    for (int e = el0; e < 128; e += 16) {
        int eg = e0 + e;
        int i = eg & (Nn-1);
        int to  = g_idx[i*KK + 1 + (eg >> 14)];
        int frm = g_idx[i*KK];
        float4 p = *(const float4*)(g_P + (size_t)to*64  + (f4<<2));
        float4 q = *(const float4*)(g_Q + (size_t)frm*64 + (f4<<2));
        float4 v = make_float4(p.x+q.x, p.y+q.y, p.z+q.z, p.w+q.w);
        s.x += v.x; s.y += v.y; s.z += v.z; s.w += v.w;
        s2.x = fmaf(v.x, v.x, s2.x); s2.y = fmaf(v.y, v.y, s2.y);
        s2.z = fmaf(v.z, v.z, s2.z); s2.w = fmaf(v.w, v.w, s2.w);
    }
    __shared__ float4 sh[256], sh2[256];
    sh[tid] = s; sh2[tid] = s2;
    __syncthreads();
    if (tid < 16) {
        float4 S  = make_float4(0.f, 0.f, 0.f, 0.f);
        float4 S2 = make_float4(0.f, 0.f, 0.f, 0.f);
        #pragma unroll
        for (int g = 0; g < 16; g++) {
            float4 a = sh[g*16 + tid], b = sh2[g*16 + tid];
            S.x += a.x; S.y += a.y; S.z += a.z; S.w += a.w;
            S2.x += b.x; S2.y += b.y; S2.z += b.z; S2.w += b.w;
        }
        float* d = g_part + (size_t)blockIdx.x*128 + tid*4;
        d[0] = S.x; d[1] = S.y; d[2] = S.z; d[3] = S.w;
        d[64] = S2.x; d[65] = S2.y; d[66] = S2.z; d[67] = S2.w;
    }
}

// ------------- GEMM B: depth-64, fused BN-affine+ReLU in, stats out ----
// MODE 0: A = bn(P[to]+Q[frm]) (msg), MODE 1: A = bn(g_u1) (upd)
template<int MODE>
__global__ __launch_bounds__(256) void k_gemm_b(const float* __restrict__ W,
                                                const float* __restrict__ bias) {
    __shared__ float As[64][128];
    __shared__ float Ws[64][64];
    const int tid = threadIdx.x;
    const int e0  = blockIdx.x * 128;
    const int r0  = (tid >> 4) * 8;
    const int f0  = (tid & 15) * 4;

    for (int t = tid; t < 1024; t += 256) {
        int f4 = t & 15, kk = t >> 4;
        *(float4*)&Ws[kk][f4<<2] = *(const float4*)(W + (size_t)kk*64 + (f4<<2));
    }
    for (int t = tid; t < 2048; t += 256) {
        int e = t & 127, k4 = t >> 7;
        int eg = e0 + e;
        float4 v;
        if (MODE == 0) {
            int i = eg & (Nn-1);
            int to  = g_idx[i*KK + 1 + (eg >> 14)];
            int frm = g_idx[i*KK];
            float4 p = *(const float4*)(g_P + (size_t)to*64  + (k4<<2));
            float4 q = *(const float4*)(g_Q + (size_t)frm*64 + (k4<<2));
            v = make_float4(p.x+q.x, p.y+q.y, p.z+q.z, p.w+q.w);
        } else {
            v = *(const float4*)(g_u1 + (size_t)eg*64 + (k4<<2));
        }
        float4 sc = *(const float4*)(g_scale + (k4<<2));
        float4 sh = *(const float4*)(g_shift + (k4<<2));
        As[(k4<<2)+0][e] = fmaxf(fmaf(v.x, sc.x, sh.x), 0.f);
        As[(k4<<2)+1][e] = fmaxf(fmaf(v.y, sc.y, sh.y), 0.f);
        As[(k4<<2)+2][e] = fmaxf(fmaf(v.z, sc.z, sh.z), 0.f);
        As[(k4<<2)+3][e] = fmaxf(fmaf(v.w, sc.w, sh.w), 0.f);
    }
    __syncthreads();

    ull acc[4][4];
    #pragma unroll
    for (int rp = 0; rp < 4; rp++)
        #pragma unroll
        for (int c = 0; c < 4; c++) acc[rp][c] = 0ull;

    #pragma unroll 4
    for (int k = 0; k < 64; k++) {
        ulonglong2 a01 = *(const ulonglong2*)(&As[k][r0]);
        ulonglong2 a23 = *(const ulonglong2*)(&As[k][r0+4]);
        float4 b = *(const float4*)(&Ws[k][f0]);
        ull ar[4] = { a01.x, a01.y, a23.x, a23.y };
        ull bd[4] = { dup2(b.x), dup2(b.y), dup2(b.z), dup2(b.w) };
        #pragma unroll
        for (int rp = 0; rp < 4; rp++)
            #pragma unroll
            for (int c = 0; c < 4; c++)
                acc[rp][c] = ff2(ar[rp], bd[c], acc[rp][c]);
    }

    float* out = (MODE == 0) ? g_y2 : g_u2;
    float4 bv = *(const float4*)(bias + f0);
    float fs[4] = {0.f,0.f,0.f,0.f}, fq[4] = {0.f,0.f,0.f,0.f};
    #pragma unroll
    for (int rp = 0; rp < 4; rp++) {
        float2 u0 = up2(acc[rp][0]), u1 = up2(acc[rp][1]);
        float2 u2 = up2(acc[rp][2]), u3 = up2(acc[rp][3]);
        int ea = e0 + r0 + 2*rp;
        float4 oA = make_float4(u0.x + bv.x, u1.x + bv.y, u2.x + bv.z, u3.x + bv.w);
        float4 oB = make_float4(u0.y + bv.x, u1.y + bv.y, u2.y + bv.z, u3.y + bv.w);
        *(float4*)(out + (size_t)ea*64 + f0) = oA;
        *(float4*)(out + (size_t)(ea+1)*64 + f0) = oB;
        fs[0] += oA.x + oB.x; fq[0] += oA.x*oA.x + oB.x*oB.x;
        fs[1] += oA.y + oB.y; fq[1] += oA.y*oA.y + oB.y*oB.y;
        fs[2] += oA.z + oB.z; fq[2] += oA.z*oA.z + oB.z*oB.z;
        fs[3] += oA.w + oB.w; fq[3] += oA.w*oA.w + oB.w*oB.w;
    }

    __syncthreads();         // all As reads done before scratch reuse
    float* scr = &As[0][0];
    #pragma unroll
    for (int c = 0; c < 4; c++) {
        scr[tid*4 + c]        = fs[c];
        scr[1024 + tid*4 + c] = fq[c];
    }
    __syncthreads();
    if (tid < 64) {
        const int fg = tid >> 2, c = tid & 3;
        float S = 0.f, Q = 0.f;
        #pragma unroll
        for (int g = 0; g < 16; g++) {
            int idx = (g*16 + fg)*4 + c;
            S += scr[idx]; Q += scr[1024 + idx];
        }
        g_part[(size_t)blockIdx.x*128 + tid]      = S;
        g_part[(size_t)blockIdx.x*128 + 64 + tid] = Q;
    }
}

// ------------- GEMM A (upd only): depth-128, fused stats partials ------
__global__ __launch_bounds__(256) void k_gemm_a1(const float* __restrict__ W,
                                                 const float* __restrict__ bias) {
    __shared__ float As[64][128];
    __shared__ float Ws[64][64];
    const int tid = threadIdx.x;
    const int e0  = blockIdx.x * 128;
    const int r0  = (tid >> 4) * 8;
    const int f0  = (tid & 15) * 4;
    ull acc[4][4];
    #pragma unroll
    for (int rp = 0; rp < 4; rp++)
        #pragma unroll
        for (int c = 0; c < 4; c++) acc[rp][c] = 0ull;

    for (int p = 0; p < 2; p++) {
        for (int t = tid; t < 1024; t += 256) {
            int f4 = t & 15, kk = t >> 4;
            *(float4*)&Ws[kk][f4<<2] =
                *(const float4*)(W + (size_t)((p<<6)+kk)*64 + (f4<<2));
        }
        for (int t = tid; t < 2048; t += 256) {
            int e = t & 127, k4 = t >> 7;
            int eg = e0 + e;
            const float* src = (p == 0 ? g_h : g_agg) + (size_t)eg*64;
            float4 v = *(const float4*)(src + (k4<<2));
            As[(k4<<2)+0][e] = v.x; As[(k4<<2)+1][e] = v.y;
            As[(k4<<2)+2][e] = v.z; As[(k4<<2)+3][e] = v.w;
        }
        __syncthreads();
        #pragma unroll 4
        for (int k = 0; k < 64; k++) {
            ulonglong2 a01 = *(const ulonglong2*)(&As[k][r0]);
            ulonglong2 a23 = *(const ulonglong2*)(&As[k][r0+4]);
            float4 b = *(const float4*)(&Ws[k][f0]);
            ull ar[4] = { a01.x, a01.y, a23.x, a23.y };
            ull bd[4] = { dup2(b.x), dup2(b.y), dup2(b.z), dup2(b.w) };
            #pragma unroll
            for (int rp = 0; rp < 4; rp++)
                #pragma unroll
                for (int c = 0; c < 4; c++)
                    acc[rp][c] = ff2(ar[rp], bd[c], acc[rp][c]);
        }
        __syncthreads();
    }

    float4 bv = *(const float4*)(bias + f0);
    float fs[4] = {0.f,0.f,0.f,0.f}, fq[4] = {0.f,0.f,0.f,0.f};
    #pragma unroll
    for (int rp = 0; rp < 4; rp++) {
        float2 u0 = up2(acc[rp][0]), u1 = up2(acc[rp][1]);
        float2 u2 = up2(acc[rp][2]), u3 = up2(acc[rp][3]);
        int ea = e0 + r0 + 2*rp;
        float4 oA = make_float4(u0.x + bv.x, u1.x + bv.y, u2.x + bv.z, u3.x + bv.w);
        float4 oB = make_float4(u0.y + bv.x, u1.y + bv.y, u2.y + bv.z, u3.y + bv.w);
        *(float4*)(g_u1 + (size_t)ea*64 + f0) = oA;
        *(float4*)(g_u1 + (size_t)(ea+1)*64 + f0) = oB;
        fs[0] += oA.x + oB.x; fq[0] += oA.x*oA.x + oB.x*oB.x;
        fs[1] += oA.y + oB.y; fq[1] += oA.y*oA.y + oB.y*oB.y;
        fs[2] += oA.z + oB.z; fq[2] += oA.z*oA.z + oB.z*oB.z;
        fs[3] += oA.w + oB.w; fq[3] += oA.w*oA.w + oB.w*oB.w;
    }

    float* scr = &As[0][0];
    #pragma unroll
    for (int c = 0; c < 4; c++) {
        scr[tid*4 + c]        = fs[c];
        scr[1024 + tid*4 + c] = fq[c];
    }
    __syncthreads();
    if (tid < 64) {
        const int fg = tid >> 2, c = tid & 3;
        float S = 0.f, Q = 0.f;
        #pragma unroll
        for (int g = 0; g < 16; g++) {
            int idx = (g*16 + fg)*4 + c;
            S += scr[idx]; Q += scr[1024 + idx];
        }
        g_part[(size_t)blockIdx.x*128 + tid]      = S;
        g_part[(size_t)blockIdx.x*128 + 64 + tid] = Q;
    }
}

// ---------------- final-pool stats (over g_h) ----------------
__global__ void k_stats(int M, int P) {
    const float* __restrict__ x = g_h;
    const int t = threadIdx.x;
    float s = 0.f, s2 = 0.f;
    const size_t total = (size_t)M * 64;
    for (size_t idx = (size_t)blockIdx.x*256 + t; idx < total; idx += (size_t)P*256) {
        float v = x[idx];
        s += v; s2 = fmaf(v, v, s2);
    }
    __shared__ float sh[256], sh2[256];
    sh[t] = s; sh2[t] = s2;
    __syncthreads();
    if (t < 64) {
        s  = sh[t]  + sh[t+64]  + sh[t+128]  + sh[t+192];
        s2 = sh2[t] + sh2[t+64] + sh2[t+128] + sh2[t+192];
        g_part[(size_t)blockIdx.x*128 + t]      = s;
        g_part[(size_t)blockIdx.x*128 + 64 + t] = s2;
    }
}

// ---------------- stats finalize: 256-thread parallel reduce ----------
__global__ void k_stats_fin(int M, int P,
                            const float* __restrict__ g,
                            const float* __restrict__ be) {
    const int tid = threadIdx.x;
    const int f = tid & 63;
    const int part = tid >> 6;               // 0..3
    float s = 0.f, s2 = 0.f;
    for (int p = part; p < P; p += 4) {
        s  += g_part[(size_t)p*128 + f];
        s2 += g_part[(size_t)p*128 + 64 + f];
    }
    __shared__ float sh[256], sh2[256];
    sh[tid] = s; sh2[tid] = s2;
    __syncthreads();
    if (tid < 64) {
        s  = sh[tid]  + sh[tid+64]  + sh[tid+128]  + sh[tid+192];
        s2 = sh2[tid] + sh2[tid+64] + sh2[tid+128] + sh2[tid+192];
        const float inv  = 1.f / (float)M;
        const float mean = s * inv;
        const float var  = fmaf(-mean, mean, s2 * inv);
        const float sc   = g[tid] * rsqrtf(var + 1e-5f);
        g_scale[tid] = sc;
        g_shift[tid] = fmaf(-mean, sc, be[tid]);
    }
}

// ---------------- zero, scatter, residual ----------------
__global__ void k_zero_agg() {
    int i = blockIdx.x*blockDim.x + threadIdx.x;
    g_agg[i] = 0.f;
}

__global__ void k_scatter() {
    const int gid = blockIdx.x*256 + threadIdx.x;
    const int q = gid & 15;
    const int e = gid >> 4;
    const int i = e & (Nn-1);
    const int to = g_idx[i*KK + 1 + (e >> 14)];
    const int f = q << 2;
    float4 v  = *(const float4*)(g_y2 + (size_t)e*64 + f);
    float4 sc = *(const float4*)(g_scale + f);
    float4 sh = *(const float4*)(g_shift + f);
    float* dst = g_agg + (size_t)to*64 + f;
    atomicAdd(dst+0, fmaxf(fmaf(v.x, sc.x, sh.x), 0.f));
    atomicAdd(dst+1, fmaxf(fmaf(v.y, sc.y, sh.y), 0.f));
    atomicAdd(dst+2, fmaxf(fmaf(v.z, sc.z, sh.z), 0.f));
    atomicAdd(dst+3, fmaxf(fmaf(v.w, sc.w, sh.w), 0.f));
}

__global__ void k_resid() {
    const int gid = blockIdx.x*blockDim.x + threadIdx.x;
    const int f = gid & 63;
    const float v = g_u2[gid];
    g_h[gid] += fmaxf(fmaf(v, g_scale[f], g_shift[f]), 0.f);
}

// ---------------- final pool + prediction ----------------
__global__ void k_fin(const float* __restrict__ pW,
                      const float* __restrict__ pb,
                      float* __restrict__ out, int P) {
    const int f = threadIdx.x;
    float s = 0.f;
    for (int p = 0; p < P; p++) s += g_part[(size_t)p*128 + f];
    float v = (s / (float)Nn) * pW[f];
    __shared__ float red[64];
    red[f] = v;
    __syncthreads();
    if (f < 32) {
        float x = red[f] + red[f+32];
        #pragma unroll
        for (int o = 16; o > 0; o >>= 1) x += __shfl_down_sync(0xffffffffu, x, o);
        if (f == 0) out[0] = x + pb[0];
    }
}

// ---------------- host driver ----------------
extern "C" void kernel_launch(void* const* d_in, const int* in_sizes, int n_in,
                              void* d_out, int out_size) {
    const float* pos    = (const float*)d_in[0];
    const float* linW   = (const float*)d_in[1];
    const float* linb   = (const float*)d_in[2];
    const float* predW  = (const float*)d_in[3];
    const float* predb  = (const float*)d_in[4];
    const float* msgW1  = (const float*)d_in[5];
    const float* msgb1  = (const float*)d_in[6];
    const float* msgg1  = (const float*)d_in[7];
    const float* msgbe1 = (const float*)d_in[8];
    const float* msgW2  = (const float*)d_in[9];
    const float* msgb2  = (const float*)d_in[10];
    const float* msgg2  = (const float*)d_in[11];
    const float* msgbe2 = (const float*)d_in[12];
    const float* updW1  = (const float*)d_in[13];
    const float* updb1  = (const float*)d_in[14];
    const float* updg1  = (const float*)d_in[15];
    const float* updbe1 = (const float*)d_in[16];
    const float* updW2  = (const float*)d_in[17];
    const float* updb2  = (const float*)d_in[18];
    const float* updg2  = (const float*)d_in[19];
    const float* updbe2 = (const float*)d_in[20];
    float* out = (float*)d_out;

    static int smem_set = 0;
    if (!smem_set) {
        cudaFuncSetAttribute(k_d2pref, cudaFuncAttributeMaxDynamicSharedMemorySize,
                             SMEM_D2);
        smem_set = 1;
    }

    k_lin_in<<<Nn, 64>>>(pos, linW, linb);

    for (int l = 0; l < Ll; l++) {
        // ---- KNN: eighth-split prefilter (top-4 reg lists) + exact rerank ----
        k_split<<<Nn/8, 256>>>();
        k_d2pref<<<1024, 256, SMEM_D2>>>();
        k_rerank<<<Nn/8, 256>>>();

        // ---- message MLP: P/Q factorization ----
        k_pq<<<Nn/128, 256>>>(msgW1 + (size_t)l*128*64, msgb1 + l*64);
        k_estats<<<2048, 256>>>();
        k_stats_fin<<<1, 256>>>(Ee, 2048, msgg1 + l*64, msgbe1 + l*64);
        k_gemm_b<0><<<Ee/128, 256>>>(msgW2 + (size_t)l*64*64, msgb2 + l*64);
        k_stats_fin<<<1, 256>>>(Ee, 2048, msgg2 + l*64, msgbe2 + l*64);

        // ---- aggregate ----
        k_zero_agg<<<Nn*64/256, 256>>>();
        k_scatter<<<Ee*16/256, 256>>>();

        // ---- update MLP + residual (stats fused) ----
        k_gemm_a1<<<Nn/128, 256>>>(updW1 + (size_t)l*128*64, updb1 + l*64);
        k_stats_fin<<<1, 256>>>(Nn, 128, updg1 + l*64, updbe1 + l*64);
        k_gemm_b<1><<<Nn/128, 256>>>(updW2 + (size_t)l*64*64, updb2 + l*64);
        k_stats_fin<<<1, 256>>>(Nn, 128, updg2 + l*64, updbe2 + l*64);
        k_resid<<<Nn*64/256, 256>>>();
    }

    k_stats<<<64, 256>>>(Nn, 64);
    k_fin<<<1, 64>>>(predW, predb, out, 64);
}

// round 15
// speedup vs baseline: 6.0547x; 1.1195x over previous
#include <cuda_runtime.h>
#include <cuda_bf16.h>
#include <cstdint>

#define Nn 16384
#define Dd 64
#define KK 17
#define Ee (Nn*16)
#define Ll 4

typedef unsigned long long ull;

// ---------------- scratch (static device allocations) ----------------
__device__ float g_h[Nn*Dd];
__device__ float g_hsq[Nn];                     // exact 0.5 * ||h_i||^2
__device__ int   g_idx[Nn*KK];
__device__ unsigned g_cand[(size_t)Nn*128];     // packed key18|idx14 candidates
__device__ float g_P[Nn*Dd];                    // h @ W1_top          (msg)
__device__ float g_Q[Nn*Dd];                    // h @ W1_bot + b1     (msg)
__device__ float g_y2[(size_t)Ee*Dd];
__device__ float g_agg[Nn*Dd];
__device__ float g_u1[Nn*Dd];
__device__ float g_u2[Nn*Dd];
__device__ float g_part[2048*128];
__device__ float g_scale[Dd];
__device__ float g_shift[Dd];
// pre-SW128-swizzled bf16 hi parts of h (row = node, 128 bytes/row)
__device__ unsigned g_hb_hi[Nn*32];

// ---------------- packed f32x2 helpers (for MLP GEMMs) ----------------
__device__ __forceinline__ ull ff2(ull a, ull b, ull c) {
    ull d;
    asm("fma.rn.f32x2 %0, %1, %2, %3;" : "=l"(d) : "l"(a), "l"(b), "l"(c));
    return d;
}
__device__ __forceinline__ ull dup2(float x) {
    ull d;
    unsigned u = __float_as_uint(x);
    asm("mov.b64 %0, {%1, %1};" : "=l"(d) : "r"(u));
    return d;
}
__device__ __forceinline__ float2 up2(ull v) {
    float2 r;
    asm("mov.b64 {%0, %1}, %2;" : "=f"(r.x), "=f"(r.y) : "l"(v));
    return r;
}

// ---------------- sm_80-era async-copy / ldmatrix / mma helpers --------
__device__ __forceinline__ uint32_t smem_u32(const void* p) {
    uint32_t a;
    asm("{ .reg .u64 t; cvta.to.shared.u64 t, %1; cvt.u32.u64 %0, t; }"
        : "=r"(a) : "l"(p));
    return a;
}
__device__ __forceinline__ void cp16(uint32_t d, const void* s) {
    asm volatile("cp.async.cg.shared.global [%0], [%1], 16;"
                 :: "r"(d), "l"(s) : "memory");
}
__device__ __forceinline__ void cp_commit() {
    asm volatile("cp.async.commit_group;" ::: "memory");
}
template<int N> __device__ __forceinline__ void cp_wait() {
    asm volatile("cp.async.wait_group %0;" :: "n"(N) : "memory");
}
__device__ __forceinline__ void ldsm4(uint32_t& r0, uint32_t& r1,
                                      uint32_t& r2, uint32_t& r3, uint32_t a) {
    asm volatile("ldmatrix.sync.aligned.m8n8.x4.shared.b16 {%0,%1,%2,%3}, [%4];"
                 : "=r"(r0), "=r"(r1), "=r"(r2), "=r"(r3) : "r"(a));
}
__device__ __forceinline__ void mma_bf16(float& c0, float& c1, float& c2, float& c3,
                                         uint32_t a0, uint32_t a1, uint32_t a2,
                                         uint32_t a3, uint32_t b0, uint32_t b1) {
    asm volatile(
        "mma.sync.aligned.m16n8k16.row.col.f32.bf16.bf16.f32 "
        "{%0,%1,%2,%3}, {%4,%5,%6,%7}, {%8,%9}, {%0,%1,%2,%3};"
        : "+f"(c0), "+f"(c1), "+f"(c2), "+f"(c3)
        : "r"(a0), "r"(a1), "r"(a2), "r"(a3), "r"(b0), "r"(b1));
}
__device__ __forceinline__ uint32_t sw128(uint32_t off) {
    return off ^ ((off >> 3) & 0x70u);
}

// ---------------- input projection ----------------
__global__ void k_lin_in(const float* __restrict__ pos,
                         const float* __restrict__ W,
                         const float* __restrict__ b) {
    __shared__ float sW[11*64];
    __shared__ float sp[11];
    const int i = blockIdx.x;
    const int f = threadIdx.x;
    for (int t = f; t < 11*64; t += 64) sW[t] = W[t];
    if (f < 11) sp[f] = pos[i*11 + f];
    __syncthreads();
    float acc = b[f];
    #pragma unroll
    for (int c = 0; c < 11; c++) acc = fmaf(sp[c], sW[c*64 + f], acc);
    g_h[i*64 + f] = acc;
}

// ---------------- bf16 hi + swizzled store + exact 0.5*sq --------------
__global__ void k_split() {
    const int node = blockIdx.x*8 + (threadIdx.x >> 5);
    const int lane = threadIdx.x & 31;
    float2 f = *(const float2*)(g_h + (size_t)node*64 + lane*2);

    __nv_bfloat16 h0 = __float2bfloat16(f.x);
    __nv_bfloat16 h1 = __float2bfloat16(f.y);

    unsigned off = (unsigned)node*128u + (unsigned)lane*4u;
    unsigned sw  = sw128(off);
    *(unsigned*)((char*)g_hb_hi + sw) =
        (unsigned)__bfloat16_as_ushort(h0) | ((unsigned)__bfloat16_as_ushort(h1) << 16);

    float s = f.x*f.x + f.y*f.y;            // exact fp32 norms
    #pragma unroll
    for (int o = 16; o > 0; o >>= 1) s += __shfl_down_sync(0xffffffffu, s, o);
    if (lane == 0) g_hsq[node] = 0.5f * s;
}

// ---------------- prefilter: eighth-split mma.sync d2, top-4 reg lists --
// grid 1024: blockIdx = rowblk*8 + eighth. 128 rows x 2048 cols per CTA.
#define OB_B    0u
#define OB_HSQ  32768u
#define SMEM_D2 (33792u + 2048u)

__device__ __forceinline__ uint32_t enc_key(float f, int idx) {
    uint32_t u = __float_as_uint(f);
    u = ((int)u < 0) ? ~u : (u | 0x80000000u);   // monotone float->uint
    return (u & 0xFFFFC000u) | (uint32_t)idx;    // key[18] | idx[14]
}
__device__ __forceinline__ void ins4r(uint32_t* L, uint32_t v) {
    #pragma unroll
    for (int p = 0; p < 4; p++) {
        uint32_t lo = umin(L[p], v);
        v = umax(L[p], v);
        L[p] = lo;
    }
}

__global__ __launch_bounds__(256, 3) void k_d2pref() {
    extern __shared__ __align__(16) char smraw[];
    const uint32_t rawb = smem_u32(smraw);
    const uint32_t sb = (rawb + 1023u) & ~1023u;
    char* smc = smraw + (sb - rawb);

    const int tid  = threadIdx.x;
    const int w    = tid >> 5;
    const int lane = tid & 31;
    const int rowblk = blockIdx.x >> 3;
    const int eighth = blockIdx.x & 7;
    const int row0 = rowblk * 128;
    const int t0   = eighth * 16;

    // ---- stage A (128 rows, hi) through B buf0 ----
    {
        const char* srchi = (const char*)g_hb_hi + (size_t)row0*128;
        for (int i = tid; i < 1024; i += 256)
            cp16(sb + OB_B + i*16, srchi + i*16);
        cp_commit();
        cp_wait<0>();
    }
    __syncthreads();

    uint32_t af[4][4];
    {
        const int m  = lane >> 3;
        const int rr = (w << 4) + ((m & 1) << 3) + (lane & 7);
        const int kb0 = (m >> 1) << 4;
        #pragma unroll
        for (int ks = 0; ks < 4; ks++) {
            uint32_t loc = (uint32_t)rr*128u + (uint32_t)(ks*32 + kb0);
            ldsm4(af[ks][0], af[ks][1], af[ks][2], af[ks][3],
                  sb + OB_B + sw128(loc));
        }
    }
    __syncthreads();      // A frags in regs; buf0 reusable

    const int q   = lane >> 2;
    const int s3  = lane & 3;
    const int lr0 = (w << 4) + q;
    const int lr1 = lr0 + 8;
    uint32_t La[4], Lb[4];
    #pragma unroll
    for (int p = 0; p < 4; p++) { La[p] = 0xFFFFFFFFu; Lb[p] = 0xFFFFFFFFu; }
    uint32_t th0 = 0xFFFFFFFFu, th1 = 0xFFFFFFFFu;

    #pragma unroll
    for (int u = 0; u < 2; u++) {
        const char* bhi = (const char*)g_hb_hi + (size_t)(t0 + u)*16384;
        uint32_t dst = sb + OB_B + (uint32_t)u*16384u;
        for (int i = tid; i < 1024; i += 256)
            cp16(dst + i*16, bhi + i*16);
        if (tid < 32) cp16(sb + OB_HSQ + (uint32_t)u*512u + tid*16,
                           (const char*)g_hsq + (size_t)(t0 + u)*512 + tid*16);
        cp_commit();
    }
    cp_wait<1>();
    __syncthreads();

    const int bm = lane >> 3;
    const int bn = lane & 7;

    for (int tl = 0; tl < 16; tl++) {
        const uint32_t bbase = sb + OB_B + (uint32_t)(tl & 1)*16384u;
        const char* hsqp = smc + OB_HSQ + (uint32_t)(tl & 1)*512u;
        const int jb = (t0 + tl) * 128;

        #pragma unroll 1
        for (int nb = 0; nb < 16; nb++) {
            uint32_t bh[8];
            {
                uint32_t loc = (uint32_t)((nb*8 + bn)*128 + bm*16);
                ldsm4(bh[0], bh[1], bh[2], bh[3], bbase + sw128(loc));
                ldsm4(bh[4], bh[5], bh[6], bh[7], bbase + sw128(loc + 64u));
            }
            float h0 = 0.f, h1 = 0.f, h2 = 0.f, h3 = 0.f;
            float g0 = 0.f, g1 = 0.f, g2 = 0.f, g3 = 0.f;
            mma_bf16(h0, h1, h2, h3, af[0][0], af[0][1], af[0][2], af[0][3],
                     bh[0], bh[1]);
            mma_bf16(g0, g1, g2, g3, af[1][0], af[1][1], af[1][2], af[1][3],
                     bh[2], bh[3]);
            mma_bf16(h0, h1, h2, h3, af[2][0], af[2][1], af[2][2], af[2][3],
                     bh[4], bh[5]);
            mma_bf16(g0, g1, g2, g3, af[3][0], af[3][1], af[3][2], af[3][3],
                     bh[6], bh[7]);
            float c0 = h0 + g0;
            float c1 = h1 + g1;
            float c2 = h2 + g2;
            float c3 = h3 + g3;

            float2 hs = *(const float2*)(hsqp + (nb*8 + 2*s3)*4);
            const int colb = jb + nb*8 + 2*s3;
            uint32_t e0 = enc_key(hs.x - c0, colb);
            uint32_t e1 = enc_key(hs.y - c1, colb + 1);
            uint32_t e2 = enc_key(hs.x - c2, colb);
            uint32_t e3 = enc_key(hs.y - c3, colb + 1);
            if (e0 < th0) { ins4r(La, e0); th0 = La[3]; }
            if (e1 < th0) { ins4r(La, e1); th0 = La[3]; }
            if (e2 < th1) { ins4r(Lb, e2); th1 = Lb[3]; }
            if (e3 < th1) { ins4r(Lb, e3); th1 = Lb[3]; }
        }

        __syncthreads();
        if (tl + 2 < 16) {
            const int tt = t0 + tl + 2;
            const char* bhi = (const char*)g_hb_hi + (size_t)tt*16384;
            uint32_t dst = sb + OB_B + (uint32_t)(tl & 1)*16384u;
            for (int i = tid; i < 1024; i += 256)
                cp16(dst + i*16, bhi + i*16);
            if (tid < 32) cp16(sb + OB_HSQ + (uint32_t)(tl & 1)*512u + tid*16,
                               (const char*)g_hsq + (size_t)tt*512 + tid*16);
            cp_commit();
            cp_wait<1>();
        } else {
            cp_wait<0>();
        }
        __syncthreads();
    }

    // dump packed key|idx candidates (sorted ascending within each list)
    unsigned* d0 = g_cand + (size_t)(row0 + lr0)*128 + eighth*16 + s3*4;
    unsigned* d1 = g_cand + (size_t)(row0 + lr1)*128 + eighth*16 + s3*4;
    #pragma unroll
    for (int p = 0; p < 4; p++) {
        d0[p] = La[p];
        d1[p] = Lb[p];
    }
}

// ---------------- rerank: approx-top-32 select + exact fp32 rerank -----
__global__ __launch_bounds__(256, 4) void k_rerank() {
    __shared__ float hi_s[8*64];
    const int tid  = threadIdx.x;
    const int w    = tid >> 5;
    const int lane = tid & 31;
    const int rbase = blockIdx.x * 8;

    for (int i = tid; i < 8*16; i += 256) {
        int r = i >> 4, k4 = i & 15;
        *(float4*)(hi_s + r*64 + k4*4) =
            *(const float4*)(g_h + (size_t)(rbase + r)*64 + k4*4);
    }
    __syncthreads();

    const int row = rbase + w;
    const float* hi4 = hi_s + w*64;

    // load my 4 packed candidates (each lane's quad is ascending-sorted)
    uint32_t Lp[4];
    {
        const uint4 v = *(const uint4*)(g_cand + (size_t)row*128 + lane*4);
        Lp[0] = v.x; Lp[1] = v.y; Lp[2] = v.z; Lp[3] = v.w;
    }

    // ---- select approx-top-32 of 128: 32 warp-argmin rounds ----
    // lane r ends holding the rank-r candidate (by packed (key, idx)).
    int mycand = 0;
    {
        int ptr = 0;
        #pragma unroll 1
        for (int r = 0; r < 32; r++) {
            uint32_t head = (ptr < 4) ? Lp[ptr] : 0xFFFFFFFFu;
            uint32_t bv = head;
            #pragma unroll
            for (int o = 16; o > 0; o >>= 1)
                bv = umin(bv, __shfl_xor_sync(0xffffffffu, bv, o));
            if (head == bv) ptr++;        // packed keys unique (idx unique)
            if (lane == r) mycand = (int)(bv & 0x3FFFu);
        }
    }

    // ---- exact fp32 key for my single candidate ----
    const float4* hj = (const float4*)(g_h + (size_t)mycand*64);
    float s0 = 0.f, s1 = 0.f, s2 = 0.f, s3 = 0.f;
    #pragma unroll
    for (int kk = 0; kk < 16; kk++) {
        float4 a = *(const float4*)(hi4 + kk*4);
        float4 b = hj[kk];
        s0 = fmaf(a.x, b.x, s0); s1 = fmaf(a.y, b.y, s1);
        s2 = fmaf(a.z, b.z, s2); s3 = fmaf(a.w, b.w, s3);
    }
    float kv = g_hsq[mycand] - ((s0 + s1) + (s2 + s3));
    const int ki = mycand;

    // ---- 17 exact (val, idx) argmin rounds ----
    #pragma unroll
    for (int r = 0; r < KK; r++) {
        float bv = kv;
        int   bi = ki;
        #pragma unroll
        for (int o = 16; o > 0; o >>= 1) {
            float ov = __shfl_xor_sync(0xffffffffu, bv, o);
            int   oi = __shfl_xor_sync(0xffffffffu, bi, o);
            if (ov < bv || (ov == bv && oi < bi)) { bv = ov; bi = oi; }
        }
        if (lane == 0) g_idx[row*KK + r] = bi;
        if (ki == bi) kv = 3.4e38f;
    }
}

// ------------- P/Q factorization: P = h@W1_top, Q = h@W1_bot + b1 -------
__global__ __launch_bounds__(256) void k_pq(const float* __restrict__ W,
                                            const float* __restrict__ b1) {
    __shared__ float As[64][128];
    __shared__ float Ws[64][64];
    const int tid = threadIdx.x;
    const int e0  = blockIdx.x * 128;
    const int r0  = (tid >> 4) * 8;
    const int f0  = (tid & 15) * 4;

    for (int t = tid; t < 2048; t += 256) {
        int e = t & 127, k4 = t >> 7;
        float4 v = *(const float4*)(g_h + (size_t)(e0 + e)*64 + (k4<<2));
        As[(k4<<2)+0][e] = v.x; As[(k4<<2)+1][e] = v.y;
        As[(k4<<2)+2][e] = v.z; As[(k4<<2)+3][e] = v.w;
    }

    for (int p = 0; p < 2; p++) {
        __syncthreads();
        for (int t = tid; t < 1024; t += 256) {
            int f4 = t & 15, kk = t >> 4;
            *(float4*)&Ws[kk][f4<<2] =
                *(const float4*)(W + (size_t)((p<<6)+kk)*64 + (f4<<2));
        }
        __syncthreads();

        ull acc[4][4];
        #pragma unroll
        for (int rp = 0; rp < 4; rp++)
            #pragma unroll
            for (int c = 0; c < 4; c++) acc[rp][c] = 0ull;

        #pragma unroll 4
        for (int k = 0; k < 64; k++) {
            ulonglong2 a01 = *(const ulonglong2*)(&As[k][r0]);
            ulonglong2 a23 = *(const ulonglong2*)(&As[k][r0+4]);
            float4 b = *(const float4*)(&Ws[k][f0]);
            ull ar[4] = { a01.x, a01.y, a23.x, a23.y };
            ull bd[4] = { dup2(b.x), dup2(b.y), dup2(b.z), dup2(b.w) };
            #pragma unroll
            for (int rp = 0; rp < 4; rp++)
                #pragma unroll
                for (int c = 0; c < 4; c++)
                    acc[rp][c] = ff2(ar[rp], bd[c], acc[rp][c]);
        }

        float* out = (p == 0) ? g_P : g_Q;
        float4 bv = (p == 0) ? make_float4(0.f, 0.f, 0.f, 0.f)
                             : *(const float4*)(b1 + f0);
        #pragma unroll
        for (int rp = 0; rp < 4; rp++) {
            float2 u0 = up2(acc[rp][0]), u1 = up2(acc[rp][1]);
            float2 u2 = up2(acc[rp][2]), u3 = up2(acc[rp][3]);
            int ea = e0 + r0 + 2*rp;
            *(float4*)(out + (size_t)ea*64 + f0) =
                make_float4(u0.x + bv.x, u1.x + bv.y, u2.x + bv.z, u3.x + bv.w);
            *(float4*)(out + (size_t)(ea+1)*64 + f0) =
                make_float4(u0.y + bv.x, u1.y + bv.y, u2.y + bv.z, u3.y + bv.w);
        }
    }
}

// ------------- edge stats: batch stats of y1 = P[to] + Q[frm] ----------
__global__ __launch_bounds__(256) void k_estats() {
    const int tid = threadIdx.x;
    const int e0  = blockIdx.x * 128;
    const int f4  = tid & 15;
    const int el0 = tid >> 4;

    float4 s  = make_float4(0.f, 0.f, 0.f, 0.f);
    float4 s2 = make_float4(0.f, 0.f, 0.f, 0.f);
    for (int e = el0; e < 128; e += 16) {
        int eg = e0 + e;
        int i = eg & (Nn-1);
        int to  = g_idx[i*KK + 1 + (eg >> 14)];
        int frm = g_idx[i*KK];
        float4 p = *(const float4*)(g_P + (size_t)to*64  + (f4<<2));
        float4 q = *(const float4*)(g_Q + (size_t)frm*64 + (f4<<2));
        float4 v = make_float4(p.x+q.x, p.y+q.y, p.z+q.z, p.w+q.w);
        s.x += v.x; s.y += v.y; s.z += v.z; s.w += v.w;
        s2.x = fmaf(v.x, v.x, s2.x); s2.y = fmaf(v.y, v.y, s2.y);
        s2.z = fmaf(v.z, v.z, s2.z); s2.w = fmaf(v.w, v.w, s2.w);
    }
    __shared__ float4 sh[256], sh2[256];
    sh[tid] = s; sh2[tid] = s2;
    __syncthreads();
    if (tid < 16) {
        float4 S  = make_float4(0.f, 0.f, 0.f, 0.f);
        float4 S2 = make_float4(0.f, 0.f, 0.f, 0.f);
        #pragma unroll
        for (int g = 0; g < 16; g++) {
            float4 a = sh[g*16 + tid], b = sh2[g*16 + tid];
            S.x += a.x; S.y += a.y; S.z += a.z; S.w += a.w;
            S2.x += b.x; S2.y += b.y; S2.z += b.z; S2.w += b.w;
        }
        float* d = g_part + (size_t)blockIdx.x*128 + tid*4;
        d[0] = S.x; d[1] = S.y; d[2] = S.z; d[3] = S.w;
        d[64] = S2.x; d[65] = S2.y; d[66] = S2.z; d[67] = S2.w;
    }
}

// ------------- GEMM B: depth-64, fused BN-affine+ReLU in, stats out ----
// MODE 0: A = bn(P[to]+Q[frm]) (msg), MODE 1: A = bn(g_u1) (upd)
template<int MODE>
__global__ __launch_bounds__(256) void k_gemm_b(const float* __restrict__ W,
                                                const float* __restrict__ bias) {
    __shared__ float As[64][128];
    __shared__ float Ws[64][64];
    const int tid = threadIdx.x;
    const int e0  = blockIdx.x * 128;
    const int r0  = (tid >> 4) * 8;
    const int f0  = (tid & 15) * 4;

    for (int t = tid; t < 1024; t += 256) {
        int f4 = t & 15, kk = t >> 4;
        *(float4*)&Ws[kk][f4<<2] = *(const float4*)(W + (size_t)kk*64 + (f4<<2));
    }
    for (int t = tid; t < 2048; t += 256) {
        int e = t & 127, k4 = t >> 7;
        int eg = e0 + e;
        float4 v;
        if (MODE == 0) {
            int i = eg & (Nn-1);
            int to  = g_idx[i*KK + 1 + (eg >> 14)];
            int frm = g_idx[i*KK];
            float4 p = *(const float4*)(g_P + (size_t)to*64  + (k4<<2));
            float4 q = *(const float4*)(g_Q + (size_t)frm*64 + (k4<<2));
            v = make_float4(p.x+q.x, p.y+q.y, p.z+q.z, p.w+q.w);
        } else {
            v = *(const float4*)(g_u1 + (size_t)eg*64 + (k4<<2));
        }
        float4 sc = *(const float4*)(g_scale + (k4<<2));
        float4 sh = *(const float4*)(g_shift + (k4<<2));
        As[(k4<<2)+0][e] = fmaxf(fmaf(v.x, sc.x, sh.x), 0.f);
        As[(k4<<2)+1][e] = fmaxf(fmaf(v.y, sc.y, sh.y), 0.f);
        As[(k4<<2)+2][e] = fmaxf(fmaf(v.z, sc.z, sh.z), 0.f);
        As[(k4<<2)+3][e] = fmaxf(fmaf(v.w, sc.w, sh.w), 0.f);
    }
    __syncthreads();

    ull acc[4][4];
    #pragma unroll
    for (int rp = 0; rp < 4; rp++)
        #pragma unroll
        for (int c = 0; c < 4; c++) acc[rp][c] = 0ull;

    #pragma unroll 4
    for (int k = 0; k < 64; k++) {
        ulonglong2 a01 = *(const ulonglong2*)(&As[k][r0]);
        ulonglong2 a23 = *(const ulonglong2*)(&As[k][r0+4]);
        float4 b = *(const float4*)(&Ws[k][f0]);
        ull ar[4] = { a01.x, a01.y, a23.x, a23.y };
        ull bd[4] = { dup2(b.x), dup2(b.y), dup2(b.z), dup2(b.w) };
        #pragma unroll
        for (int rp = 0; rp < 4; rp++)
            #pragma unroll
            for (int c = 0; c < 4; c++)
                acc[rp][c] = ff2(ar[rp], bd[c], acc[rp][c]);
    }

    float* out = (MODE == 0) ? g_y2 : g_u2;
    float4 bv = *(const float4*)(bias + f0);
    float fs[4] = {0.f,0.f,0.f,0.f}, fq[4] = {0.f,0.f,0.f,0.f};
    #pragma unroll
    for (int rp = 0; rp < 4; rp++) {
        float2 u0 = up2(acc[rp][0]), u1 = up2(acc[rp][1]);
        float2 u2 = up2(acc[rp][2]), u3 = up2(acc[rp][3]);
        int ea = e0 + r0 + 2*rp;
        float4 oA = make_float4(u0.x + bv.x, u1.x + bv.y, u2.x + bv.z, u3.x + bv.w);
        float4 oB = make_float4(u0.y + bv.x, u1.y + bv.y, u2.y + bv.z, u3.y + bv.w);
        *(float4*)(out + (size_t)ea*64 + f0) = oA;
        *(float4*)(out + (size_t)(ea+1)*64 + f0) = oB;
        fs[0] += oA.x + oB.x; fq[0] += oA.x*oA.x + oB.x*oB.x;
        fs[1] += oA.y + oB.y; fq[1] += oA.y*oA.y + oB.y*oB.y;
        fs[2] += oA.z + oB.z; fq[2] += oA.z*oA.z + oB.z*oB.z;
        fs[3] += oA.w + oB.w; fq[3] += oA.w*oA.w + oB.w*oB.w;
    }

    __syncthreads();         // all As reads done before scratch reuse
    float* scr = &As[0][0];
    #pragma unroll
    for (int c = 0; c < 4; c++) {
        scr[tid*4 + c]        = fs[c];
        scr[1024 + tid*4 + c] = fq[c];
    }
    __syncthreads();
    if (tid < 64) {
        const int fg = tid >> 2, c = tid & 3;
        float S = 0.f, Q = 0.f;
        #pragma unroll
        for (int g = 0; g < 16; g++) {
            int idx = (g*16 + fg)*4 + c;
            S += scr[idx]; Q += scr[1024 + idx];
        }
        g_part[(size_t)blockIdx.x*128 + tid]      = S;
        g_part[(size_t)blockIdx.x*128 + 64 + tid] = Q;
    }
}

// ------------- GEMM A (upd only): depth-128, fused stats partials ------
__global__ __launch_bounds__(256) void k_gemm_a1(const float* __restrict__ W,
                                                 const float* __restrict__ bias) {
    __shared__ float As[64][128];
    __shared__ float Ws[64][64];
    const int tid = threadIdx.x;
    const int e0  = blockIdx.x * 128;
    const int r0  = (tid >> 4) * 8;
    const int f0  = (tid & 15) * 4;
    ull acc[4][4];
    #pragma unroll
    for (int rp = 0; rp < 4; rp++)
        #pragma unroll
        for (int c = 0; c < 4; c++) acc[rp][c] = 0ull;

    for (int p = 0; p < 2; p++) {
        for (int t = tid; t < 1024; t += 256) {
            int f4 = t & 15, kk = t >> 4;
            *(float4*)&Ws[kk][f4<<2] =
                *(const float4*)(W + (size_t)((p<<6)+kk)*64 + (f4<<2));
        }
        for (int t = tid; t < 2048; t += 256) {
            int e = t & 127, k4 = t >> 7;
            int eg = e0 + e;
            const float* src = (p == 0 ? g_h : g_agg) + (size_t)eg*64;
            float4 v = *(const float4*)(src + (k4<<2));
            As[(k4<<2)+0][e] = v.x; As[(k4<<2)+1][e] = v.y;
            As[(k4<<2)+2][e] = v.z; As[(k4<<2)+3][e] = v.w;
        }
        __syncthreads();
        #pragma unroll 4
        for (int k = 0; k < 64; k++) {
            ulonglong2 a01 = *(const ulonglong2*)(&As[k][r0]);
            ulonglong2 a23 = *(const ulonglong2*)(&As[k][r0+4]);
            float4 b = *(const float4*)(&Ws[k][f0]);
            ull ar[4] = { a01.x, a01.y, a23.x, a23.y };
            ull bd[4] = { dup2(b.x), dup2(b.y), dup2(b.z), dup2(b.w) };
            #pragma unroll
            for (int rp = 0; rp < 4; rp++)
                #pragma unroll
                for (int c = 0; c < 4; c++)
                    acc[rp][c] = ff2(ar[rp], bd[c], acc[rp][c]);
        }
        __syncthreads();
    }

    float4 bv = *(const float4*)(bias + f0);
    float fs[4] = {0.f,0.f,0.f,0.f}, fq[4] = {0.f,0.f,0.f,0.f};
    #pragma unroll
    for (int rp = 0; rp < 4; rp++) {
        float2 u0 = up2(acc[rp][0]), u1 = up2(acc[rp][1]);
        float2 u2 = up2(acc[rp][2]), u3 = up2(acc[rp][3]);
        int ea = e0 + r0 + 2*rp;
        float4 oA = make_float4(u0.x + bv.x, u1.x + bv.y, u2.x + bv.z, u3.x + bv.w);
        float4 oB = make_float4(u0.y + bv.x, u1.y + bv.y, u2.y + bv.z, u3.y + bv.w);
        *(float4*)(g_u1 + (size_t)ea*64 + f0) = oA;
        *(float4*)(g_u1 + (size_t)(ea+1)*64 + f0) = oB;
        fs[0] += oA.x + oB.x; fq[0] += oA.x*oA.x + oB.x*oB.x;
        fs[1] += oA.y + oB.y; fq[1] += oA.y*oA.y + oB.y*oB.y;
        fs[2] += oA.z + oB.z; fq[2] += oA.z*oA.z + oB.z*oB.z;
        fs[3] += oA.w + oB.w; fq[3] += oA.w*oA.w + oB.w*oB.w;
    }

    float* scr = &As[0][0];
    #pragma unroll
    for (int c = 0; c < 4; c++) {
        scr[tid*4 + c]        = fs[c];
        scr[1024 + tid*4 + c] = fq[c];
    }
    __syncthreads();
    if (tid < 64) {
        const int fg = tid >> 2, c = tid & 3;
        float S = 0.f, Q = 0.f;
        #pragma unroll
        for (int g = 0; g < 16; g++) {
            int idx = (g*16 + fg)*4 + c;
            S += scr[idx]; Q += scr[1024 + idx];
        }
        g_part[(size_t)blockIdx.x*128 + tid]      = S;
        g_part[(size_t)blockIdx.x*128 + 64 + tid] = Q;
    }
}

// ---------------- final-pool stats (over g_h) ----------------
__global__ void k_stats(int M, int P) {
    const float* __restrict__ x = g_h;
    const int t = threadIdx.x;
    float s = 0.f, s2 = 0.f;
    const size_t total = (size_t)M * 64;
    for (size_t idx = (size_t)blockIdx.x*256 + t; idx < total; idx += (size_t)P*256) {
        float v = x[idx];
        s += v; s2 = fmaf(v, v, s2);
    }
    __shared__ float sh[256], sh2[256];
    sh[t] = s; sh2[t] = s2;
    __syncthreads();
    if (t < 64) {
        s  = sh[t]  + sh[t+64]  + sh[t+128]  + sh[t+192];
        s2 = sh2[t] + sh2[t+64] + sh2[t+128] + sh2[t+192];
        g_part[(size_t)blockIdx.x*128 + t]      = s;
        g_part[(size_t)blockIdx.x*128 + 64 + t] = s2;
    }
}

// ---------------- stats finalize: 256-thread parallel reduce ----------
__global__ void k_stats_fin(int M, int P,
                            const float* __restrict__ g,
                            const float* __restrict__ be) {
    const int tid = threadIdx.x;
    const int f = tid & 63;
    const int part = tid >> 6;               // 0..3
    float s = 0.f, s2 = 0.f;
    for (int p = part; p < P; p += 4) {
        s  += g_part[(size_t)p*128 + f];
        s2 += g_part[(size_t)p*128 + 64 + f];
    }
    __shared__ float sh[256], sh2[256];
    sh[tid] = s; sh2[tid] = s2;
    __syncthreads();
    if (tid < 64) {
        s  = sh[tid]  + sh[tid+64]  + sh[tid+128]  + sh[tid+192];
        s2 = sh2[tid] + sh2[tid+64] + sh2[tid+128] + sh2[tid+192];
        const float inv  = 1.f / (float)M;
        const float mean = s * inv;
        const float var  = fmaf(-mean, mean, s2 * inv);
        const float sc   = g[tid] * rsqrtf(var + 1e-5f);
        g_scale[tid] = sc;
        g_shift[tid] = fmaf(-mean, sc, be[tid]);
    }
}

// ---------------- zero, scatter, residual ----------------
__global__ void k_zero_agg() {
    int i = blockIdx.x*blockDim.x + threadIdx.x;
    g_agg[i] = 0.f;
}

__global__ void k_scatter() {
    const int gid = blockIdx.x*256 + threadIdx.x;
    const int q = gid & 15;
    const int e = gid >> 4;
    const int i = e & (Nn-1);
    const int to = g_idx[i*KK + 1 + (e >> 14)];
    const int f = q << 2;
    float4 v  = *(const float4*)(g_y2 + (size_t)e*64 + f);
    float4 sc = *(const float4*)(g_scale + f);
    float4 sh = *(const float4*)(g_shift + f);
    float* dst = g_agg + (size_t)to*64 + f;
    atomicAdd(dst+0, fmaxf(fmaf(v.x, sc.x, sh.x), 0.f));
    atomicAdd(dst+1, fmaxf(fmaf(v.y, sc.y, sh.y), 0.f));
    atomicAdd(dst+2, fmaxf(fmaf(v.z, sc.z, sh.z), 0.f));
    atomicAdd(dst+3, fmaxf(fmaf(v.w, sc.w, sh.w), 0.f));
}

__global__ void k_resid() {
    const int gid = blockIdx.x*blockDim.x + threadIdx.x;
    const int f = gid & 63;
    const float v = g_u2[gid];
    g_h[gid] += fmaxf(fmaf(v, g_scale[f], g_shift[f]), 0.f);
}

// ---------------- final pool + prediction ----------------
__global__ void k_fin(const float* __restrict__ pW,
                      const float* __restrict__ pb,
                      float* __restrict__ out, int P) {
    const int f = threadIdx.x;
    float s = 0.f;
    for (int p = 0; p < P; p++) s += g_part[(size_t)p*128 + f];
    float v = (s / (float)Nn) * pW[f];
    __shared__ float red[64];
    red[f] = v;
    __syncthreads();
    if (f < 32) {
        float x = red[f] + red[f+32];
        #pragma unroll
        for (int o = 16; o > 0; o >>= 1) x += __shfl_down_sync(0xffffffffu, x, o);
        if (f == 0) out[0] = x + pb[0];
    }
}

// ---------------- host driver ----------------
extern "C" void kernel_launch(void* const* d_in, const int* in_sizes, int n_in,
                              void* d_out, int out_size) {
    const float* pos    = (const float*)d_in[0];
    const float* linW   = (const float*)d_in[1];
    const float* linb   = (const float*)d_in[2];
    const float* predW  = (const float*)d_in[3];
    const float* predb  = (const float*)d_in[4];
    const float* msgW1  = (const float*)d_in[5];
    const float* msgb1  = (const float*)d_in[6];
    const float* msgg1  = (const float*)d_in[7];
    const float* msgbe1 = (const float*)d_in[8];
    const float* msgW2  = (const float*)d_in[9];
    const float* msgb2  = (const float*)d_in[10];
    const float* msgg2  = (const float*)d_in[11];
    const float* msgbe2 = (const float*)d_in[12];
    const float* updW1  = (const float*)d_in[13];
    const float* updb1  = (const float*)d_in[14];
    const float* updg1  = (const float*)d_in[15];
    const float* updbe1 = (const float*)d_in[16];
    const float* updW2  = (const float*)d_in[17];
    const float* updb2  = (const float*)d_in[18];
    const float* updg2  = (const float*)d_in[19];
    const float* updbe2 = (const float*)d_in[20];
    float* out = (float*)d_out;

    static int smem_set = 0;
    if (!smem_set) {
        cudaFuncSetAttribute(k_d2pref, cudaFuncAttributeMaxDynamicSharedMemorySize,
                             SMEM_D2);
        smem_set = 1;
    }

    k_lin_in<<<Nn, 64>>>(pos, linW, linb);

    for (int l = 0; l < Ll; l++) {
        // ---- KNN: prefilter + approx-top-32 select + exact rerank ----
        k_split<<<Nn/8, 256>>>();
        k_d2pref<<<1024, 256, SMEM_D2>>>();
        k_rerank<<<Nn/8, 256>>>();

        // ---- message MLP: P/Q factorization ----
        k_pq<<<Nn/128, 256>>>(msgW1 + (size_t)l*128*64, msgb1 + l*64);
        k_estats<<<2048, 256>>>();
        k_stats_fin<<<1, 256>>>(Ee, 2048, msgg1 + l*64, msgbe1 + l*64);
        k_gemm_b<0><<<Ee/128, 256>>>(msgW2 + (size_t)l*64*64, msgb2 + l*64);
        k_stats_fin<<<1, 256>>>(Ee, 2048, msgg2 + l*64, msgbe2 + l*64);

        // ---- aggregate ----
        k_zero_agg<<<Nn*64/256, 256>>>();
        k_scatter<<<Ee*16/256, 256>>>();

        // ---- update MLP + residual (stats fused) ----
        k_gemm_a1<<<Nn/128, 256>>>(updW1 + (size_t)l*128*64, updb1 + l*64);
        k_stats_fin<<<1, 256>>>(Nn, 128, updg1 + l*64, updbe1 + l*64);
        k_gemm_b<1><<<Nn/128, 256>>>(updW2 + (size_t)l*64*64, updb2 + l*64);
        k_stats_fin<<<1, 256>>>(Nn, 128, updg2 + l*64, updbe2 + l*64);
        k_resid<<<Nn*64/256, 256>>>();
    }

    k_stats<<<64, 256>>>(Nn, 64);
    k_fin<<<1, 64>>>(predW, predb, out, 64);
}

// round 16
// speedup vs baseline: 6.0994x; 1.0074x over previous
#include <cuda_runtime.h>
#include <cuda_bf16.h>
#include <cstdint>

#define Nn 16384
#define Dd 64
#define KK 17
#define Ee (Nn*16)
#define Ll 4

typedef unsigned long long ull;

// ---------------- scratch (static device allocations) ----------------
__device__ float g_h[Nn*Dd];
__device__ float g_hsq[Nn];                     // exact 0.5 * ||h_i||^2
__device__ float g_hsqq[Nn];                    // hsq * scale^2 (quant domain)
__device__ int   g_amax;                        // float-bits of max|h| (>=0)
__device__ int   g_idx[Nn*KK];
__device__ unsigned g_cand[(size_t)Nn*128];     // packed key18|idx14 candidates
__device__ float g_P[Nn*Dd];                    // h @ W1_top          (msg)
__device__ float g_Q[Nn*Dd];                    // h @ W1_bot + b1     (msg)
__device__ float g_y2[(size_t)Ee*Dd];
__device__ float g_agg[Nn*Dd];
__device__ float g_u1[Nn*Dd];
__device__ float g_u2[Nn*Dd];
__device__ float g_part[2048*128];
__device__ float g_scale[Dd];
__device__ float g_shift[Dd];
// swizzled int8 quantized h (64 bytes per node)
__device__ unsigned g_hq[Nn*16];

// ---------------- packed f32x2 helpers (for MLP GEMMs) ----------------
__device__ __forceinline__ ull ff2(ull a, ull b, ull c) {
    ull d;
    asm("fma.rn.f32x2 %0, %1, %2, %3;" : "=l"(d) : "l"(a), "l"(b), "l"(c));
    return d;
}
__device__ __forceinline__ ull dup2(float x) {
    ull d;
    unsigned u = __float_as_uint(x);
    asm("mov.b64 %0, {%1, %1};" : "=l"(d) : "r"(u));
    return d;
}
__device__ __forceinline__ float2 up2(ull v) {
    float2 r;
    asm("mov.b64 {%0, %1}, %2;" : "=f"(r.x), "=f"(r.y) : "l"(v));
    return r;
}

// ---------------- sm_80-era async-copy / ldmatrix / mma helpers --------
__device__ __forceinline__ uint32_t smem_u32(const void* p) {
    uint32_t a;
    asm("{ .reg .u64 t; cvta.to.shared.u64 t, %1; cvt.u32.u64 %0, t; }"
        : "=r"(a) : "l"(p));
    return a;
}
__device__ __forceinline__ void cp16(uint32_t d, const void* s) {
    asm volatile("cp.async.cg.shared.global [%0], [%1], 16;"
                 :: "r"(d), "l"(s) : "memory");
}
__device__ __forceinline__ void cp_commit() {
    asm volatile("cp.async.commit_group;" ::: "memory");
}
template<int N> __device__ __forceinline__ void cp_wait() {
    asm volatile("cp.async.wait_group %0;" :: "n"(N) : "memory");
}
__device__ __forceinline__ void ldsm4(uint32_t& r0, uint32_t& r1,
                                      uint32_t& r2, uint32_t& r3, uint32_t a) {
    asm volatile("ldmatrix.sync.aligned.m8n8.x4.shared.b16 {%0,%1,%2,%3}, [%4];"
                 : "=r"(r0), "=r"(r1), "=r"(r2), "=r"(r3) : "r"(a));
}
__device__ __forceinline__ void mma_s8(int& c0, int& c1, int& c2, int& c3,
                                       uint32_t a0, uint32_t a1, uint32_t a2,
                                       uint32_t a3, uint32_t b0, uint32_t b1) {
    asm volatile(
        "mma.sync.aligned.m16n8k32.row.col.s32.s8.s8.s32 "
        "{%0,%1,%2,%3}, {%4,%5,%6,%7}, {%8,%9}, {%0,%1,%2,%3};"
        : "+r"(c0), "+r"(c1), "+r"(c2), "+r"(c3)
        : "r"(a0), "r"(a1), "r"(a2), "r"(a3), "r"(b0), "r"(b1));
}
__device__ __forceinline__ uint32_t sw128(uint32_t off) {
    return off ^ ((off >> 3) & 0x70u);
}

// ---------------- input projection ----------------
__global__ void k_lin_in(const float* __restrict__ pos,
                         const float* __restrict__ W,
                         const float* __restrict__ b) {
    __shared__ float sW[11*64];
    __shared__ float sp[11];
    const int i = blockIdx.x;
    const int f = threadIdx.x;
    if (i == 0 && f == 0) g_amax = 0;
    for (int t = f; t < 11*64; t += 64) sW[t] = W[t];
    if (f < 11) sp[f] = pos[i*11 + f];
    __syncthreads();
    float acc = b[f];
    #pragma unroll
    for (int c = 0; c < 11; c++) acc = fmaf(sp[c], sW[c*64 + f], acc);
    g_h[i*64 + f] = acc;
}

// ---------------- exact 0.5*sq + global amax ----------------
__global__ void k_split() {
    const int node = blockIdx.x*8 + (threadIdx.x >> 5);
    const int lane = threadIdx.x & 31;
    float2 f = *(const float2*)(g_h + (size_t)node*64 + lane*2);

    float s = f.x*f.x + f.y*f.y;
    float m = fmaxf(fabsf(f.x), fabsf(f.y));
    #pragma unroll
    for (int o = 16; o > 0; o >>= 1) {
        s += __shfl_down_sync(0xffffffffu, s, o);
        m = fmaxf(m, __shfl_down_sync(0xffffffffu, m, o));
    }
    if (lane == 0) {
        g_hsq[node] = 0.5f * s;
        atomicMax(&g_amax, __float_as_int(m));
    }
}

// ---------------- int8 quantize (swizzled) + scaled hsq -----------------
__global__ void k_quant() {
    const int gid = blockIdx.x*256 + threadIdx.x;   // 65536 = Nn*4
    const int node = gid >> 2;
    const int c    = gid & 3;
    const float amax = __int_as_float(g_amax);
    const float scale = 127.0f / amax;

    unsigned pk[4];
    #pragma unroll
    for (int t = 0; t < 4; t++) {
        float4 v = *(const float4*)(g_h + (size_t)node*64 + c*16 + t*4);
        int q0 = max(-127, min(127, __float2int_rn(v.x*scale)));
        int q1 = max(-127, min(127, __float2int_rn(v.y*scale)));
        int q2 = max(-127, min(127, __float2int_rn(v.z*scale)));
        int q3 = max(-127, min(127, __float2int_rn(v.w*scale)));
        pk[t] = (unsigned)(q0 & 255) | ((unsigned)(q1 & 255) << 8) |
                ((unsigned)(q2 & 255) << 16) | ((unsigned)(q3 & 255) << 24);
    }
    unsigned off = (unsigned)node*64u + (unsigned)c*16u;
    *(uint4*)((char*)g_hq + sw128(off)) = make_uint4(pk[0], pk[1], pk[2], pk[3]);
    if (c == 0) g_hsqq[node] = g_hsq[node] * scale * scale;
}

// ---------------- prefilter: int8 mma d2, eighth-split, top-4 lists -----
// grid 1024: blockIdx = rowblk*8 + eighth. 128 rows x 2048 cols per CTA.
// smem: B bufs 2 x 8192 @0, A 8192 @16384, hsqq 2 x 512 @24576
#define OB_B    0u
#define OB_A    16384u
#define OB_HSQ  24576u
#define SMEM_D2 (25600u + 2048u)

__device__ __forceinline__ uint32_t enc_key(float f, int idx) {
    uint32_t u = __float_as_uint(f);
    u = ((int)u < 0) ? ~u : (u | 0x80000000u);   // monotone float->uint
    return (u & 0xFFFFC000u) | (uint32_t)idx;    // key[18] | idx[14]
}
__device__ __forceinline__ void ins4r(uint32_t* L, uint32_t v) {
    #pragma unroll
    for (int p = 0; p < 4; p++) {
        uint32_t lo = umin(L[p], v);
        v = umax(L[p], v);
        L[p] = lo;
    }
}

__global__ __launch_bounds__(256, 3) void k_d2pref() {
    extern __shared__ __align__(16) char smraw[];
    const uint32_t rawb = smem_u32(smraw);
    const uint32_t sb = (rawb + 1023u) & ~1023u;
    char* smc = smraw + (sb - rawb);

    const int tid  = threadIdx.x;
    const int w    = tid >> 5;
    const int lane = tid & 31;
    const int rowblk = blockIdx.x >> 3;
    const int eighth = blockIdx.x & 7;
    const int row0 = rowblk * 128;
    const int t0   = eighth * 16;

    // ---- stage A (128 nodes, int8) + B tiles t0, t0+1 (+ hsqq) ----
    {
        const char* srcA = (const char*)g_hq + (size_t)row0*64;
        for (int i = tid; i < 512; i += 256)
            cp16(sb + OB_A + i*16, srcA + i*16);
        cp_commit();
        #pragma unroll
        for (int u = 0; u < 2; u++) {
            const char* bq = (const char*)g_hq + (size_t)(t0 + u)*8192;
            uint32_t dst = sb + OB_B + (uint32_t)u*8192u;
            for (int i = tid; i < 512; i += 256)
                cp16(dst + i*16, bq + i*16);
            if (tid < 32) cp16(sb + OB_HSQ + (uint32_t)u*512u + tid*16,
                               (const char*)g_hsqq + (size_t)(t0 + u)*512 + tid*16);
            cp_commit();
        }
    }
    cp_wait<1>();          // A + B0 resident
    __syncthreads();

    // ---- A fragments: 2 k32-steps, int8 via b16-pair ldmatrix ----
    uint32_t af[2][4];
    {
        const int m  = lane >> 3;
        const int rr = (w << 4) + ((m & 1) << 3) + (lane & 7);
        const int kb0 = (m >> 1) << 4;
        #pragma unroll
        for (int ks = 0; ks < 2; ks++) {
            uint32_t loc = (uint32_t)rr*64u + (uint32_t)(ks*32 + kb0);
            ldsm4(af[ks][0], af[ks][1], af[ks][2], af[ks][3],
                  sb + OB_A + sw128(loc));
        }
    }

    const int q   = lane >> 2;
    const int s3  = lane & 3;
    const int lr0 = (w << 4) + q;
    const int lr1 = lr0 + 8;
    uint32_t La[4], Lb[4];
    #pragma unroll
    for (int p = 0; p < 4; p++) { La[p] = 0xFFFFFFFFu; Lb[p] = 0xFFFFFFFFu; }
    uint32_t th0 = 0xFFFFFFFFu, th1 = 0xFFFFFFFFu;

    const int bm = lane >> 3;          // 0..3 -> byte chunk (tile select)
    const int bn = lane & 7;           // node within n8

    for (int tl = 0; tl < 16; tl++) {
        const uint32_t bbase = sb + OB_B + (uint32_t)(tl & 1)*8192u;
        const char* hsqp = smc + OB_HSQ + (uint32_t)(tl & 1)*512u;
        const int jb = (t0 + tl) * 128;

        #pragma unroll 1
        for (int nb = 0; nb < 16; nb++) {
            // one ldsm.x4: tiles = (n8, bytes 0-15/16-31/32-47/48-63)
            uint32_t bf0, bf1, bf2, bf3;
            {
                uint32_t loc = (uint32_t)((nb*8 + bn)*64 + bm*16);
                ldsm4(bf0, bf1, bf2, bf3, bbase + sw128(loc));
            }
            int d0 = 0, d1 = 0, d2i = 0, d3 = 0;
            int e0i = 0, e1i = 0, e2i = 0, e3i = 0;
            mma_s8(d0, d1, d2i, d3, af[0][0], af[0][1], af[0][2], af[0][3],
                   bf0, bf1);
            mma_s8(e0i, e1i, e2i, e3i, af[1][0], af[1][1], af[1][2], af[1][3],
                   bf2, bf3);
            float c0 = (float)(d0 + e0i);
            float c1 = (float)(d1 + e1i);
            float c2 = (float)(d2i + e2i);
            float c3 = (float)(d3 + e3i);

            float2 hs = *(const float2*)(hsqp + (nb*8 + 2*s3)*4);
            const int colb = jb + nb*8 + 2*s3;
            uint32_t k0 = enc_key(hs.x - c0, colb);
            uint32_t k1 = enc_key(hs.y - c1, colb + 1);
            uint32_t k2 = enc_key(hs.x - c2, colb);
            uint32_t k3 = enc_key(hs.y - c3, colb + 1);
            if (k0 < th0) { ins4r(La, k0); th0 = La[3]; }
            if (k1 < th0) { ins4r(La, k1); th0 = La[3]; }
            if (k2 < th1) { ins4r(Lb, k2); th1 = Lb[3]; }
            if (k3 < th1) { ins4r(Lb, k3); th1 = Lb[3]; }
        }

        __syncthreads();
        if (tl + 2 < 16) {
            const int tt = t0 + tl + 2;
            const char* bq = (const char*)g_hq + (size_t)tt*8192;
            uint32_t dst = sb + OB_B + (uint32_t)(tl & 1)*8192u;
            for (int i = tid; i < 512; i += 256)
                cp16(dst + i*16, bq + i*16);
            if (tid < 32) cp16(sb + OB_HSQ + (uint32_t)(tl & 1)*512u + tid*16,
                               (const char*)g_hsqq + (size_t)tt*512 + tid*16);
            cp_commit();
            cp_wait<1>();
        } else {
            cp_wait<0>();
        }
        __syncthreads();
    }

    // dump packed key|idx candidates (sorted ascending within each list)
    unsigned* d0p = g_cand + (size_t)(row0 + lr0)*128 + eighth*16 + s3*4;
    unsigned* d1p = g_cand + (size_t)(row0 + lr1)*128 + eighth*16 + s3*4;
    #pragma unroll
    for (int p = 0; p < 4; p++) {
        d0p[p] = La[p];
        d1p[p] = Lb[p];
    }
}

// ---------------- rerank: approx-top-32 select + exact fp32 rerank -----
__global__ __launch_bounds__(256, 4) void k_rerank() {
    __shared__ float hi_s[8*64];
    const int tid  = threadIdx.x;
    const int w    = tid >> 5;
    const int lane = tid & 31;
    const int rbase = blockIdx.x * 8;

    for (int i = tid; i < 8*16; i += 256) {
        int r = i >> 4, k4 = i & 15;
        *(float4*)(hi_s + r*64 + k4*4) =
            *(const float4*)(g_h + (size_t)(rbase + r)*64 + k4*4);
    }
    __syncthreads();

    const int row = rbase + w;
    const float* hi4 = hi_s + w*64;

    uint32_t Lp[4];
    {
        const uint4 v = *(const uint4*)(g_cand + (size_t)row*128 + lane*4);
        Lp[0] = v.x; Lp[1] = v.y; Lp[2] = v.z; Lp[3] = v.w;
    }

    int mycand = 0;
    {
        int ptr = 0;
        #pragma unroll 1
        for (int r = 0; r < 32; r++) {
            uint32_t head = (ptr < 4) ? Lp[ptr] : 0xFFFFFFFFu;
            uint32_t bv = head;
            #pragma unroll
            for (int o = 16; o > 0; o >>= 1)
                bv = umin(bv, __shfl_xor_sync(0xffffffffu, bv, o));
            if (head == bv) ptr++;
            if (lane == r) mycand = (int)(bv & 0x3FFFu);
        }
    }

    const float4* hj = (const float4*)(g_h + (size_t)mycand*64);
    float s0 = 0.f, s1 = 0.f, s2 = 0.f, s3 = 0.f;
    #pragma unroll
    for (int kk = 0; kk < 16; kk++) {
        float4 a = *(const float4*)(hi4 + kk*4);
        float4 b = hj[kk];
        s0 = fmaf(a.x, b.x, s0); s1 = fmaf(a.y, b.y, s1);
        s2 = fmaf(a.z, b.z, s2); s3 = fmaf(a.w, b.w, s3);
    }
    float kv = g_hsq[mycand] - ((s0 + s1) + (s2 + s3));
    const int ki = mycand;

    #pragma unroll
    for (int r = 0; r < KK; r++) {
        float bv = kv;
        int   bi = ki;
        #pragma unroll
        for (int o = 16; o > 0; o >>= 1) {
            float ov = __shfl_xor_sync(0xffffffffu, bv, o);
            int   oi = __shfl_xor_sync(0xffffffffu, bi, o);
            if (ov < bv || (ov == bv && oi < bi)) { bv = ov; bi = oi; }
        }
        if (lane == 0) g_idx[row*KK + r] = bi;
        if (ki == bi) kv = 3.4e38f;
    }
}

// ------------- P/Q factorization: P = h@W1_top, Q = h@W1_bot + b1 -------
__global__ __launch_bounds__(256) void k_pq(const float* __restrict__ W,
                                            const float* __restrict__ b1) {
    __shared__ float As[64][128];
    __shared__ float Ws[64][64];
    const int tid = threadIdx.x;
    const int e0  = blockIdx.x * 128;
    const int r0  = (tid >> 4) * 8;
    const int f0  = (tid & 15) * 4;

    for (int t = tid; t < 2048; t += 256) {
        int e = t & 127, k4 = t >> 7;
        float4 v = *(const float4*)(g_h + (size_t)(e0 + e)*64 + (k4<<2));
        As[(k4<<2)+0][e] = v.x; As[(k4<<2)+1][e] = v.y;
        As[(k4<<2)+2][e] = v.z; As[(k4<<2)+3][e] = v.w;
    }

    for (int p = 0; p < 2; p++) {
        __syncthreads();
        for (int t = tid; t < 1024; t += 256) {
            int f4 = t & 15, kk = t >> 4;
            *(float4*)&Ws[kk][f4<<2] =
                *(const float4*)(W + (size_t)((p<<6)+kk)*64 + (f4<<2));
        }
        __syncthreads();

        ull acc[4][4];
        #pragma unroll
        for (int rp = 0; rp < 4; rp++)
            #pragma unroll
            for (int c = 0; c < 4; c++) acc[rp][c] = 0ull;

        #pragma unroll 4
        for (int k = 0; k < 64; k++) {
            ulonglong2 a01 = *(const ulonglong2*)(&As[k][r0]);
            ulonglong2 a23 = *(const ulonglong2*)(&As[k][r0+4]);
            float4 b = *(const float4*)(&Ws[k][f0]);
            ull ar[4] = { a01.x, a01.y, a23.x, a23.y };
            ull bd[4] = { dup2(b.x), dup2(b.y), dup2(b.z), dup2(b.w) };
            #pragma unroll
            for (int rp = 0; rp < 4; rp++)
                #pragma unroll
                for (int c = 0; c < 4; c++)
                    acc[rp][c] = ff2(ar[rp], bd[c], acc[rp][c]);
        }

        float* out = (p == 0) ? g_P : g_Q;
        float4 bv = (p == 0) ? make_float4(0.f, 0.f, 0.f, 0.f)
                             : *(const float4*)(b1 + f0);
        #pragma unroll
        for (int rp = 0; rp < 4; rp++) {
            float2 u0 = up2(acc[rp][0]), u1 = up2(acc[rp][1]);
            float2 u2 = up2(acc[rp][2]), u3 = up2(acc[rp][3]);
            int ea = e0 + r0 + 2*rp;
            *(float4*)(out + (size_t)ea*64 + f0) =
                make_float4(u0.x + bv.x, u1.x + bv.y, u2.x + bv.z, u3.x + bv.w);
            *(float4*)(out + (size_t)(ea+1)*64 + f0) =
                make_float4(u0.y + bv.x, u1.y + bv.y, u2.y + bv.z, u3.y + bv.w);
        }
    }
}

// ------------- edge stats: batch stats of y1 = P[to] + Q[frm] ----------
__global__ __launch_bounds__(256) void k_estats() {
    const int tid = threadIdx.x;
    const int e0  = blockIdx.x * 128;
    const int f4  = tid & 15;
    const int el0 = tid >> 4;

    float4 s  = make_float4(0.f, 0.f, 0.f, 0.f);
    float4 s2 = make_float4(0.f, 0.f, 0.f, 0.f);
    for (int e = el0; e < 128; e += 16) {
        int eg = e0 + e;
        int i = eg & (Nn-1);
        int to  = g_idx[i*KK + 1 + (eg >> 14)];
        int frm = g_idx[i*KK];
        float4 p = *(const float4*)(g_P + (size_t)to*64  + (f4<<2));
        float4 q = *(const float4*)(g_Q + (size_t)frm*64 + (f4<<2));
        float4 v = make_float4(p.x+q.x, p.y+q.y, p.z+q.z, p.w+q.w);
        s.x += v.x; s.y += v.y; s.z += v.z; s.w += v.w;
        s2.x = fmaf(v.x, v.x, s2.x); s2.y = fmaf(v.y, v.y, s2.y);
        s2.z = fmaf(v.z, v.z, s2.z); s2.w = fmaf(v.w, v.w, s2.w);
    }
    __shared__ float4 sh[256], sh2[256];
    sh[tid] = s; sh2[tid] = s2;
    __syncthreads();
    if (tid < 16) {
        float4 S  = make_float4(0.f, 0.f, 0.f, 0.f);
        float4 S2 = make_float4(0.f, 0.f, 0.f, 0.f);
        #pragma unroll
        for (int g = 0; g < 16; g++) {
            float4 a = sh[g*16 + tid], b = sh2[g*16 + tid];
            S.x += a.x; S.y += a.y; S.z += a.z; S.w += a.w;
            S2.x += b.x; S2.y += b.y; S2.z += b.z; S2.w += b.w;
        }
        float* d = g_part + (size_t)blockIdx.x*128 + tid*4;
        d[0] = S.x; d[1] = S.y; d[2] = S.z; d[3] = S.w;
        d[64] = S2.x; d[65] = S2.y; d[66] = S2.z; d[67] = S2.w;
    }
}

// ------------- GEMM B: depth-64, fused BN-affine+ReLU in, stats out ----
// MODE 0: A = bn(P[to]+Q[frm]) (msg), MODE 1: A = bn(g_u1) (upd)
template<int MODE>
__global__ __launch_bounds__(256) void k_gemm_b(const float* __restrict__ W,
                                                const float* __restrict__ bias) {
    __shared__ float As[64][128];
    __shared__ float Ws[64][64];
    const int tid = threadIdx.x;
    const int e0  = blockIdx.x * 128;
    const int r0  = (tid >> 4) * 8;
    const int f0  = (tid & 15) * 4;

    for (int t = tid; t < 1024; t += 256) {
        int f4 = t & 15, kk = t >> 4;
        *(float4*)&Ws[kk][f4<<2] = *(const float4*)(W + (size_t)kk*64 + (f4<<2));
    }
    for (int t = tid; t < 2048; t += 256) {
        int e = t & 127, k4 = t >> 7;
        int eg = e0 + e;
        float4 v;
        if (MODE == 0) {
            int i = eg & (Nn-1);
            int to  = g_idx[i*KK + 1 + (eg >> 14)];
            int frm = g_idx[i*KK];
            float4 p = *(const float4*)(g_P + (size_t)to*64  + (k4<<2));
            float4 q = *(const float4*)(g_Q + (size_t)frm*64 + (k4<<2));
            v = make_float4(p.x+q.x, p.y+q.y, p.z+q.z, p.w+q.w);
        } else {
            v = *(const float4*)(g_u1 + (size_t)eg*64 + (k4<<2));
        }
        float4 sc = *(const float4*)(g_scale + (k4<<2));
        float4 sh = *(const float4*)(g_shift + (k4<<2));
        As[(k4<<2)+0][e] = fmaxf(fmaf(v.x, sc.x, sh.x), 0.f);
        As[(k4<<2)+1][e] = fmaxf(fmaf(v.y, sc.y, sh.y), 0.f);
        As[(k4<<2)+2][e] = fmaxf(fmaf(v.z, sc.z, sh.z), 0.f);
        As[(k4<<2)+3][e] = fmaxf(fmaf(v.w, sc.w, sh.w), 0.f);
    }
    __syncthreads();

    ull acc[4][4];
    #pragma unroll
    for (int rp = 0; rp < 4; rp++)
        #pragma unroll
        for (int c = 0; c < 4; c++) acc[rp][c] = 0ull;

    #pragma unroll 4
    for (int k = 0; k < 64; k++) {
        ulonglong2 a01 = *(const ulonglong2*)(&As[k][r0]);
        ulonglong2 a23 = *(const ulonglong2*)(&As[k][r0+4]);
        float4 b = *(const float4*)(&Ws[k][f0]);
        ull ar[4] = { a01.x, a01.y, a23.x, a23.y };
        ull bd[4] = { dup2(b.x), dup2(b.y), dup2(b.z), dup2(b.w) };
        #pragma unroll
        for (int rp = 0; rp < 4; rp++)
            #pragma unroll
            for (int c = 0; c < 4; c++)
                acc[rp][c] = ff2(ar[rp], bd[c], acc[rp][c]);
    }

    float* out = (MODE == 0) ? g_y2 : g_u2;
    float4 bv = *(const float4*)(bias + f0);
    float fs[4] = {0.f,0.f,0.f,0.f}, fq[4] = {0.f,0.f,0.f,0.f};
    #pragma unroll
    for (int rp = 0; rp < 4; rp++) {
        float2 u0 = up2(acc[rp][0]), u1 = up2(acc[rp][1]);
        float2 u2 = up2(acc[rp][2]), u3 = up2(acc[rp][3]);
        int ea = e0 + r0 + 2*rp;
        float4 oA = make_float4(u0.x + bv.x, u1.x + bv.y, u2.x + bv.z, u3.x + bv.w);
        float4 oB = make_float4(u0.y + bv.x, u1.y + bv.y, u2.y + bv.z, u3.y + bv.w);
        *(float4*)(out + (size_t)ea*64 + f0) = oA;
        *(float4*)(out + (size_t)(ea+1)*64 + f0) = oB;
        fs[0] += oA.x + oB.x; fq[0] += oA.x*oA.x + oB.x*oB.x;
        fs[1] += oA.y + oB.y; fq[1] += oA.y*oA.y + oB.y*oB.y;
        fs[2] += oA.z + oB.z; fq[2] += oA.z*oA.z + oB.z*oB.z;
        fs[3] += oA.w + oB.w; fq[3] += oA.w*oA.w + oB.w*oB.w;
    }

    __syncthreads();         // all As reads done before scratch reuse
    float* scr = &As[0][0];
    #pragma unroll
    for (int c = 0; c < 4; c++) {
        scr[tid*4 + c]        = fs[c];
        scr[1024 + tid*4 + c] = fq[c];
    }
    __syncthreads();
    if (tid < 64) {
        const int fg = tid >> 2, c = tid & 3;
        float S = 0.f, Q = 0.f;
        #pragma unroll
        for (int g = 0; g < 16; g++) {
            int idx = (g*16 + fg)*4 + c;
            S += scr[idx]; Q += scr[1024 + idx];
        }
        g_part[(size_t)blockIdx.x*128 + tid]      = S;
        g_part[(size_t)blockIdx.x*128 + 64 + tid] = Q;
    }
}

// ------------- GEMM A (upd only): depth-128, fused stats partials ------
__global__ __launch_bounds__(256) void k_gemm_a1(const float* __restrict__ W,
                                                 const float* __restrict__ bias) {
    __shared__ float As[64][128];
    __shared__ float Ws[64][64];
    const int tid = threadIdx.x;
    const int e0  = blockIdx.x * 128;
    const int r0  = (tid >> 4) * 8;
    const int f0  = (tid & 15) * 4;
    ull acc[4][4];
    #pragma unroll
    for (int rp = 0; rp < 4; rp++)
        #pragma unroll
        for (int c = 0; c < 4; c++) acc[rp][c] = 0ull;

    for (int p = 0; p < 2; p++) {
        for (int t = tid; t < 1024; t += 256) {
            int f4 = t & 15, kk = t >> 4;
            *(float4*)&Ws[kk][f4<<2] =
                *(const float4*)(W + (size_t)((p<<6)+kk)*64 + (f4<<2));
        }
        for (int t = tid; t < 2048; t += 256) {
            int e = t & 127, k4 = t >> 7;
            int eg = e0 + e;
            const float* src = (p == 0 ? g_h : g_agg) + (size_t)eg*64;
            float4 v = *(const float4*)(src + (k4<<2));
            As[(k4<<2)+0][e] = v.x; As[(k4<<2)+1][e] = v.y;
            As[(k4<<2)+2][e] = v.z; As[(k4<<2)+3][e] = v.w;
        }
        __syncthreads();
        #pragma unroll 4
        for (int k = 0; k < 64; k++) {
            ulonglong2 a01 = *(const ulonglong2*)(&As[k][r0]);
            ulonglong2 a23 = *(const ulonglong2*)(&As[k][r0+4]);
            float4 b = *(const float4*)(&Ws[k][f0]);
            ull ar[4] = { a01.x, a01.y, a23.x, a23.y };
            ull bd[4] = { dup2(b.x), dup2(b.y), dup2(b.z), dup2(b.w) };
            #pragma unroll
            for (int rp = 0; rp < 4; rp++)
                #pragma unroll
                for (int c = 0; c < 4; c++)
                    acc[rp][c] = ff2(ar[rp], bd[c], acc[rp][c]);
        }
        __syncthreads();
    }

    float4 bv = *(const float4*)(bias + f0);
    float fs[4] = {0.f,0.f,0.f,0.f}, fq[4] = {0.f,0.f,0.f,0.f};
    #pragma unroll
    for (int rp = 0; rp < 4; rp++) {
        float2 u0 = up2(acc[rp][0]), u1 = up2(acc[rp][1]);
        float2 u2 = up2(acc[rp][2]), u3 = up2(acc[rp][3]);
        int ea = e0 + r0 + 2*rp;
        float4 oA = make_float4(u0.x + bv.x, u1.x + bv.y, u2.x + bv.z, u3.x + bv.w);
        float4 oB = make_float4(u0.y + bv.x, u1.y + bv.y, u2.y + bv.z, u3.y + bv.w);
        *(float4*)(g_u1 + (size_t)ea*64 + f0) = oA;
        *(float4*)(g_u1 + (size_t)(ea+1)*64 + f0) = oB;
        fs[0] += oA.x + oB.x; fq[0] += oA.x*oA.x + oB.x*oB.x;
        fs[1] += oA.y + oB.y; fq[1] += oA.y*oA.y + oB.y*oB.y;
        fs[2] += oA.z + oB.z; fq[2] += oA.z*oA.z + oB.z*oB.z;
        fs[3] += oA.w + oB.w; fq[3] += oA.w*oA.w + oB.w*oB.w;
    }

    float* scr = &As[0][0];
    #pragma unroll
    for (int c = 0; c < 4; c++) {
        scr[tid*4 + c]        = fs[c];
        scr[1024 + tid*4 + c] = fq[c];
    }
    __syncthreads();
    if (tid < 64) {
        const int fg = tid >> 2, c = tid & 3;
        float S = 0.f, Q = 0.f;
        #pragma unroll
        for (int g = 0; g < 16; g++) {
            int idx = (g*16 + fg)*4 + c;
            S += scr[idx]; Q += scr[1024 + idx];
        }
        g_part[(size_t)blockIdx.x*128 + tid]      = S;
        g_part[(size_t)blockIdx.x*128 + 64 + tid] = Q;
    }
}

// ---------------- final-pool stats (over g_h) ----------------
__global__ void k_stats(int M, int P) {
    const float* __restrict__ x = g_h;
    const int t = threadIdx.x;
    float s = 0.f, s2 = 0.f;
    const size_t total = (size_t)M * 64;
    for (size_t idx = (size_t)blockIdx.x*256 + t; idx < total; idx += (size_t)P*256) {
        float v = x[idx];
        s += v; s2 = fmaf(v, v, s2);
    }
    __shared__ float sh[256], sh2[256];
    sh[t] = s; sh2[t] = s2;
    __syncthreads();
    if (t < 64) {
        s  = sh[t]  + sh[t+64]  + sh[t+128]  + sh[t+192];
        s2 = sh2[t] + sh2[t+64] + sh2[t+128] + sh2[t+192];
        g_part[(size_t)blockIdx.x*128 + t]      = s;
        g_part[(size_t)blockIdx.x*128 + 64 + t] = s2;
    }
}

// ---------------- stats finalize: 256-thread parallel reduce ----------
__global__ void k_stats_fin(int M, int P,
                            const float* __restrict__ g,
                            const float* __restrict__ be) {
    const int tid = threadIdx.x;
    const int f = tid & 63;
    const int part = tid >> 6;               // 0..3
    float s = 0.f, s2 = 0.f;
    for (int p = part; p < P; p += 4) {
        s  += g_part[(size_t)p*128 + f];
        s2 += g_part[(size_t)p*128 + 64 + f];
    }
    __shared__ float sh[256], sh2[256];
    sh[tid] = s; sh2[tid] = s2;
    __syncthreads();
    if (tid < 64) {
        s  = sh[tid]  + sh[tid+64]  + sh[tid+128]  + sh[tid+192];
        s2 = sh2[tid] + sh2[tid+64] + sh2[tid+128] + sh2[tid+192];
        const float inv  = 1.f / (float)M;
        const float mean = s * inv;
        const float var  = fmaf(-mean, mean, s2 * inv);
        const float sc   = g[tid] * rsqrtf(var + 1e-5f);
        g_scale[tid] = sc;
        g_shift[tid] = fmaf(-mean, sc, be[tid]);
    }
}

// ---------------- zero, scatter, residual ----------------
__global__ void k_zero_agg() {
    int i = blockIdx.x*blockDim.x + threadIdx.x;
    g_agg[i] = 0.f;
}

__global__ void k_scatter() {
    const int gid = blockIdx.x*256 + threadIdx.x;
    const int q = gid & 15;
    const int e = gid >> 4;
    const int i = e & (Nn-1);
    const int to = g_idx[i*KK + 1 + (e >> 14)];
    const int f = q << 2;
    float4 v  = *(const float4*)(g_y2 + (size_t)e*64 + f);
    float4 sc = *(const float4*)(g_scale + f);
    float4 sh = *(const float4*)(g_shift + f);
    float* dst = g_agg + (size_t)to*64 + f;
    atomicAdd(dst+0, fmaxf(fmaf(v.x, sc.x, sh.x), 0.f));
    atomicAdd(dst+1, fmaxf(fmaf(v.y, sc.y, sh.y), 0.f));
    atomicAdd(dst+2, fmaxf(fmaf(v.z, sc.z, sh.z), 0.f));
    atomicAdd(dst+3, fmaxf(fmaf(v.w, sc.w, sh.w), 0.f));
}

__global__ void k_resid() {
    const int gid = blockIdx.x*blockDim.x + threadIdx.x;
    const int f = gid & 63;
    const float v = g_u2[gid];
    g_h[gid] += fmaxf(fmaf(v, g_scale[f], g_shift[f]), 0.f);
    if (gid == 0) g_amax = 0;          // reset for next layer's k_split
}

// ---------------- final pool + prediction ----------------
__global__ void k_fin(const float* __restrict__ pW,
                      const float* __restrict__ pb,
                      float* __restrict__ out, int P) {
    const int f = threadIdx.x;
    float s = 0.f;
    for (int p = 0; p < P; p++) s += g_part[(size_t)p*128 + f];
    float v = (s / (float)Nn) * pW[f];
    __shared__ float red[64];
    red[f] = v;
    __syncthreads();
    if (f < 32) {
        float x = red[f] + red[f+32];
        #pragma unroll
        for (int o = 16; o > 0; o >>= 1) x += __shfl_down_sync(0xffffffffu, x, o);
        if (f == 0) out[0] = x + pb[0];
    }
}

// ---------------- host driver ----------------
extern "C" void kernel_launch(void* const* d_in, const int* in_sizes, int n_in,
                              void* d_out, int out_size) {
    const float* pos    = (const float*)d_in[0];
    const float* linW   = (const float*)d_in[1];
    const float* linb   = (const float*)d_in[2];
    const float* predW  = (const float*)d_in[3];
    const float* predb  = (const float*)d_in[4];
    const float* msgW1  = (const float*)d_in[5];
    const float* msgb1  = (const float*)d_in[6];
    const float* msgg1  = (const float*)d_in[7];
    const float* msgbe1 = (const float*)d_in[8];
    const float* msgW2  = (const float*)d_in[9];
    const float* msgb2  = (const float*)d_in[10];
    const float* msgg2  = (const float*)d_in[11];
    const float* msgbe2 = (const float*)d_in[12];
    const float* updW1  = (const float*)d_in[13];
    const float* updb1  = (const float*)d_in[14];
    const float* updg1  = (const float*)d_in[15];
    const float* updbe1 = (const float*)d_in[16];
    const float* updW2  = (const float*)d_in[17];
    const float* updb2  = (const float*)d_in[18];
    const float* updg2  = (const float*)d_in[19];
    const float* updbe2 = (const float*)d_in[20];
    float* out = (float*)d_out;

    static int smem_set = 0;
    if (!smem_set) {
        cudaFuncSetAttribute(k_d2pref, cudaFuncAttributeMaxDynamicSharedMemorySize,
                             SMEM_D2);
        smem_set = 1;
    }

    k_lin_in<<<Nn, 64>>>(pos, linW, linb);

    for (int l = 0; l < Ll; l++) {
        // ---- KNN: int8 prefilter + approx-top-32 select + exact rerank ----
        k_split<<<Nn/8, 256>>>();
        k_quant<<<256, 256>>>();
        k_d2pref<<<1024, 256, SMEM_D2>>>();
        k_rerank<<<Nn/8, 256>>>();

        // ---- message MLP: P/Q factorization ----
        k_pq<<<Nn/128, 256>>>(msgW1 + (size_t)l*128*64, msgb1 + l*64);
        k_estats<<<2048, 256>>>();
        k_stats_fin<<<1, 256>>>(Ee, 2048, msgg1 + l*64, msgbe1 + l*64);
        k_gemm_b<0><<<Ee/128, 256>>>(msgW2 + (size_t)l*64*64, msgb2 + l*64);
        k_stats_fin<<<1, 256>>>(Ee, 2048, msgg2 + l*64, msgbe2 + l*64);

        // ---- aggregate ----
        k_zero_agg<<<Nn*64/256, 256>>>();
        k_scatter<<<Ee*16/256, 256>>>();

        // ---- update MLP + residual (stats fused) ----
        k_gemm_a1<<<Nn/128, 256>>>(updW1 + (size_t)l*128*64, updb1 + l*64);
        k_stats_fin<<<1, 256>>>(Nn, 128, updg1 + l*64, updbe1 + l*64);
        k_gemm_b<1><<<Nn/128, 256>>>(updW2 + (size_t)l*64*64, updb2 + l*64);
        k_stats_fin<<<1, 256>>>(Nn, 128, updg2 + l*64, updbe2 + l*64);
        k_resid<<<Nn*64/256, 256>>>();
    }

    k_stats<<<64, 256>>>(Nn, 64);
    k_fin<<<1, 64>>>(predW, predb, out, 64);
}

// round 17
// speedup vs baseline: 6.5239x; 1.0696x over previous
#include <cuda_runtime.h>
#include <cuda_bf16.h>
#include <cstdint>

#define Nn 16384
#define Dd 64
#define KK 17
#define Ee (Nn*16)
#define Ll 4

typedef unsigned long long ull;

// ---------------- scratch (static device allocations) ----------------
__device__ float g_h[Nn*Dd];
__device__ float g_hsq[Nn];                     // exact 0.5 * ||h_i||^2
__device__ int   g_hsqqi[Nn];                   // rint(hsq*scale^2) + 2^22
__device__ int   g_amax;                        // float-bits of max|h| (>=0)
__device__ int   g_idx[Nn*KK];
__device__ unsigned g_cand[(size_t)Nn*128];     // packed key18|idx14 candidates
__device__ float g_P[Nn*Dd];                    // h @ W1_top          (msg)
__device__ float g_Q[Nn*Dd];                    // h @ W1_bot + b1     (msg)
__device__ float g_y2[(size_t)Ee*Dd];
__device__ float g_agg[Nn*Dd];
__device__ float g_u1[Nn*Dd];
__device__ float g_u2[Nn*Dd];
__device__ float g_part[2048*128];
__device__ float g_scale[Dd];
__device__ float g_shift[Dd];
// swizzled int8 quantized h (64 bytes per node)
__device__ unsigned g_hq[Nn*16];

// ---------------- packed f32x2 helpers (for MLP GEMMs) ----------------
__device__ __forceinline__ ull ff2(ull a, ull b, ull c) {
    ull d;
    asm("fma.rn.f32x2 %0, %1, %2, %3;" : "=l"(d) : "l"(a), "l"(b), "l"(c));
    return d;
}
__device__ __forceinline__ ull dup2(float x) {
    ull d;
    unsigned u = __float_as_uint(x);
    asm("mov.b64 %0, {%1, %1};" : "=l"(d) : "r"(u));
    return d;
}
__device__ __forceinline__ float2 up2(ull v) {
    float2 r;
    asm("mov.b64 {%0, %1}, %2;" : "=f"(r.x), "=f"(r.y) : "l"(v));
    return r;
}

// ---------------- sm_80-era async-copy / ldmatrix / mma helpers --------
__device__ __forceinline__ uint32_t smem_u32(const void* p) {
    uint32_t a;
    asm("{ .reg .u64 t; cvta.to.shared.u64 t, %1; cvt.u32.u64 %0, t; }"
        : "=r"(a) : "l"(p));
    return a;
}
__device__ __forceinline__ void cp16(uint32_t d, const void* s) {
    asm volatile("cp.async.cg.shared.global [%0], [%1], 16;"
                 :: "r"(d), "l"(s) : "memory");
}
__device__ __forceinline__ void cp_commit() {
    asm volatile("cp.async.commit_group;" ::: "memory");
}
template<int N> __device__ __forceinline__ void cp_wait() {
    asm volatile("cp.async.wait_group %0;" :: "n"(N) : "memory");
}
__device__ __forceinline__ void ldsm4(uint32_t& r0, uint32_t& r1,
                                      uint32_t& r2, uint32_t& r3, uint32_t a) {
    asm volatile("ldmatrix.sync.aligned.m8n8.x4.shared.b16 {%0,%1,%2,%3}, [%4];"
                 : "=r"(r0), "=r"(r1), "=r"(r2), "=r"(r3) : "r"(a));
}
__device__ __forceinline__ void mma_s8(int& c0, int& c1, int& c2, int& c3,
                                       uint32_t a0, uint32_t a1, uint32_t a2,
                                       uint32_t a3, uint32_t b0, uint32_t b1) {
    asm volatile(
        "mma.sync.aligned.m16n8k32.row.col.s32.s8.s8.s32 "
        "{%0,%1,%2,%3}, {%4,%5,%6,%7}, {%8,%9}, {%0,%1,%2,%3};"
        : "+r"(c0), "+r"(c1), "+r"(c2), "+r"(c3)
        : "r"(a0), "r"(a1), "r"(a2), "r"(a3), "r"(b0), "r"(b1));
}
__device__ __forceinline__ uint32_t sw128(uint32_t off) {
    return off ^ ((off >> 3) & 0x70u);
}

// ---------------- input projection ----------------
__global__ void k_lin_in(const float* __restrict__ pos,
                         const float* __restrict__ W,
                         const float* __restrict__ b) {
    __shared__ float sW[11*64];
    __shared__ float sp[11];
    const int i = blockIdx.x;
    const int f = threadIdx.x;
    if (i == 0 && f == 0) g_amax = 0;
    for (int t = f; t < 11*64; t += 64) sW[t] = W[t];
    if (f < 11) sp[f] = pos[i*11 + f];
    __syncthreads();
    float acc = b[f];
    #pragma unroll
    for (int c = 0; c < 11; c++) acc = fmaf(sp[c], sW[c*64 + f], acc);
    g_h[i*64 + f] = acc;
}

// ---------------- exact 0.5*sq + global amax ----------------
__global__ void k_split() {
    const int node = blockIdx.x*8 + (threadIdx.x >> 5);
    const int lane = threadIdx.x & 31;
    float2 f = *(const float2*)(g_h + (size_t)node*64 + lane*2);

    float s = f.x*f.x + f.y*f.y;
    float m = fmaxf(fabsf(f.x), fabsf(f.y));
    #pragma unroll
    for (int o = 16; o > 0; o >>= 1) {
        s += __shfl_down_sync(0xffffffffu, s, o);
        m = fmaxf(m, __shfl_down_sync(0xffffffffu, m, o));
    }
    if (lane == 0) {
        g_hsq[node] = 0.5f * s;
        atomicMax(&g_amax, __float_as_int(m));
    }
}

// ---------------- int8 quantize (swizzled) + biased int hsq -------------
__global__ void k_quant() {
    const int gid = blockIdx.x*256 + threadIdx.x;   // 65536 = Nn*4
    const int node = gid >> 2;
    const int c    = gid & 3;
    const float amax = __int_as_float(g_amax);
    const float scale = 127.0f / amax;

    unsigned pk[4];
    #pragma unroll
    for (int t = 0; t < 4; t++) {
        float4 v = *(const float4*)(g_h + (size_t)node*64 + c*16 + t*4);
        int q0 = max(-127, min(127, __float2int_rn(v.x*scale)));
        int q1 = max(-127, min(127, __float2int_rn(v.y*scale)));
        int q2 = max(-127, min(127, __float2int_rn(v.z*scale)));
        int q3 = max(-127, min(127, __float2int_rn(v.w*scale)));
        pk[t] = (unsigned)(q0 & 255) | ((unsigned)(q1 & 255) << 8) |
                ((unsigned)(q2 & 255) << 16) | ((unsigned)(q3 & 255) << 24);
    }
    unsigned off = (unsigned)node*64u + (unsigned)c*16u;
    *(uint4*)((char*)g_hq + sw128(off)) = make_uint4(pk[0], pk[1], pk[2], pk[3]);
    if (c == 0)
        g_hsqqi[node] = __float2int_rn(g_hsq[node] * scale * scale) + (1 << 22);
}

// ---------------- prefilter: int8 mma d2, pure-int epilogue -------------
// grid 1024: blockIdx = rowblk*8 + eighth. 128 rows x 2048 cols per CTA.
// smem: B bufs 2 x 8192 @0, A 8192 @16384, hsqqi 2 x 512 @24576
#define OB_B    0u
#define OB_A    16384u
#define OB_HSQ  24576u
#define SMEM_D2 (25600u + 2048u)

__device__ __forceinline__ void ins4r(uint32_t* L, uint32_t v) {
    #pragma unroll
    for (int p = 0; p < 4; p++) {
        uint32_t lo = umin(L[p], v);
        v = umax(L[p], v);
        L[p] = lo;
    }
}

__global__ __launch_bounds__(256, 3) void k_d2pref() {
    extern __shared__ __align__(16) char smraw[];
    const uint32_t rawb = smem_u32(smraw);
    const uint32_t sb = (rawb + 1023u) & ~1023u;
    char* smc = smraw + (sb - rawb);

    const int tid  = threadIdx.x;
    const int w    = tid >> 5;
    const int lane = tid & 31;
    const int rowblk = blockIdx.x >> 3;
    const int eighth = blockIdx.x & 7;
    const int row0 = rowblk * 128;
    const int t0   = eighth * 16;

    // ---- stage A (128 nodes, int8) + B tiles t0, t0+1 (+ hsqqi) ----
    {
        const char* srcA = (const char*)g_hq + (size_t)row0*64;
        for (int i = tid; i < 512; i += 256)
            cp16(sb + OB_A + i*16, srcA + i*16);
        cp_commit();
        #pragma unroll
        for (int u = 0; u < 2; u++) {
            const char* bq = (const char*)g_hq + (size_t)(t0 + u)*8192;
            uint32_t dst = sb + OB_B + (uint32_t)u*8192u;
            for (int i = tid; i < 512; i += 256)
                cp16(dst + i*16, bq + i*16);
            if (tid < 32) cp16(sb + OB_HSQ + (uint32_t)u*512u + tid*16,
                               (const char*)g_hsqqi + (size_t)(t0 + u)*512 + tid*16);
            cp_commit();
        }
    }
    cp_wait<1>();          // A + B0 resident
    __syncthreads();

    // ---- A fragments: 2 k32-steps, int8 via b16-pair ldmatrix ----
    uint32_t af[2][4];
    {
        const int m  = lane >> 3;
        const int rr = (w << 4) + ((m & 1) << 3) + (lane & 7);
        const int kb0 = (m >> 1) << 4;
        #pragma unroll
        for (int ks = 0; ks < 2; ks++) {
            uint32_t loc = (uint32_t)rr*64u + (uint32_t)(ks*32 + kb0);
            ldsm4(af[ks][0], af[ks][1], af[ks][2], af[ks][3],
                  sb + OB_A + sw128(loc));
        }
    }

    const int q   = lane >> 2;
    const int s3  = lane & 3;
    const int lr0 = (w << 4) + q;
    const int lr1 = lr0 + 8;
    uint32_t La[4], Lb[4];
    #pragma unroll
    for (int p = 0; p < 4; p++) { La[p] = 0xFFFFFFFFu; Lb[p] = 0xFFFFFFFFu; }
    uint32_t th0 = 0xFFFFFFFFu, th1 = 0xFFFFFFFFu;

    const int bm = lane >> 3;          // 0..3 -> byte chunk (tile select)
    const int bn = lane & 7;           // node within n8

    for (int tl = 0; tl < 16; tl++) {
        const uint32_t bbase = sb + OB_B + (uint32_t)(tl & 1)*8192u;
        const char* hsqp = smc + OB_HSQ + (uint32_t)(tl & 1)*512u;
        const int jb = (t0 + tl) * 128;

        #pragma unroll 1
        for (int nb = 0; nb < 16; nb++) {
            // one ldsm.x4: tiles = (n8, bytes 0-15/16-31/32-47/48-63)
            uint32_t bf0, bf1, bf2, bf3;
            {
                uint32_t loc = (uint32_t)((nb*8 + bn)*64 + bm*16);
                ldsm4(bf0, bf1, bf2, bf3, bbase + sw128(loc));
            }
            // chained accumulation: one accumulator set for both k32 steps
            int d0 = 0, d1 = 0, d2i = 0, d3 = 0;
            mma_s8(d0, d1, d2i, d3, af[0][0], af[0][1], af[0][2], af[0][3],
                   bf0, bf1);
            mma_s8(d0, d1, d2i, d3, af[1][0], af[1][1], af[1][2], af[1][3],
                   bf2, bf3);

            // pure-int epilogue: key_b = hsqqi - dot (positive, biased)
            int2 hb = *(const int2*)(hsqp + (nb*8 + 2*s3)*4);
            const unsigned colb = (unsigned)(jb + nb*8 + 2*s3);
            uint32_t k0 = ((unsigned)(hb.x - d0)  >> 5)*16384u + colb;
            uint32_t k1 = ((unsigned)(hb.y - d1)  >> 5)*16384u + colb + 1u;
            uint32_t k2 = ((unsigned)(hb.x - d2i) >> 5)*16384u + colb;
            uint32_t k3 = ((unsigned)(hb.y - d3)  >> 5)*16384u + colb + 1u;
            if (k0 < th0) { ins4r(La, k0); th0 = La[3]; }
            if (k1 < th0) { ins4r(La, k1); th0 = La[3]; }
            if (k2 < th1) { ins4r(Lb, k2); th1 = Lb[3]; }
            if (k3 < th1) { ins4r(Lb, k3); th1 = Lb[3]; }
        }

        __syncthreads();
        if (tl + 2 < 16) {
            const int tt = t0 + tl + 2;
            const char* bq = (const char*)g_hq + (size_t)tt*8192;
            uint32_t dst = sb + OB_B + (uint32_t)(tl & 1)*8192u;
            for (int i = tid; i < 512; i += 256)
                cp16(dst + i*16, bq + i*16);
            if (tid < 32) cp16(sb + OB_HSQ + (uint32_t)(tl & 1)*512u + tid*16,
                               (const char*)g_hsqqi + (size_t)tt*512 + tid*16);
            cp_commit();
            cp_wait<1>();
        } else {
            cp_wait<0>();
        }
        __syncthreads();
    }

    // dump packed key|idx candidates (sorted ascending within each list)
    unsigned* d0p = g_cand + (size_t)(row0 + lr0)*128 + eighth*16 + s3*4;
    unsigned* d1p = g_cand + (size_t)(row0 + lr1)*128 + eighth*16 + s3*4;
    #pragma unroll
    for (int p = 0; p < 4; p++) {
        d0p[p] = La[p];
        d1p[p] = Lb[p];
    }
}

// ---------------- rerank: approx-top-32 select + exact fp32 rerank -----
__global__ __launch_bounds__(256, 4) void k_rerank() {
    __shared__ float hi_s[8*64];
    const int tid  = threadIdx.x;
    const int w    = tid >> 5;
    const int lane = tid & 31;
    const int rbase = blockIdx.x * 8;

    for (int i = tid; i < 8*16; i += 256) {
        int r = i >> 4, k4 = i & 15;
        *(float4*)(hi_s + r*64 + k4*4) =
            *(const float4*)(g_h + (size_t)(rbase + r)*64 + k4*4);
    }
    __syncthreads();

    const int row = rbase + w;
    const float* hi4 = hi_s + w*64;

    uint32_t Lp[4];
    {
        const uint4 v = *(const uint4*)(g_cand + (size_t)row*128 + lane*4);
        Lp[0] = v.x; Lp[1] = v.y; Lp[2] = v.z; Lp[3] = v.w;
    }

    int mycand = 0;
    {
        int ptr = 0;
        #pragma unroll 1
        for (int r = 0; r < 32; r++) {
            uint32_t head = (ptr < 4) ? Lp[ptr] : 0xFFFFFFFFu;
            uint32_t bv = head;
            #pragma unroll
            for (int o = 16; o > 0; o >>= 1)
                bv = umin(bv, __shfl_xor_sync(0xffffffffu, bv, o));
            if (head == bv) ptr++;
            if (lane == r) mycand = (int)(bv & 0x3FFFu);
        }
    }

    const float4* hj = (const float4*)(g_h + (size_t)mycand*64);
    float s0 = 0.f, s1 = 0.f, s2 = 0.f, s3 = 0.f;
    #pragma unroll
    for (int kk = 0; kk < 16; kk++) {
        float4 a = *(const float4*)(hi4 + kk*4);
        float4 b = hj[kk];
        s0 = fmaf(a.x, b.x, s0); s1 = fmaf(a.y, b.y, s1);
        s2 = fmaf(a.z, b.z, s2); s3 = fmaf(a.w, b.w, s3);
    }
    float kv = g_hsq[mycand] - ((s0 + s1) + (s2 + s3));
    const int ki = mycand;

    #pragma unroll
    for (int r = 0; r < KK; r++) {
        float bv = kv;
        int   bi = ki;
        #pragma unroll
        for (int o = 16; o > 0; o >>= 1) {
            float ov = __shfl_xor_sync(0xffffffffu, bv, o);
            int   oi = __shfl_xor_sync(0xffffffffu, bi, o);
            if (ov < bv || (ov == bv && oi < bi)) { bv = ov; bi = oi; }
        }
        if (lane == 0) g_idx[row*KK + r] = bi;
        if (ki == bi) kv = 3.4e38f;
    }
}

// ------------- P/Q factorization: P = h@W1_top, Q = h@W1_bot + b1 -------
__global__ __launch_bounds__(256) void k_pq(const float* __restrict__ W,
                                            const float* __restrict__ b1) {
    __shared__ float As[64][128];
    __shared__ float Ws[64][64];
    const int tid = threadIdx.x;
    const int e0  = blockIdx.x * 128;
    const int r0  = (tid >> 4) * 8;
    const int f0  = (tid & 15) * 4;

    for (int t = tid; t < 2048; t += 256) {
        int e = t & 127, k4 = t >> 7;
        float4 v = *(const float4*)(g_h + (size_t)(e0 + e)*64 + (k4<<2));
        As[(k4<<2)+0][e] = v.x; As[(k4<<2)+1][e] = v.y;
        As[(k4<<2)+2][e] = v.z; As[(k4<<2)+3][e] = v.w;
    }

    for (int p = 0; p < 2; p++) {
        __syncthreads();
        for (int t = tid; t < 1024; t += 256) {
            int f4 = t & 15, kk = t >> 4;
            *(float4*)&Ws[kk][f4<<2] =
                *(const float4*)(W + (size_t)((p<<6)+kk)*64 + (f4<<2));
        }
        __syncthreads();

        ull acc[4][4];
        #pragma unroll
        for (int rp = 0; rp < 4; rp++)
            #pragma unroll
            for (int c = 0; c < 4; c++) acc[rp][c] = 0ull;

        #pragma unroll 4
        for (int k = 0; k < 64; k++) {
            ulonglong2 a01 = *(const ulonglong2*)(&As[k][r0]);
            ulonglong2 a23 = *(const ulonglong2*)(&As[k][r0+4]);
            float4 b = *(const float4*)(&Ws[k][f0]);
            ull ar[4] = { a01.x, a01.y, a23.x, a23.y };
            ull bd[4] = { dup2(b.x), dup2(b.y), dup2(b.z), dup2(b.w) };
            #pragma unroll
            for (int rp = 0; rp < 4; rp++)
                #pragma unroll
                for (int c = 0; c < 4; c++)
                    acc[rp][c] = ff2(ar[rp], bd[c], acc[rp][c]);
        }

        float* out = (p == 0) ? g_P : g_Q;
        float4 bv = (p == 0) ? make_float4(0.f, 0.f, 0.f, 0.f)
                             : *(const float4*)(b1 + f0);
        #pragma unroll
        for (int rp = 0; rp < 4; rp++) {
            float2 u0 = up2(acc[rp][0]), u1 = up2(acc[rp][1]);
            float2 u2 = up2(acc[rp][2]), u3 = up2(acc[rp][3]);
            int ea = e0 + r0 + 2*rp;
            *(float4*)(out + (size_t)ea*64 + f0) =
                make_float4(u0.x + bv.x, u1.x + bv.y, u2.x + bv.z, u3.x + bv.w);
            *(float4*)(out + (size_t)(ea+1)*64 + f0) =
                make_float4(u0.y + bv.x, u1.y + bv.y, u2.y + bv.z, u3.y + bv.w);
        }
    }
}

// ------------- edge stats: batch stats of y1 = P[to] + Q[frm] ----------
__global__ __launch_bounds__(256) void k_estats() {
    const int tid = threadIdx.x;
    const int e0  = blockIdx.x * 128;
    const int f4  = tid & 15;
    const int el0 = tid >> 4;

    float4 s  = make_float4(0.f, 0.f, 0.f, 0.f);
    float4 s2 = make_float4(0.f, 0.f, 0.f, 0.f);
    for (int e = el0; e < 128; e += 16) {
        int eg = e0 + e;
        int i = eg & (Nn-1);
        int to  = g_idx[i*KK + 1 + (eg >> 14)];
        int frm = g_idx[i*KK];
        float4 p = *(const float4*)(g_P + (size_t)to*64  + (f4<<2));
        float4 q = *(const float4*)(g_Q + (size_t)frm*64 + (f4<<2));
        float4 v = make_float4(p.x+q.x, p.y+q.y, p.z+q.z, p.w+q.w);
        s.x += v.x; s.y += v.y; s.z += v.z; s.w += v.w;
        s2.x = fmaf(v.x, v.x, s2.x); s2.y = fmaf(v.y, v.y, s2.y);
        s2.z = fmaf(v.z, v.z, s2.z); s2.w = fmaf(v.w, v.w, s2.w);
    }
    __shared__ float4 sh[256], sh2[256];
    sh[tid] = s; sh2[tid] = s2;
    __syncthreads();
    if (tid < 16) {
        float4 S  = make_float4(0.f, 0.f, 0.f, 0.f);
        float4 S2 = make_float4(0.f, 0.f, 0.f, 0.f);
        #pragma unroll
        for (int g = 0; g < 16; g++) {
            float4 a = sh[g*16 + tid], b = sh2[g*16 + tid];
            S.x += a.x; S.y += a.y; S.z += a.z; S.w += a.w;
            S2.x += b.x; S2.y += b.y; S2.z += b.z; S2.w += b.w;
        }
        float* d = g_part + (size_t)blockIdx.x*128 + tid*4;
        d[0] = S.x; d[1] = S.y; d[2] = S.z; d[3] = S.w;
        d[64] = S2.x; d[65] = S2.y; d[66] = S2.z; d[67] = S2.w;
    }
}

// ------------- GEMM B: depth-64, fused BN-affine+ReLU in, stats out ----
// MODE 0: A = bn(P[to]+Q[frm]) (msg), MODE 1: A = bn(g_u1) (upd)
template<int MODE>
__global__ __launch_bounds__(256) void k_gemm_b(const float* __restrict__ W,
                                                const float* __restrict__ bias) {
    __shared__ float As[64][128];
    __shared__ float Ws[64][64];
    const int tid = threadIdx.x;
    const int e0  = blockIdx.x * 128;
    const int r0  = (tid >> 4) * 8;
    const int f0  = (tid & 15) * 4;

    for (int t = tid; t < 1024; t += 256) {
        int f4 = t & 15, kk = t >> 4;
        *(float4*)&Ws[kk][f4<<2] = *(const float4*)(W + (size_t)kk*64 + (f4<<2));
    }
    for (int t = tid; t < 2048; t += 256) {
        int e = t & 127, k4 = t >> 7;
        int eg = e0 + e;
        float4 v;
        if (MODE == 0) {
            int i = eg & (Nn-1);
            int to  = g_idx[i*KK + 1 + (eg >> 14)];
            int frm = g_idx[i*KK];
            float4 p = *(const float4*)(g_P + (size_t)to*64  + (k4<<2));
            float4 q = *(const float4*)(g_Q + (size_t)frm*64 + (k4<<2));
            v = make_float4(p.x+q.x, p.y+q.y, p.z+q.z, p.w+q.w);
        } else {
            v = *(const float4*)(g_u1 + (size_t)eg*64 + (k4<<2));
        }
        float4 sc = *(const float4*)(g_scale + (k4<<2));
        float4 sh = *(const float4*)(g_shift + (k4<<2));
        As[(k4<<2)+0][e] = fmaxf(fmaf(v.x, sc.x, sh.x), 0.f);
        As[(k4<<2)+1][e] = fmaxf(fmaf(v.y, sc.y, sh.y), 0.f);
        As[(k4<<2)+2][e] = fmaxf(fmaf(v.z, sc.z, sh.z), 0.f);
        As[(k4<<2)+3][e] = fmaxf(fmaf(v.w, sc.w, sh.w), 0.f);
    }
    __syncthreads();

    ull acc[4][4];
    #pragma unroll
    for (int rp = 0; rp < 4; rp++)
        #pragma unroll
        for (int c = 0; c < 4; c++) acc[rp][c] = 0ull;

    #pragma unroll 4
    for (int k = 0; k < 64; k++) {
        ulonglong2 a01 = *(const ulonglong2*)(&As[k][r0]);
        ulonglong2 a23 = *(const ulonglong2*)(&As[k][r0+4]);
        float4 b = *(const float4*)(&Ws[k][f0]);
        ull ar[4] = { a01.x, a01.y, a23.x, a23.y };
        ull bd[4] = { dup2(b.x), dup2(b.y), dup2(b.z), dup2(b.w) };
        #pragma unroll
        for (int rp = 0; rp < 4; rp++)
            #pragma unroll
            for (int c = 0; c < 4; c++)
                acc[rp][c] = ff2(ar[rp], bd[c], acc[rp][c]);
    }

    float* out = (MODE == 0) ? g_y2 : g_u2;
    float4 bv = *(const float4*)(bias + f0);
    float fs[4] = {0.f,0.f,0.f,0.f}, fq[4] = {0.f,0.f,0.f,0.f};
    #pragma unroll
    for (int rp = 0; rp < 4; rp++) {
        float2 u0 = up2(acc[rp][0]), u1 = up2(acc[rp][1]);
        float2 u2 = up2(acc[rp][2]), u3 = up2(acc[rp][3]);
        int ea = e0 + r0 + 2*rp;
        float4 oA = make_float4(u0.x + bv.x, u1.x + bv.y, u2.x + bv.z, u3.x + bv.w);
        float4 oB = make_float4(u0.y + bv.x, u1.y + bv.y, u2.y + bv.z, u3.y + bv.w);
        *(float4*)(out + (size_t)ea*64 + f0) = oA;
        *(float4*)(out + (size_t)(ea+1)*64 + f0) = oB;
        fs[0] += oA.x + oB.x; fq[0] += oA.x*oA.x + oB.x*oB.x;
        fs[1] += oA.y + oB.y; fq[1] += oA.y*oA.y + oB.y*oB.y;
        fs[2] += oA.z + oB.z; fq[2] += oA.z*oA.z + oB.z*oB.z;
        fs[3] += oA.w + oB.w; fq[3] += oA.w*oA.w + oB.w*oB.w;
    }

    __syncthreads();         // all As reads done before scratch reuse
    float* scr = &As[0][0];
    #pragma unroll
    for (int c = 0; c < 4; c++) {
        scr[tid*4 + c]        = fs[c];
        scr[1024 + tid*4 + c] = fq[c];
    }
    __syncthreads();
    if (tid < 64) {
        const int fg = tid >> 2, c = tid & 3;
        float S = 0.f, Q = 0.f;
        #pragma unroll
        for (int g = 0; g < 16; g++) {
            int idx = (g*16 + fg)*4 + c;
            S += scr[idx]; Q += scr[1024 + idx];
        }
        g_part[(size_t)blockIdx.x*128 + tid]      = S;
        g_part[(size_t)blockIdx.x*128 + 64 + tid] = Q;
    }
}

// ------------- GEMM A (upd only): depth-128, fused stats partials ------
__global__ __launch_bounds__(256) void k_gemm_a1(const float* __restrict__ W,
                                                 const float* __restrict__ bias) {
    __shared__ float As[64][128];
    __shared__ float Ws[64][64];
    const int tid = threadIdx.x;
    const int e0  = blockIdx.x * 128;
    const int r0  = (tid >> 4) * 8;
    const int f0  = (tid & 15) * 4;
    ull acc[4][4];
    #pragma unroll
    for (int rp = 0; rp < 4; rp++)
        #pragma unroll
        for (int c = 0; c < 4; c++) acc[rp][c] = 0ull;

    for (int p = 0; p < 2; p++) {
        for (int t = tid; t < 1024; t += 256) {
            int f4 = t & 15, kk = t >> 4;
            *(float4*)&Ws[kk][f4<<2] =
                *(const float4*)(W + (size_t)((p<<6)+kk)*64 + (f4<<2));
        }
        for (int t = tid; t < 2048; t += 256) {
            int e = t & 127, k4 = t >> 7;
            int eg = e0 + e;
            const float* src = (p == 0 ? g_h : g_agg) + (size_t)eg*64;
            float4 v = *(const float4*)(src + (k4<<2));
            As[(k4<<2)+0][e] = v.x; As[(k4<<2)+1][e] = v.y;
            As[(k4<<2)+2][e] = v.z; As[(k4<<2)+3][e] = v.w;
        }
        __syncthreads();
        #pragma unroll 4
        for (int k = 0; k < 64; k++) {
            ulonglong2 a01 = *(const ulonglong2*)(&As[k][r0]);
            ulonglong2 a23 = *(const ulonglong2*)(&As[k][r0+4]);
            float4 b = *(const float4*)(&Ws[k][f0]);
            ull ar[4] = { a01.x, a01.y, a23.x, a23.y };
            ull bd[4] = { dup2(b.x), dup2(b.y), dup2(b.z), dup2(b.w) };
            #pragma unroll
            for (int rp = 0; rp < 4; rp++)
                #pragma unroll
                for (int c = 0; c < 4; c++)
                    acc[rp][c] = ff2(ar[rp], bd[c], acc[rp][c]);
        }
        __syncthreads();
    }

    float4 bv = *(const float4*)(bias + f0);
    float fs[4] = {0.f,0.f,0.f,0.f}, fq[4] = {0.f,0.f,0.f,0.f};
    #pragma unroll
    for (int rp = 0; rp < 4; rp++) {
        float2 u0 = up2(acc[rp][0]), u1 = up2(acc[rp][1]);
        float2 u2 = up2(acc[rp][2]), u3 = up2(acc[rp][3]);
        int ea = e0 + r0 + 2*rp;
        float4 oA = make_float4(u0.x + bv.x, u1.x + bv.y, u2.x + bv.z, u3.x + bv.w);
        float4 oB = make_float4(u0.y + bv.x, u1.y + bv.y, u2.y + bv.z, u3.y + bv.w);
        *(float4*)(g_u1 + (size_t)ea*64 + f0) = oA;
        *(float4*)(g_u1 + (size_t)(ea+1)*64 + f0) = oB;
        fs[0] += oA.x + oB.x; fq[0] += oA.x*oA.x + oB.x*oB.x;
        fs[1] += oA.y + oB.y; fq[1] += oA.y*oA.y + oB.y*oB.y;
        fs[2] += oA.z + oB.z; fq[2] += oA.z*oA.z + oB.z*oB.z;
        fs[3] += oA.w + oB.w; fq[3] += oA.w*oA.w + oB.w*oB.w;
    }

    float* scr = &As[0][0];
    #pragma unroll
    for (int c = 0; c < 4; c++) {
        scr[tid*4 + c]        = fs[c];
        scr[1024 + tid*4 + c] = fq[c];
    }
    __syncthreads();
    if (tid < 64) {
        const int fg = tid >> 2, c = tid & 3;
        float S = 0.f, Q = 0.f;
        #pragma unroll
        for (int g = 0; g < 16; g++) {
            int idx = (g*16 + fg)*4 + c;
            S += scr[idx]; Q += scr[1024 + idx];
        }
        g_part[(size_t)blockIdx.x*128 + tid]      = S;
        g_part[(size_t)blockIdx.x*128 + 64 + tid] = Q;
    }
}

// ---------------- final-pool stats (over g_h) ----------------
__global__ void k_stats(int M, int P) {
    const float* __restrict__ x = g_h;
    const int t = threadIdx.x;
    float s = 0.f, s2 = 0.f;
    const size_t total = (size_t)M * 64;
    for (size_t idx = (size_t)blockIdx.x*256 + t; idx < total; idx += (size_t)P*256) {
        float v = x[idx];
        s += v; s2 = fmaf(v, v, s2);
    }
    __shared__ float sh[256], sh2[256];
    sh[t] = s; sh2[t] = s2;
    __syncthreads();
    if (t < 64) {
        s  = sh[t]  + sh[t+64]  + sh[t+128]  + sh[t+192];
        s2 = sh2[t] + sh2[t+64] + sh2[t+128] + sh2[t+192];
        g_part[(size_t)blockIdx.x*128 + t]      = s;
        g_part[(size_t)blockIdx.x*128 + 64 + t] = s2;
    }
}

// ---------------- stats finalize: 256-thread parallel reduce ----------
__global__ void k_stats_fin(int M, int P,
                            const float* __restrict__ g,
                            const float* __restrict__ be) {
    const int tid = threadIdx.x;
    const int f = tid & 63;
    const int part = tid >> 6;               // 0..3
    float s = 0.f, s2 = 0.f;
    for (int p = part; p < P; p += 4) {
        s  += g_part[(size_t)p*128 + f];
        s2 += g_part[(size_t)p*128 + 64 + f];
    }
    __shared__ float sh[256], sh2[256];
    sh[tid] = s; sh2[tid] = s2;
    __syncthreads();
    if (tid < 64) {
        s  = sh[tid]  + sh[tid+64]  + sh[tid+128]  + sh[tid+192];
        s2 = sh2[tid] + sh2[tid+64] + sh2[tid+128] + sh2[tid+192];
        const float inv  = 1.f / (float)M;
        const float mean = s * inv;
        const float var  = fmaf(-mean, mean, s2 * inv);
        const float sc   = g[tid] * rsqrtf(var + 1e-5f);
        g_scale[tid] = sc;
        g_shift[tid] = fmaf(-mean, sc, be[tid]);
    }
}

// ---------------- zero, scatter, residual ----------------
__global__ void k_zero_agg() {
    int i = blockIdx.x*blockDim.x + threadIdx.x;
    g_agg[i] = 0.f;
}

__global__ void k_scatter() {
    const int gid = blockIdx.x*256 + threadIdx.x;
    const int q = gid & 15;
    const int e = gid >> 4;
    const int i = e & (Nn-1);
    const int to = g_idx[i*KK + 1 + (e >> 14)];
    const int f = q << 2;
    float4 v  = *(const float4*)(g_y2 + (size_t)e*64 + f);
    float4 sc = *(const float4*)(g_scale + f);
    float4 sh = *(const float4*)(g_shift + f);
    float* dst = g_agg + (size_t)to*64 + f;
    atomicAdd(dst+0, fmaxf(fmaf(v.x, sc.x, sh.x), 0.f));
    atomicAdd(dst+1, fmaxf(fmaf(v.y, sc.y, sh.y), 0.f));
    atomicAdd(dst+2, fmaxf(fmaf(v.z, sc.z, sh.z), 0.f));
    atomicAdd(dst+3, fmaxf(fmaf(v.w, sc.w, sh.w), 0.f));
}

__global__ void k_resid() {
    const int gid = blockIdx.x*blockDim.x + threadIdx.x;
    const int f = gid & 63;
    const float v = g_u2[gid];
    g_h[gid] += fmaxf(fmaf(v, g_scale[f], g_shift[f]), 0.f);
    if (gid == 0) g_amax = 0;          // reset for next layer's k_split
}

// ---------------- final pool + prediction ----------------
__global__ void k_fin(const float* __restrict__ pW,
                      const float* __restrict__ pb,
                      float* __restrict__ out, int P) {
    const int f = threadIdx.x;
    float s = 0.f;
    for (int p = 0; p < P; p++) s += g_part[(size_t)p*128 + f];
    float v = (s / (float)Nn) * pW[f];
    __shared__ float red[64];
    red[f] = v;
    __syncthreads();
    if (f < 32) {
        float x = red[f] + red[f+32];
        #pragma unroll
        for (int o = 16; o > 0; o >>= 1) x += __shfl_down_sync(0xffffffffu, x, o);
        if (f == 0) out[0] = x + pb[0];
    }
}

// ---------------- host driver ----------------
extern "C" void kernel_launch(void* const* d_in, const int* in_sizes, int n_in,
                              void* d_out, int out_size) {
    const float* pos    = (const float*)d_in[0];
    const float* linW   = (const float*)d_in[1];
    const float* linb   = (const float*)d_in[2];
    const float* predW  = (const float*)d_in[3];
    const float* predb  = (const float*)d_in[4];
    const float* msgW1  = (const float*)d_in[5];
    const float* msgb1  = (const float*)d_in[6];
    const float* msgg1  = (const float*)d_in[7];
    const float* msgbe1 = (const float*)d_in[8];
    const float* msgW2  = (const float*)d_in[9];
    const float* msgb2  = (const float*)d_in[10];
    const float* msgg2  = (const float*)d_in[11];
    const float* msgbe2 = (const float*)d_in[12];
    const float* updW1  = (const float*)d_in[13];
    const float* updb1  = (const float*)d_in[14];
    const float* updg1  = (const float*)d_in[15];
    const float* updbe1 = (const float*)d_in[16];
    const float* updW2  = (const float*)d_in[17];
    const float* updb2  = (const float*)d_in[18];
    const float* updg2  = (const float*)d_in[19];
    const float* updbe2 = (const float*)d_in[20];
    float* out = (float*)d_out;

    static int smem_set = 0;
    if (!smem_set) {
        cudaFuncSetAttribute(k_d2pref, cudaFuncAttributeMaxDynamicSharedMemorySize,
                             SMEM_D2);
        smem_set = 1;
    }

    k_lin_in<<<Nn, 64>>>(pos, linW, linb);

    for (int l = 0; l < Ll; l++) {
        // ---- KNN: int8 prefilter (int epilogue) + top-32 + exact rerank ----
        k_split<<<Nn/8, 256>>>();
        k_quant<<<256, 256>>>();
        k_d2pref<<<1024, 256, SMEM_D2>>>();
        k_rerank<<<Nn/8, 256>>>();

        // ---- message MLP: P/Q factorization ----
        k_pq<<<Nn/128, 256>>>(msgW1 + (size_t)l*128*64, msgb1 + l*64);
        k_estats<<<2048, 256>>>();
        k_stats_fin<<<1, 256>>>(Ee, 2048, msgg1 + l*64, msgbe1 + l*64);
        k_gemm_b<0><<<Ee/128, 256>>>(msgW2 + (size_t)l*64*64, msgb2 + l*64);
        k_stats_fin<<<1, 256>>>(Ee, 2048, msgg2 + l*64, msgbe2 + l*64);

        // ---- aggregate ----
        k_zero_agg<<<Nn*64/256, 256>>>();
        k_scatter<<<Ee*16/256, 256>>>();

        // ---- update MLP + residual (stats fused) ----
        k_gemm_a1<<<Nn/128, 256>>>(updW1 + (size_t)l*128*64, updb1 + l*64);
        k_stats_fin<<<1, 256>>>(Nn, 128, updg1 + l*64, updbe1 + l*64);
        k_gemm_b<1><<<Nn/128, 256>>>(updW2 + (size_t)l*64*64, updb2 + l*64);
        k_stats_fin<<<1, 256>>>(Nn, 128, updg2 + l*64, updbe2 + l*64);
        k_resid<<<Nn*64/256, 256>>>();
    }

    k_stats<<<64, 256>>>(Nn, 64);
    k_fin<<<1, 64>>>(predW, predb, out, 64);
}